// round 13
// baseline (speedup 1.0000x reference)
#include <cuda_runtime.h>
#include <cstdint>
#include <math.h>

// ---------------- problem constants ----------------
#define BB     2
#define CC     512
#define NQ     2304
#define INNER_ 512
#define HEADS_ 8
#define DHEAD_ 64
#define CTX    77
#define CTXD   768
#define FFI    2048
#define MTOK   4608

// ---------------- scratch (device globals) ---------------------------------
__device__ float g_hn  [MTOK*INNER_];
__device__ float g_t   [MTOK*INNER_];
__device__ float g_q   [MTOK*INNER_];
__device__ float g_at  [MTOK*INNER_];
__device__ float g_qkv [MTOK*1536];
__device__ float g_kvc [160*1024];
__device__ float g_gl  [MTOK*FFI];
__device__ float g_stat[BB*32*2];
__device__ float g_vt  [16*DHEAD_*NQ];
// transposed weights [N,K]
__device__ float g_wt_in [512*512];
__device__ float g_wqkv  [1536*512];
__device__ float g_wto1  [512*512];
__device__ float g_wtq2  [512*512];
__device__ float g_wtkv2 [1024*768];
__device__ float g_wto2  [512*512];
__device__ float g_wtff1 [4096*512];
__device__ float g_wtff2 [512*2048];
__device__ float g_wtout [512*512];

// ---------------- PTX helpers ------------------------------------------------
__device__ __forceinline__ uint32_t smem_u32(const void* p) {
    uint32_t a;
    asm("{ .reg .u64 t; cvta.to.shared.u64 t, %1; cvt.u32.u64 %0, t; }"
        : "=r"(a) : "l"(p));
    return a;
}
__device__ __forceinline__ uint32_t f2tf(float x) {
    uint32_t r;
    asm("cvt.rna.tf32.f32 %0, %1;" : "=r"(r) : "f"(x));
    return r;
}
__device__ __forceinline__ void mma_t(float* c, const uint32_t* a, const uint32_t* b) {
    asm volatile("mma.sync.aligned.m16n8k8.row.col.f32.tf32.tf32.f32 "
        "{%0,%1,%2,%3}, {%4,%5,%6,%7}, {%8,%9}, {%0,%1,%2,%3};"
        : "+f"(c[0]), "+f"(c[1]), "+f"(c[2]), "+f"(c[3])
        : "r"(a[0]), "r"(a[1]), "r"(a[2]), "r"(a[3]), "r"(b[0]), "r"(b[1]));
}
__device__ __forceinline__ void cp16(uint32_t dst, const float* src, bool valid) {
    int sz = valid ? 16 : 0;
    asm volatile("cp.async.cg.shared.global [%0], [%1], 16, %2;"
                 :: "r"(dst), "l"(src), "r"(sz) : "memory");
}
#define CP_COMMIT() asm volatile("cp.async.commit_group;" ::: "memory")
#define CP_WAIT(n)  asm volatile("cp.async.wait_group %0;" :: "n"(n) : "memory")
#define U32(x) (*(const uint32_t*)&(x))

// ---------------- tf32 mma.sync GEMM (plain, R4-proven) ----------------------
__global__ void __launch_bounds__(256)
tgemm_k(const float* __restrict__ A, const float* __restrict__ Bt,
        const float* __restrict__ bias, const float* __restrict__ res,
        float* __restrict__ C,
        int M, int K, int lda, int ldb, int ldc)
{
    extern __shared__ float smem[];
    const int t = threadIdx.x, wid = t >> 5, lane = t & 31;
    const int bn = blockIdx.x * 128, bm = blockIdx.y * 128;

    constexpr int AFL = 128 * 36;
    constexpr int STR = 2 * AFL;

    const int mw = wid & 3, nw = wid >> 2;
    const int gp = lane >> 2, qd = lane & 3;

    float acc[2][8][4];
    #pragma unroll
    for (int i = 0; i < 2; i++)
        #pragma unroll
        for (int j = 0; j < 8; j++)
            #pragma unroll
            for (int c = 0; c < 4; c++) acc[i][j][c] = 0.f;

    const uint32_t sbase = smem_u32(smem);

    auto load_tile = [&](int kt, int buf) {
        const int k0 = kt * 32;
        const uint32_t offA = sbase + buf * STR * 4;
        const uint32_t offB = offA + AFL * 4;
        #pragma unroll
        for (int i = 0; i < 4; i++) {
            int idx = t + i * 256, row = idx >> 3, q = idx & 7;
            bool ok = (bm + row) < M;
            cp16(offA + (row * 36 + q * 4) * 4,
                 &A[(size_t)(ok ? bm + row : 0) * lda + k0 + q * 4], ok);
        }
        #pragma unroll
        for (int i = 0; i < 4; i++) {
            int idx = t + i * 256, row = idx >> 3, q = idx & 7;
            cp16(offB + (row * 36 + q * 4) * 4,
                 &Bt[(size_t)(bn + row) * ldb + k0 + q * 4], true);
        }
        CP_COMMIT();
    };

    const int KT = K / 32;
    load_tile(0, 0);

    for (int kt = 0; kt < KT; kt++) {
        const int cur = kt & 1;
        if (kt + 1 < KT) { load_tile(kt + 1, cur ^ 1); CP_WAIT(1); }
        else             { CP_WAIT(0); }
        __syncthreads();
        const float* As = smem + cur * STR;
        const float* Bs = As + AFL;
        #pragma unroll
        for (int ks = 0; ks < 4; ks++) {
            const int kc = ks * 8 + qd;
            uint32_t fA[2][4];
            #pragma unroll
            for (int mt = 0; mt < 2; mt++) {
                const int r = mw * 32 + mt * 16 + gp;
                fA[mt][0] = U32(As[(r    ) * 36 + kc    ]);
                fA[mt][1] = U32(As[(r + 8) * 36 + kc    ]);
                fA[mt][2] = U32(As[(r    ) * 36 + kc + 4]);
                fA[mt][3] = U32(As[(r + 8) * 36 + kc + 4]);
            }
            uint32_t fB[8][2];
            #pragma unroll
            for (int nt = 0; nt < 8; nt++) {
                const int n = nw * 64 + nt * 8 + gp;
                fB[nt][0] = U32(Bs[n * 36 + kc    ]);
                fB[nt][1] = U32(Bs[n * 36 + kc + 4]);
            }
            #pragma unroll
            for (int mt = 0; mt < 2; mt++)
                #pragma unroll
                for (int nt = 0; nt < 8; nt++)
                    mma_t(acc[mt][nt], fA[mt], fB[nt]);
        }
        __syncthreads();
    }

    #pragma unroll
    for (int mt = 0; mt < 2; mt++) {
        const int r0 = bm + mw * 32 + mt * 16 + gp;
        #pragma unroll
        for (int nt = 0; nt < 8; nt++) {
            const int col = bn + nw * 64 + nt * 8 + qd * 2;
            float2 lo = make_float2(acc[mt][nt][0], acc[mt][nt][1]);
            float2 hi = make_float2(acc[mt][nt][2], acc[mt][nt][3]);
            if (bias) {
                const float2 b2 = *(const float2*)&bias[col];
                lo.x += b2.x; lo.y += b2.y; hi.x += b2.x; hi.y += b2.y;
            }
            if (r0 < M) {
                if (res) {
                    const float2 r2 = *(const float2*)&res[(size_t)r0 * ldc + col];
                    lo.x += r2.x; lo.y += r2.y;
                }
                *(float2*)&C[(size_t)r0 * ldc + col] = lo;
            }
            if (r0 + 8 < M) {
                if (res) {
                    const float2 r2 = *(const float2*)&res[(size_t)(r0 + 8) * ldc + col];
                    hi.x += r2.x; hi.y += r2.y;
                }
                *(float2*)&C[(size_t)(r0 + 8) * ldc + col] = hi;
            }
        }
    }
}

// ---------------- qkv GEMM with fused LayerNorm on A -------------------------
// A = t_ [4608,512]; LN(ln g,b) applied on the fly. q/k cols -> qkv, v -> Vt.
__global__ void __launch_bounds__(256)
tgemmQKV_k(const float* __restrict__ A, const float* __restrict__ Bt,
           const float* __restrict__ lng, const float* __restrict__ lnb,
           float* __restrict__ C, float* __restrict__ Vt)
{
    extern __shared__ float smem[];
    const int t = threadIdx.x, wid = t >> 5, lane = t & 31;
    const int bn = blockIdx.x * 128, bm = blockIdx.y * 128;

    constexpr int AFL = 128 * 36;
    constexpr int STR = 2 * AFL;

    const int mw = wid & 3, nw = wid >> 2;
    const int gp = lane >> 2, qd = lane & 3;

    float* stats = smem + 2 * STR;     // 256
    float* sg    = stats + 256;        // 512
    float* sb    = sg + 512;           // 512

    float acc[2][8][4];
    #pragma unroll
    for (int i = 0; i < 2; i++)
        #pragma unroll
        for (int j = 0; j < 8; j++)
            #pragma unroll
            for (int c = 0; c < 4; c++) acc[i][j][c] = 0.f;

    const uint32_t sbase = smem_u32(smem);

    auto load_tile = [&](int kt, int buf) {
        const int k0 = kt * 32;
        const uint32_t offA = sbase + buf * STR * 4;
        const uint32_t offB = offA + AFL * 4;
        #pragma unroll
        for (int i = 0; i < 4; i++) {
            int idx = t + i * 256, row = idx >> 3, q = idx & 7;
            cp16(offA + (row * 36 + q * 4) * 4,
                 &A[(size_t)(bm + row) * 512 + k0 + q * 4], true);
        }
        #pragma unroll
        for (int i = 0; i < 4; i++) {
            int idx = t + i * 256, row = idx >> 3, q = idx & 7;
            cp16(offB + (row * 36 + q * 4) * 4,
                 &Bt[(size_t)(bn + row) * 512 + k0 + q * 4], true);
        }
        CP_COMMIT();
    };

    load_tile(0, 0);

    // LN prep: gamma/beta + per-row stats (overlaps with tile-0 cp.async)
    #pragma unroll
    for (int i = t; i < 512; i += 256) { sg[i] = lng[i]; sb[i] = lnb[i]; }
    {
        const int row = t >> 1, half = t & 1;
        const float* ar = A + (size_t)(bm + row) * 512 + half * 256;
        float s = 0.f, s2 = 0.f;
        #pragma unroll 8
        for (int j = 0; j < 64; j++) {
            const float4 v = *(const float4*)&ar[j * 4];
            s  += v.x + v.y + v.z + v.w;
            s2 += v.x*v.x + v.y*v.y + v.z*v.z + v.w*v.w;
        }
        s  += __shfl_xor_sync(~0u, s, 1);
        s2 += __shfl_xor_sync(~0u, s2, 1);
        if (half == 0) {
            const float mean = s * (1.f / 512.f);
            const float var  = s2 * (1.f / 512.f) - mean * mean;
            stats[row * 2]     = mean;
            stats[row * 2 + 1] = rsqrtf(var + 1e-5f);
        }
    }
    __syncthreads();

    for (int kt = 0; kt < 16; kt++) {
        const int cur = kt & 1;
        if (kt + 1 < 16) { load_tile(kt + 1, cur ^ 1); CP_WAIT(1); }
        else             { CP_WAIT(0); }
        __syncthreads();
        float* As = smem + cur * STR;
        const float* Bs = As + AFL;
        // normalize this A tile in smem
        const int k0c = kt * 32;
        #pragma unroll
        for (int i = 0; i < 4; i++) {
            int idx = t + i * 256, row = idx >> 3, q = idx & 7;
            float4* p = (float4*)&As[row * 36 + q * 4];
            float4 v = *p;
            const float mean = stats[row * 2], rstd = stats[row * 2 + 1];
            const int c = k0c + q * 4;
            const float4 g4 = *(const float4*)&sg[c];
            const float4 b4 = *(const float4*)&sb[c];
            v.x = (v.x - mean) * rstd * g4.x + b4.x;
            v.y = (v.y - mean) * rstd * g4.y + b4.y;
            v.z = (v.z - mean) * rstd * g4.z + b4.z;
            v.w = (v.w - mean) * rstd * g4.w + b4.w;
            *p = v;
        }
        __syncthreads();
        #pragma unroll
        for (int ks = 0; ks < 4; ks++) {
            const int kc = ks * 8 + qd;
            uint32_t fA[2][4];
            #pragma unroll
            for (int mt = 0; mt < 2; mt++) {
                const int r = mw * 32 + mt * 16 + gp;
                fA[mt][0] = U32(As[(r    ) * 36 + kc    ]);
                fA[mt][1] = U32(As[(r + 8) * 36 + kc    ]);
                fA[mt][2] = U32(As[(r    ) * 36 + kc + 4]);
                fA[mt][3] = U32(As[(r + 8) * 36 + kc + 4]);
            }
            uint32_t fB[8][2];
            #pragma unroll
            for (int nt = 0; nt < 8; nt++) {
                const int n = nw * 64 + nt * 8 + gp;
                fB[nt][0] = U32(Bs[n * 36 + kc    ]);
                fB[nt][1] = U32(Bs[n * 36 + kc + 4]);
            }
            #pragma unroll
            for (int mt = 0; mt < 2; mt++)
                #pragma unroll
                for (int nt = 0; nt < 8; nt++)
                    mma_t(acc[mt][nt], fA[mt], fB[nt]);
        }
        __syncthreads();
    }

    if (bn < 1024) {
        #pragma unroll
        for (int mt = 0; mt < 2; mt++) {
            const int r0 = bm + mw * 32 + mt * 16 + gp;
            #pragma unroll
            for (int nt = 0; nt < 8; nt++) {
                const int col = bn + nw * 64 + nt * 8 + qd * 2;
                *(float2*)&C[(size_t)r0 * 1536 + col] =
                    make_float2(acc[mt][nt][0], acc[mt][nt][1]);
                *(float2*)&C[(size_t)(r0 + 8) * 1536 + col] =
                    make_float2(acc[mt][nt][2], acc[mt][nt][3]);
            }
        }
    } else {
        float* tile = smem;
        __syncthreads();
        #pragma unroll
        for (int mt = 0; mt < 2; mt++) {
            const int nl0 = mw * 32 + mt * 16 + gp;
            #pragma unroll
            for (int nt = 0; nt < 8; nt++) {
                const int cl = nw * 64 + nt * 8 + qd * 2;
                tile[(cl    ) * 132 + nl0    ] = acc[mt][nt][0];
                tile[(cl + 1) * 132 + nl0    ] = acc[mt][nt][1];
                tile[(cl    ) * 132 + nl0 + 8] = acc[mt][nt][2];
                tile[(cl + 1) * 132 + nl0 + 8] = acc[mt][nt][3];
            }
        }
        __syncthreads();

        const int b = bm / NQ;
        const int n0 = bm - b * NQ;
        const int bnl = bn - 1024;
        #pragma unroll
        for (int i = 0; i < 16; i++) {
            int idx4 = t + i * 256;
            int cl = idx4 >> 5, n4 = (idx4 & 31) * 4;
            const int gcol = bnl + cl;
            const int h = gcol >> 6, d = gcol & 63;
            float* dst = &Vt[((size_t)(b * 8 + h) * 64 + d) * NQ + n0 + n4];
            float4 o;
            o.x = tile[cl * 132 + n4 + 0];
            o.y = tile[cl * 132 + n4 + 1];
            o.z = tile[cl * 132 + n4 + 2];
            o.w = tile[cl * 132 + n4 + 3];
            *(float4*)dst = o;
        }
    }
}

// ------ merged cross-attn projections: LN-q GEMM + ctx kv GEMM ---------------
// grid (4, 40): y<36 -> LN-q (A=t_, Bt=wtq2 -> Q). y>=36 -> kv (ctx@wtkv2 -> KVc).
__global__ void __launch_bounds__(256)
xqkv_k(const float* __restrict__ A, const float* __restrict__ Bt,
       const float* __restrict__ lng, const float* __restrict__ lnb,
       float* __restrict__ Q,
       const float* __restrict__ ctx, const float* __restrict__ Btkv,
       float* __restrict__ KVc)
{
    extern __shared__ float smem[];
    const int t = threadIdx.x, wid = t >> 5, lane = t & 31;

    constexpr int AFL = 128 * 36;
    constexpr int STR = 2 * AFL;

    const int mw = wid & 3, nw = wid >> 2;
    const int gp = lane >> 2, qd = lane & 3;

    float acc[2][8][4];
    #pragma unroll
    for (int i = 0; i < 2; i++)
        #pragma unroll
        for (int j = 0; j < 8; j++)
            #pragma unroll
            for (int c = 0; c < 4; c++) acc[i][j][c] = 0.f;

    const uint32_t sbase = smem_u32(smem);

    if (blockIdx.y < 36) {
        // ---- LN-q path: K=512, M full tiles ----
        const int bn = blockIdx.x * 128, bm = blockIdx.y * 128;
        float* stats = smem + 2 * STR;
        float* sg    = stats + 256;
        float* sb    = sg + 512;

        auto load_tile = [&](int kt, int buf) {
            const int k0 = kt * 32;
            const uint32_t offA = sbase + buf * STR * 4;
            const uint32_t offB = offA + AFL * 4;
            #pragma unroll
            for (int i = 0; i < 4; i++) {
                int idx = t + i * 256, row = idx >> 3, q = idx & 7;
                cp16(offA + (row * 36 + q * 4) * 4,
                     &A[(size_t)(bm + row) * 512 + k0 + q * 4], true);
            }
            #pragma unroll
            for (int i = 0; i < 4; i++) {
                int idx = t + i * 256, row = idx >> 3, q = idx & 7;
                cp16(offB + (row * 36 + q * 4) * 4,
                     &Bt[(size_t)(bn + row) * 512 + k0 + q * 4], true);
            }
            CP_COMMIT();
        };

        load_tile(0, 0);
        #pragma unroll
        for (int i = t; i < 512; i += 256) { sg[i] = lng[i]; sb[i] = lnb[i]; }
        {
            const int row = t >> 1, half = t & 1;
            const float* ar = A + (size_t)(bm + row) * 512 + half * 256;
            float s = 0.f, s2 = 0.f;
            #pragma unroll 8
            for (int j = 0; j < 64; j++) {
                const float4 v = *(const float4*)&ar[j * 4];
                s  += v.x + v.y + v.z + v.w;
                s2 += v.x*v.x + v.y*v.y + v.z*v.z + v.w*v.w;
            }
            s  += __shfl_xor_sync(~0u, s, 1);
            s2 += __shfl_xor_sync(~0u, s2, 1);
            if (half == 0) {
                const float mean = s * (1.f / 512.f);
                const float var  = s2 * (1.f / 512.f) - mean * mean;
                stats[row * 2]     = mean;
                stats[row * 2 + 1] = rsqrtf(var + 1e-5f);
            }
        }
        __syncthreads();

        for (int kt = 0; kt < 16; kt++) {
            const int cur = kt & 1;
            if (kt + 1 < 16) { load_tile(kt + 1, cur ^ 1); CP_WAIT(1); }
            else             { CP_WAIT(0); }
            __syncthreads();
            float* As = smem + cur * STR;
            const float* Bs = As + AFL;
            const int k0c = kt * 32;
            #pragma unroll
            for (int i = 0; i < 4; i++) {
                int idx = t + i * 256, row = idx >> 3, q = idx & 7;
                float4* p = (float4*)&As[row * 36 + q * 4];
                float4 v = *p;
                const float mean = stats[row * 2], rstd = stats[row * 2 + 1];
                const int c = k0c + q * 4;
                const float4 g4 = *(const float4*)&sg[c];
                const float4 b4 = *(const float4*)&sb[c];
                v.x = (v.x - mean) * rstd * g4.x + b4.x;
                v.y = (v.y - mean) * rstd * g4.y + b4.y;
                v.z = (v.z - mean) * rstd * g4.z + b4.z;
                v.w = (v.w - mean) * rstd * g4.w + b4.w;
                *p = v;
            }
            __syncthreads();
            #pragma unroll
            for (int ks = 0; ks < 4; ks++) {
                const int kc = ks * 8 + qd;
                uint32_t fA[2][4];
                #pragma unroll
                for (int mt = 0; mt < 2; mt++) {
                    const int r = mw * 32 + mt * 16 + gp;
                    fA[mt][0] = U32(As[(r    ) * 36 + kc    ]);
                    fA[mt][1] = U32(As[(r + 8) * 36 + kc    ]);
                    fA[mt][2] = U32(As[(r    ) * 36 + kc + 4]);
                    fA[mt][3] = U32(As[(r + 8) * 36 + kc + 4]);
                }
                uint32_t fB[8][2];
                #pragma unroll
                for (int nt = 0; nt < 8; nt++) {
                    const int n = nw * 64 + nt * 8 + gp;
                    fB[nt][0] = U32(Bs[n * 36 + kc    ]);
                    fB[nt][1] = U32(Bs[n * 36 + kc + 4]);
                }
                #pragma unroll
                for (int mt = 0; mt < 2; mt++)
                    #pragma unroll
                    for (int nt = 0; nt < 8; nt++)
                        mma_t(acc[mt][nt], fA[mt], fB[nt]);
            }
            __syncthreads();
        }

        #pragma unroll
        for (int mt = 0; mt < 2; mt++) {
            const int r0 = bm + mw * 32 + mt * 16 + gp;
            #pragma unroll
            for (int nt = 0; nt < 8; nt++) {
                const int col = bn + nw * 64 + nt * 8 + qd * 2;
                *(float2*)&Q[(size_t)r0 * 512 + col] =
                    make_float2(acc[mt][nt][0], acc[mt][nt][1]);
                *(float2*)&Q[(size_t)(r0 + 8) * 512 + col] =
                    make_float2(acc[mt][nt][2], acc[mt][nt][3]);
            }
        }
    } else {
        // ---- kv path: A=ctx [154,768], Bt=wtkv2 [1024,768], C=KVc ldc 1024 ----
        const int idx16 = (blockIdx.y - 36) * 4 + blockIdx.x;   // 0..15
        const int bn = (idx16 & 7) * 128, bm = (idx16 >> 3) * 128;
        const int M = BB * CTX;

        auto load_tile = [&](int kt, int buf) {
            const int k0 = kt * 32;
            const uint32_t offA = sbase + buf * STR * 4;
            const uint32_t offB = offA + AFL * 4;
            #pragma unroll
            for (int i = 0; i < 4; i++) {
                int idx = t + i * 256, row = idx >> 3, q = idx & 7;
                bool ok = (bm + row) < M;
                cp16(offA + (row * 36 + q * 4) * 4,
                     &ctx[(size_t)(ok ? bm + row : 0) * 768 + k0 + q * 4], ok);
            }
            #pragma unroll
            for (int i = 0; i < 4; i++) {
                int idx = t + i * 256, row = idx >> 3, q = idx & 7;
                cp16(offB + (row * 36 + q * 4) * 4,
                     &Btkv[(size_t)(bn + row) * 768 + k0 + q * 4], true);
            }
            CP_COMMIT();
        };

        load_tile(0, 0);
        for (int kt = 0; kt < 24; kt++) {
            const int cur = kt & 1;
            if (kt + 1 < 24) { load_tile(kt + 1, cur ^ 1); CP_WAIT(1); }
            else             { CP_WAIT(0); }
            __syncthreads();
            const float* As = smem + cur * STR;
            const float* Bs = As + AFL;
            #pragma unroll
            for (int ks = 0; ks < 4; ks++) {
                const int kc = ks * 8 + qd;
                uint32_t fA[2][4];
                #pragma unroll
                for (int mt = 0; mt < 2; mt++) {
                    const int r = mw * 32 + mt * 16 + gp;
                    fA[mt][0] = U32(As[(r    ) * 36 + kc    ]);
                    fA[mt][1] = U32(As[(r + 8) * 36 + kc    ]);
                    fA[mt][2] = U32(As[(r    ) * 36 + kc + 4]);
                    fA[mt][3] = U32(As[(r + 8) * 36 + kc + 4]);
                }
                uint32_t fB[8][2];
                #pragma unroll
                for (int nt = 0; nt < 8; nt++) {
                    const int n = nw * 64 + nt * 8 + gp;
                    fB[nt][0] = U32(Bs[n * 36 + kc    ]);
                    fB[nt][1] = U32(Bs[n * 36 + kc + 4]);
                }
                #pragma unroll
                for (int mt = 0; mt < 2; mt++)
                    #pragma unroll
                    for (int nt = 0; nt < 8; nt++)
                        mma_t(acc[mt][nt], fA[mt], fB[nt]);
            }
            __syncthreads();
        }

        #pragma unroll
        for (int mt = 0; mt < 2; mt++) {
            const int r0 = bm + mw * 32 + mt * 16 + gp;
            #pragma unroll
            for (int nt = 0; nt < 8; nt++) {
                const int col = bn + nw * 64 + nt * 8 + qd * 2;
                if (r0 < M)
                    *(float2*)&KVc[(size_t)r0 * 1024 + col] =
                        make_float2(acc[mt][nt][0], acc[mt][nt][1]);
                if (r0 + 8 < M)
                    *(float2*)&KVc[(size_t)(r0 + 8) * 1024 + col] =
                        make_float2(acc[mt][nt][2], acc[mt][nt][3]);
            }
        }
    }
}

// ---------------- proj_out GEMM + transpose + image residual -----------------
__global__ void __launch_bounds__(256)
tgemmT_k(const float* __restrict__ A, const float* __restrict__ Bt,
         const float* __restrict__ bias, const float* __restrict__ x,
         float* __restrict__ out)
{
    extern __shared__ float smem[];
    const int t = threadIdx.x, wid = t >> 5, lane = t & 31;
    const int bn = blockIdx.x * 128, bm = blockIdx.y * 128;

    constexpr int AFL = 128 * 36;
    constexpr int STR = 2 * AFL;

    const int mw = wid & 3, nw = wid >> 2;
    const int gp = lane >> 2, qd = lane & 3;

    float acc[2][8][4];
    #pragma unroll
    for (int i = 0; i < 2; i++)
        #pragma unroll
        for (int j = 0; j < 8; j++)
            #pragma unroll
            for (int c = 0; c < 4; c++) acc[i][j][c] = 0.f;

    const uint32_t sbase = smem_u32(smem);

    auto load_tile = [&](int kt, int buf) {
        const int k0 = kt * 32;
        const uint32_t offA = sbase + buf * STR * 4;
        const uint32_t offB = offA + AFL * 4;
        #pragma unroll
        for (int i = 0; i < 4; i++) {
            int idx = t + i * 256, row = idx >> 3, q = idx & 7;
            cp16(offA + (row * 36 + q * 4) * 4,
                 &A[(size_t)(bm + row) * 512 + k0 + q * 4], true);
        }
        #pragma unroll
        for (int i = 0; i < 4; i++) {
            int idx = t + i * 256, row = idx >> 3, q = idx & 7;
            cp16(offB + (row * 36 + q * 4) * 4,
                 &Bt[(size_t)(bn + row) * 512 + k0 + q * 4], true);
        }
        CP_COMMIT();
    };

    load_tile(0, 0);
    for (int kt = 0; kt < 16; kt++) {
        const int cur = kt & 1;
        if (kt + 1 < 16) { load_tile(kt + 1, cur ^ 1); CP_WAIT(1); }
        else             { CP_WAIT(0); }
        __syncthreads();
        const float* As = smem + cur * STR;
        const float* Bs = As + AFL;
        #pragma unroll
        for (int ks = 0; ks < 4; ks++) {
            const int kc = ks * 8 + qd;
            uint32_t fA[2][4];
            #pragma unroll
            for (int mt = 0; mt < 2; mt++) {
                const int r = mw * 32 + mt * 16 + gp;
                fA[mt][0] = U32(As[(r    ) * 36 + kc    ]);
                fA[mt][1] = U32(As[(r + 8) * 36 + kc    ]);
                fA[mt][2] = U32(As[(r    ) * 36 + kc + 4]);
                fA[mt][3] = U32(As[(r + 8) * 36 + kc + 4]);
            }
            uint32_t fB[8][2];
            #pragma unroll
            for (int nt = 0; nt < 8; nt++) {
                const int n = nw * 64 + nt * 8 + gp;
                fB[nt][0] = U32(Bs[n * 36 + kc    ]);
                fB[nt][1] = U32(Bs[n * 36 + kc + 4]);
            }
            #pragma unroll
            for (int mt = 0; mt < 2; mt++)
                #pragma unroll
                for (int nt = 0; nt < 8; nt++)
                    mma_t(acc[mt][nt], fA[mt], fB[nt]);
        }
        __syncthreads();
    }

    float* tile = smem;
    __syncthreads();
    #pragma unroll
    for (int mt = 0; mt < 2; mt++) {
        const int nl0 = mw * 32 + mt * 16 + gp;
        #pragma unroll
        for (int nt = 0; nt < 8; nt++) {
            const int cl = nw * 64 + nt * 8 + qd * 2;
            const float2 b2 = *(const float2*)&bias[bn + cl];
            tile[(cl    ) * 132 + nl0    ] = acc[mt][nt][0] + b2.x;
            tile[(cl + 1) * 132 + nl0    ] = acc[mt][nt][1] + b2.y;
            tile[(cl    ) * 132 + nl0 + 8] = acc[mt][nt][2] + b2.x;
            tile[(cl + 1) * 132 + nl0 + 8] = acc[mt][nt][3] + b2.y;
        }
    }
    __syncthreads();

    const int b = bm / NQ;
    const int n0 = bm - b * NQ;
    #pragma unroll
    for (int i = 0; i < 16; i++) {
        int idx4 = t + i * 256;
        int cl = idx4 >> 5, n4 = (idx4 & 31) * 4;
        const size_t gidx = ((size_t)b * CC + bn + cl) * NQ + n0 + n4;
        const float4 xr = *(const float4*)&x[gidx];
        float4 o;
        o.x = tile[cl * 132 + n4 + 0] + xr.x;
        o.y = tile[cl * 132 + n4 + 1] + xr.y;
        o.z = tile[cl * 132 + n4 + 2] + xr.z;
        o.w = tile[cl * 132 + n4 + 3] + xr.w;
        *(float4*)&out[gidx] = o;
    }
}

// ---------------- fused LN + FF1 + GEGLU -------------------------------------
__global__ void __launch_bounds__(256)
ffgeglu_k(const float* __restrict__ A, const float* __restrict__ Bt,
          const float* __restrict__ lng, const float* __restrict__ lnb,
          const float* __restrict__ bias, float* __restrict__ GL)
{
    extern __shared__ float smem[];
    const int t = threadIdx.x, wid = t >> 5, lane = t & 31;
    const int bn = blockIdx.x * 128;
    const int bm = blockIdx.y * 64;

    constexpr int AFL = 64 * 36;
    constexpr int BFL = 256 * 36;
    constexpr int STR = AFL + BFL;

    const int mw = wid & 1, nw = wid >> 1;
    const int gp = lane >> 2, qd = lane & 3;

    float* stats = smem + 2 * STR;     // 128
    float* sg    = stats + 128;        // 512
    float* sb    = sg + 512;           // 512

    float acc[2][2][4][4];
    #pragma unroll
    for (int h = 0; h < 2; h++)
        #pragma unroll
        for (int i = 0; i < 2; i++)
            #pragma unroll
            for (int j = 0; j < 4; j++)
                #pragma unroll
                for (int c = 0; c < 4; c++) acc[h][i][j][c] = 0.f;

    const uint32_t sbase = smem_u32(smem);

    auto load_tile = [&](int kt, int buf) {
        const int k0 = kt * 32;
        const uint32_t offA = sbase + buf * STR * 4;
        const uint32_t offB = offA + AFL * 4;
        #pragma unroll
        for (int i = 0; i < 2; i++) {
            int idx = t + i * 256, row = idx >> 3, q = idx & 7;
            cp16(offA + (row * 36 + q * 4) * 4,
                 &A[(size_t)(bm + row) * 512 + k0 + q * 4], true);
        }
        #pragma unroll
        for (int i = 0; i < 8; i++) {
            int idx = t + i * 256, row = idx >> 3, q = idx & 7;
            int grow = (row < 128) ? (bn + row) : (2048 + bn + row - 128);
            cp16(offB + (row * 36 + q * 4) * 4,
                 &Bt[(size_t)grow * 512 + k0 + q * 4], true);
        }
        CP_COMMIT();
    };

    load_tile(0, 0);

    #pragma unroll
    for (int i = t; i < 512; i += 256) { sg[i] = lng[i]; sb[i] = lnb[i]; }
    {
        const int row = t >> 2, qtr = t & 3;
        const float* ar = A + (size_t)(bm + row) * 512 + qtr * 128;
        float s = 0.f, s2 = 0.f;
        #pragma unroll 8
        for (int j = 0; j < 32; j++) {
            const float4 v = *(const float4*)&ar[j * 4];
            s  += v.x + v.y + v.z + v.w;
            s2 += v.x*v.x + v.y*v.y + v.z*v.z + v.w*v.w;
        }
        s  += __shfl_xor_sync(~0u, s, 1);
        s2 += __shfl_xor_sync(~0u, s2, 1);
        s  += __shfl_xor_sync(~0u, s, 2);
        s2 += __shfl_xor_sync(~0u, s2, 2);
        if (qtr == 0) {
            const float mean = s * (1.f / 512.f);
            const float var  = s2 * (1.f / 512.f) - mean * mean;
            stats[row * 2]     = mean;
            stats[row * 2 + 1] = rsqrtf(var + 1e-5f);
        }
    }
    __syncthreads();

    for (int kt = 0; kt < 16; kt++) {
        const int cur = kt & 1;
        if (kt + 1 < 16) { load_tile(kt + 1, cur ^ 1); CP_WAIT(1); }
        else             { CP_WAIT(0); }
        __syncthreads();
        float* As = smem + cur * STR;
        const float* Bs = As + AFL;
        const int k0c = kt * 32;
        #pragma unroll
        for (int i = 0; i < 2; i++) {
            int idx = t + i * 256, row = idx >> 3, q = idx & 7;
            float4* p = (float4*)&As[row * 36 + q * 4];
            float4 v = *p;
            const float mean = stats[row * 2], rstd = stats[row * 2 + 1];
            const int c = k0c + q * 4;
            const float4 g4 = *(const float4*)&sg[c];
            const float4 b4 = *(const float4*)&sb[c];
            v.x = (v.x - mean) * rstd * g4.x + b4.x;
            v.y = (v.y - mean) * rstd * g4.y + b4.y;
            v.z = (v.z - mean) * rstd * g4.z + b4.z;
            v.w = (v.w - mean) * rstd * g4.w + b4.w;
            *p = v;
        }
        __syncthreads();
        #pragma unroll
        for (int ks = 0; ks < 4; ks++) {
            const int kc = ks * 8 + qd;
            uint32_t fA[2][4];
            #pragma unroll
            for (int mt = 0; mt < 2; mt++) {
                const int r = mw * 32 + mt * 16 + gp;
                fA[mt][0] = U32(As[(r    ) * 36 + kc    ]);
                fA[mt][1] = U32(As[(r + 8) * 36 + kc    ]);
                fA[mt][2] = U32(As[(r    ) * 36 + kc + 4]);
                fA[mt][3] = U32(As[(r + 8) * 36 + kc + 4]);
            }
            #pragma unroll
            for (int h = 0; h < 2; h++) {
                uint32_t fB[4][2];
                #pragma unroll
                for (int nt = 0; nt < 4; nt++) {
                    const int n = h * 128 + nw * 32 + nt * 8 + gp;
                    fB[nt][0] = U32(Bs[n * 36 + kc    ]);
                    fB[nt][1] = U32(Bs[n * 36 + kc + 4]);
                }
                #pragma unroll
                for (int mt = 0; mt < 2; mt++)
                    #pragma unroll
                    for (int nt = 0; nt < 4; nt++)
                        mma_t(acc[h][mt][nt], fA[mt], fB[nt]);
            }
        }
        __syncthreads();
    }

    #pragma unroll
    for (int mt = 0; mt < 2; mt++) {
        const int r0 = bm + mw * 32 + mt * 16 + gp;
        #pragma unroll
        for (int nt = 0; nt < 4; nt++) {
            const int col = bn + nw * 32 + nt * 8 + qd * 2;
            const float2 ba = *(const float2*)&bias[col];
            const float2 bg = *(const float2*)&bias[col + 2048];
            #pragma unroll
            for (int half_row = 0; half_row < 2; half_row++) {
                const int r = r0 + half_row * 8;
                float a0 = acc[0][mt][nt][half_row * 2 + 0] + ba.x;
                float a1 = acc[0][mt][nt][half_row * 2 + 1] + ba.y;
                float g0 = acc[1][mt][nt][half_row * 2 + 0] + bg.x;
                float g1 = acc[1][mt][nt][half_row * 2 + 1] + bg.y;
                float2 o;
                o.x = a0 * (0.5f * g0 * (1.f + erff(g0 * 0.70710678118654752f)));
                o.y = a1 * (0.5f * g1 * (1.f + erff(g1 * 0.70710678118654752f)));
                *(float2*)&GL[(size_t)r * 2048 + col] = o;
            }
        }
    }
}

// ---------------- flash self-attention (R9-proven simple version) ------------
__global__ void __launch_bounds__(256, 2) fattn_k(
    const float* __restrict__ QKV, const float* __restrict__ Vt,
    float* __restrict__ O)
{
    extern __shared__ float sm[];
    float* Qs  = sm;
    float* Ks  = Qs  + 128 * 68;
    float* Vts = Ks  +  64 * 68;
    float* Ps  = Vts +  64 * 68;

    const int t = threadIdx.x, w = t >> 5, lane = t & 31;
    const int gp = lane >> 2, qd = lane & 3;
    const int q0 = blockIdx.x * 128;
    const int h = blockIdx.y, b = blockIdx.z;

    const float* qb  = QKV + ((size_t)b * NQ) * 1536 + h * 64;
    const float* kb  = qb + 512;
    const float* vtb = Vt + ((size_t)(b * 8 + h)) * 64 * NQ;

    const uint32_t aQ = smem_u32(Qs), aK = smem_u32(Ks), aV = smem_u32(Vts);

    #pragma unroll
    for (int i = 0; i < 8; i++) {
        int idx = t + i * 256, r = idx >> 4, c4 = (idx & 15) * 4;
        cp16(aQ + (r * 68 + c4) * 4, &qb[(size_t)(q0 + r) * 1536 + c4], true);
    }
    CP_COMMIT(); CP_WAIT(0);
    __syncthreads();
    #pragma unroll
    for (int i = 0; i < 8; i++) {
        int idx = t + i * 256, r = idx >> 4, c4 = (idx & 15) * 4;
        float4* p = (float4*)&Qs[r * 68 + c4];
        float4 v = *p;
        v.x *= 0.125f; v.y *= 0.125f; v.z *= 0.125f; v.w *= 0.125f;
        *p = v;
    }
    __syncthreads();

    const int r0l = w * 16 + gp, r1l = r0l + 8;

    float o[8][4];
    #pragma unroll
    for (int nt = 0; nt < 8; nt++)
        #pragma unroll
        for (int c = 0; c < 4; c++) o[nt][c] = 0.f;
    float m0 = -1e30f, m1 = -1e30f, l0 = 0.f, l1 = 0.f;

    for (int kt = 0; kt < NQ / 64; kt++) {
        const int k0 = kt * 64;
        #pragma unroll
        for (int i = 0; i < 4; i++) {
            int idx = t + i * 256, r = idx >> 4, c4 = (idx & 15) * 4;
            cp16(aK + (r * 68 + c4) * 4, &kb[(size_t)(k0 + r) * 1536 + c4], true);
        }
        #pragma unroll
        for (int i = 0; i < 4; i++) {
            int idx = t + i * 256, d = idx >> 4, c4 = (idx & 15) * 4;
            cp16(aV + (d * 68 + c4) * 4, &vtb[(size_t)d * NQ + k0 + c4], true);
        }
        CP_COMMIT(); CP_WAIT(0);
        __syncthreads();

        float s[8][4];
        #pragma unroll
        for (int nt = 0; nt < 8; nt++)
            #pragma unroll
            for (int c = 0; c < 4; c++) s[nt][c] = 0.f;
        #pragma unroll
        for (int ks = 0; ks < 8; ks++) {
            const int kc = ks * 8 + qd;
            uint32_t af[4];
            af[0] = U32(Qs[r0l * 68 + kc    ]);
            af[1] = U32(Qs[r1l * 68 + kc    ]);
            af[2] = U32(Qs[r0l * 68 + kc + 4]);
            af[3] = U32(Qs[r1l * 68 + kc + 4]);
            #pragma unroll
            for (int nt = 0; nt < 8; nt++) {
                uint32_t bf[2];
                const int n = nt * 8 + gp;
                bf[0] = U32(Ks[n * 68 + kc    ]);
                bf[1] = U32(Ks[n * 68 + kc + 4]);
                mma_t(s[nt], af, bf);
            }
        }

        float tm0 = -1e30f, tm1 = -1e30f;
        #pragma unroll
        for (int nt = 0; nt < 8; nt++) {
            tm0 = fmaxf(tm0, fmaxf(s[nt][0], s[nt][1]));
            tm1 = fmaxf(tm1, fmaxf(s[nt][2], s[nt][3]));
        }
        tm0 = fmaxf(tm0, __shfl_xor_sync(~0u, tm0, 1));
        tm0 = fmaxf(tm0, __shfl_xor_sync(~0u, tm0, 2));
        tm1 = fmaxf(tm1, __shfl_xor_sync(~0u, tm1, 1));
        tm1 = fmaxf(tm1, __shfl_xor_sync(~0u, tm1, 2));
        const float mn0 = fmaxf(m0, tm0), mn1 = fmaxf(m1, tm1);
        const float al0 = __expf(m0 - mn0), al1 = __expf(m1 - mn1);
        float sum0 = 0.f, sum1 = 0.f;
        #pragma unroll
        for (int nt = 0; nt < 8; nt++) {
            s[nt][0] = __expf(s[nt][0] - mn0);
            s[nt][1] = __expf(s[nt][1] - mn0);
            s[nt][2] = __expf(s[nt][2] - mn1);
            s[nt][3] = __expf(s[nt][3] - mn1);
            sum0 += s[nt][0] + s[nt][1];
            sum1 += s[nt][2] + s[nt][3];
        }
        sum0 += __shfl_xor_sync(~0u, sum0, 1);
        sum0 += __shfl_xor_sync(~0u, sum0, 2);
        sum1 += __shfl_xor_sync(~0u, sum1, 1);
        sum1 += __shfl_xor_sync(~0u, sum1, 2);
        l0 = l0 * al0 + sum0;  m0 = mn0;
        l1 = l1 * al1 + sum1;  m1 = mn1;
        #pragma unroll
        for (int nt = 0; nt < 8; nt++) {
            o[nt][0] *= al0; o[nt][1] *= al0;
            o[nt][2] *= al1; o[nt][3] *= al1;
        }
        #pragma unroll
        for (int nt = 0; nt < 8; nt++) {
            *(float2*)&Ps[r0l * 68 + nt * 8 + 2 * qd] = make_float2(s[nt][0], s[nt][1]);
            *(float2*)&Ps[r1l * 68 + nt * 8 + 2 * qd] = make_float2(s[nt][2], s[nt][3]);
        }
        __syncthreads();

        #pragma unroll
        for (int ks = 0; ks < 8; ks++) {
            const int kc = ks * 8 + qd;
            uint32_t af[4];
            af[0] = U32(Ps[r0l * 68 + kc    ]);
            af[1] = U32(Ps[r1l * 68 + kc    ]);
            af[2] = U32(Ps[r0l * 68 + kc + 4]);
            af[3] = U32(Ps[r1l * 68 + kc + 4]);
            #pragma unroll
            for (int nt = 0; nt < 8; nt++) {
                uint32_t bf[2];
                const int n = nt * 8 + gp;
                bf[0] = U32(Vts[n * 68 + kc    ]);
                bf[1] = U32(Vts[n * 68 + kc + 4]);
                mma_t(o[nt], af, bf);
            }
        }
        __syncthreads();
    }

    const float i0 = 1.f / l0, i1 = 1.f / l1;
    const size_t gr0 = (size_t)(b * NQ + q0 + r0l);
    const size_t gr1 = gr0 + 8;
    #pragma unroll
    for (int nt = 0; nt < 8; nt++) {
        const int col = h * 64 + nt * 8 + 2 * qd;
        *(float2*)&O[gr0 * 512 + col] = make_float2(o[nt][0] * i0, o[nt][1] * i0);
        *(float2*)&O[gr1 * 512 + col] = make_float2(o[nt][2] * i1, o[nt][3] * i1);
    }
}

// ----- merged preamble: weight transposes (+rna) AND GroupNorm stats ---------
struct TrJobs {
    const float* src[12];
    float*       dst[12];
    int K[12], N[12], tiles[12];
    int tot;
    const float* x;
    float* st;
};
__global__ void pre_k(TrJobs J)
{
    const int tid = threadIdx.x;
    if ((int)blockIdx.x >= J.tot) {
        int bg = blockIdx.x - J.tot, b = bg >> 5, g = bg & 31;
        const float* base = J.x + ((size_t)b * CC + (size_t)g * 16) * NQ;
        float s = 0.f, s2 = 0.f;
        for (int i = tid; i < 16 * NQ; i += 256) {
            float v = base[i]; s += v; s2 += v * v;
        }
        for (int o = 16; o > 0; o >>= 1) {
            s  += __shfl_down_sync(~0u, s,  o);
            s2 += __shfl_down_sync(~0u, s2, o);
        }
        __shared__ float sh1[8], sh2[8];
        int w = tid >> 5, lane = tid & 31;
        if (lane == 0) { sh1[w] = s; sh2[w] = s2; }
        __syncthreads();
        if (tid == 0) {
            float S = 0.f, S2 = 0.f;
            for (int i = 0; i < 8; i++) { S += sh1[i]; S2 += sh2[i]; }
            float mean = S / (16.f * NQ);
            float var  = S2 / (16.f * NQ) - mean * mean;
            J.st[bg * 2]     = mean;
            J.st[bg * 2 + 1] = rsqrtf(var + 1e-6f);
        }
        return;
    }
    __shared__ float tl[32][33];
    int bid = blockIdx.x, j = 0;
    #pragma unroll
    for (int i = 0; i < 12; i++) {
        if (bid >= J.tiles[j]) { bid -= J.tiles[j]; j++; }
        else break;
    }
    const int kt = bid % (J.K[j] / 32), nt = bid / (J.K[j] / 32);
    const int k0 = kt * 32, n0 = nt * 32;
    const float* W = J.src[j];
    float* Wt = J.dst[j];
    const int K = J.K[j], N = J.N[j];
    int tx = tid & 31, ty = tid >> 5;
    #pragma unroll
    for (int i = 0; i < 4; i++) {
        float v = W[(size_t)(k0 + ty + i * 8) * N + n0 + tx];
        tl[ty + i * 8][tx] = __uint_as_float(f2tf(v));
    }
    __syncthreads();
    #pragma unroll
    for (int i = 0; i < 4; i++)
        Wt[(size_t)(n0 + ty + i * 8) * K + k0 + tx] = tl[tx][ty + i * 8];
}

// --------- GroupNorm apply + NCHW -> [b,n,c] transpose -----------------------
__global__ void gn_apply_t_k(const float* __restrict__ x, const float* __restrict__ st,
                             const float* __restrict__ gg, const float* __restrict__ gb,
                             float* __restrict__ o)
{
    __shared__ float tile[32][33];
    int n0 = blockIdx.x * 32, c0 = blockIdx.y * 32, b = blockIdx.z;
    int tx = threadIdx.x, ty = threadIdx.y;
    #pragma unroll
    for (int i = 0; i < 4; i++) {
        int c = c0 + ty + i * 8;
        int g = c >> 4;
        float mean = st[(b * 32 + g) * 2], rstd = st[(b * 32 + g) * 2 + 1];
        float v = x[((size_t)b * CC + c) * NQ + n0 + tx];
        tile[ty + i * 8][tx] = (v - mean) * rstd * gg[c] + gb[c];
    }
    __syncthreads();
    #pragma unroll
    for (int i = 0; i < 4; i++) {
        int n = n0 + ty + i * 8;
        o[((size_t)b * NQ + n) * INNER_ + c0 + tx] = tile[tx][ty + i * 8];
    }
}

// ---------------- fp32 flash attention (cross-attn, 77 keys) -----------------
__global__ void __launch_bounds__(256) attn_k(
    const float* __restrict__ Q, const float* __restrict__ Kb,
    const float* __restrict__ Vb, float* __restrict__ O,
    int n_q, int n_kv, int ldq, int ldkv)
{
    __shared__ float Qs[64][68];
    __shared__ float Ks[32][68];
    __shared__ float Vs[32][68];
    __shared__ float Sx[64][33];
    __shared__ float mrow[64], lrow[64], arow[64];

    const int t  = threadIdx.x;
    const int h  = blockIdx.y, b = blockIdx.z;
    const int q0 = blockIdx.x * 64;
    const float* qb = Q  + ((size_t)b * n_q ) * ldq  + h * DHEAD_;
    const float* kb = Kb + ((size_t)b * n_kv) * ldkv + h * DHEAD_;
    const float* vb = Vb + ((size_t)b * n_kv) * ldkv + h * DHEAD_;

    #pragma unroll
    for (int j = 0; j < 4; j++) {
        int idx4 = t + j * 256;
        int r = idx4 >> 4, c4 = (idx4 & 15) * 4;
        float4 v = *(const float4*)&qb[(size_t)(q0 + r) * ldq + c4];
        Qs[r][c4+0]=v.x; Qs[r][c4+1]=v.y; Qs[r][c4+2]=v.z; Qs[r][c4+3]=v.w;
    }
    if (t < 64) { mrow[t] = -1e30f; lrow[t] = 0.f; }

    float acc[16];
    #pragma unroll
    for (int i = 0; i < 16; i++) acc[i] = 0.f;
    const int r  = t >> 2;
    const int jq = t & 3;

    const int ntiles = (n_kv + 31) / 32;
    for (int kt = 0; kt < ntiles; kt++) {
        const int j0 = kt * 32;
        #pragma unroll
        for (int j = 0; j < 2; j++) {
            int idx4 = t + j * 256;
            int jr = idx4 >> 4, c4 = (idx4 & 15) * 4;
            int krow = j0 + jr;
            float4 kv = make_float4(0.f,0.f,0.f,0.f);
            float4 vv = make_float4(0.f,0.f,0.f,0.f);
            if (krow < n_kv) {
                kv = *(const float4*)&kb[(size_t)krow * ldkv + c4];
                vv = *(const float4*)&vb[(size_t)krow * ldkv + c4];
            }
            Ks[jr][c4+0]=kv.x; Ks[jr][c4+1]=kv.y; Ks[jr][c4+2]=kv.z; Ks[jr][c4+3]=kv.w;
            Vs[jr][c4+0]=vv.x; Vs[jr][c4+1]=vv.y; Vs[jr][c4+2]=vv.z; Vs[jr][c4+3]=vv.w;
        }
        __syncthreads();
        #pragma unroll
        for (int jj = 0; jj < 8; jj++) {
            int j = jq + 4*jj;
            float s = 0.f;
            #pragma unroll
            for (int d = 0; d < 64; d++) s += Qs[r][d] * Ks[j][d];
            Sx[r][j] = (j0 + j < n_kv) ? s * 0.125f : -1e30f;
        }
        __syncthreads();
        if (t < 64) {
            float m_old = mrow[t];
            float mnew = m_old;
            #pragma unroll 8
            for (int j = 0; j < 32; j++) mnew = fmaxf(mnew, Sx[t][j]);
            float alpha = __expf(m_old - mnew);
            float psum = 0.f;
            #pragma unroll 8
            for (int j = 0; j < 32; j++) {
                float p = __expf(Sx[t][j] - mnew);
                Sx[t][j] = p; psum += p;
            }
            mrow[t] = mnew;
            lrow[t] = lrow[t]*alpha + psum;
            arow[t] = alpha;
        }
        __syncthreads();
        float alpha = arow[r];
        #pragma unroll
        for (int i = 0; i < 16; i++) acc[i] *= alpha;
        #pragma unroll 4
        for (int j = 0; j < 32; j++) {
            float p = Sx[r][j];
            #pragma unroll
            for (int i = 0; i < 16; i++)
                acc[i] += p * Vs[j][jq + 4*i];
        }
        __syncthreads();
    }
    const float inv = 1.f / lrow[r];
    float* orow = O + ((size_t)(b * n_q + q0 + r)) * INNER_ + h * DHEAD_ + jq;
    #pragma unroll
    for (int i = 0; i < 16; i++) orow[4*i] = acc[i] * inv;
}

// ---------------- launch -------------------------------------------------------
extern "C" void kernel_launch(void* const* d_in, const int* in_sizes, int n_in,
                              void* d_out, int out_size)
{
    const float* x    = (const float*)d_in[0];
    const float* ctx  = (const float*)d_in[1];
    const float* gng  = (const float*)d_in[2];
    const float* gnb  = (const float*)d_in[3];
    const float* w_in = (const float*)d_in[4];
    const float* b_in = (const float*)d_in[5];
    const float* ln1g = (const float*)d_in[6];
    const float* ln1b = (const float*)d_in[7];
    const float* wq1  = (const float*)d_in[8];
    const float* wk1  = (const float*)d_in[9];
    const float* wv1  = (const float*)d_in[10];
    const float* wo1  = (const float*)d_in[11];
    const float* bo1  = (const float*)d_in[12];
    const float* ln2g = (const float*)d_in[13];
    const float* ln2b = (const float*)d_in[14];
    const float* wq2  = (const float*)d_in[15];
    const float* wk2  = (const float*)d_in[16];
    const float* wv2  = (const float*)d_in[17];
    const float* wo2  = (const float*)d_in[18];
    const float* bo2  = (const float*)d_in[19];
    const float* ln3g = (const float*)d_in[20];
    const float* ln3b = (const float*)d_in[21];
    const float* wff1 = (const float*)d_in[22];
    const float* bff1 = (const float*)d_in[23];
    const float* wff2 = (const float*)d_in[24];
    const float* bff2 = (const float*)d_in[25];
    const float* wout = (const float*)d_in[26];
    const float* bout = (const float*)d_in[27];
    float* out = (float*)d_out;

    float *hn,*t_,*q,*at,*qkv,*kvc,*gl,*st,*vt;
    float *wt_in,*wqkv,*wto1,*wtq2,*wtkv2,*wto2,*wtff1,*wtff2,*wtout;
    cudaGetSymbolAddress((void**)&hn,  g_hn);
    cudaGetSymbolAddress((void**)&t_,  g_t);
    cudaGetSymbolAddress((void**)&q,   g_q);
    cudaGetSymbolAddress((void**)&at,  g_at);
    cudaGetSymbolAddress((void**)&qkv, g_qkv);
    cudaGetSymbolAddress((void**)&kvc, g_kvc);
    cudaGetSymbolAddress((void**)&gl,  g_gl);
    cudaGetSymbolAddress((void**)&st,  g_stat);
    cudaGetSymbolAddress((void**)&vt,  g_vt);
    cudaGetSymbolAddress((void**)&wt_in, g_wt_in);
    cudaGetSymbolAddress((void**)&wqkv,  g_wqkv);
    cudaGetSymbolAddress((void**)&wto1,  g_wto1);
    cudaGetSymbolAddress((void**)&wtq2,  g_wtq2);
    cudaGetSymbolAddress((void**)&wtkv2, g_wtkv2);
    cudaGetSymbolAddress((void**)&wto2,  g_wto2);
    cudaGetSymbolAddress((void**)&wtff1, g_wtff1);
    cudaGetSymbolAddress((void**)&wtff2, g_wtff2);
    cudaGetSymbolAddress((void**)&wtout, g_wtout);

    const int SM2   = 2 * (128 * 36 + 128 * 36) * 4;              // 73728
    const int SMLN  = SM2 + (256 + 512 + 512) * 4;                // 78848
    const int SMFG  = 2 * (64 * 36 + 256 * 36) * 4
                      + (128 + 512 + 512) * 4;                    // 96768
    const int SMFA  = 384 * 68 * 4;                               // 104448
    cudaFuncSetAttribute(tgemm_k,    cudaFuncAttributeMaxDynamicSharedMemorySize, SM2);
    cudaFuncSetAttribute(tgemmQKV_k, cudaFuncAttributeMaxDynamicSharedMemorySize, SMLN);
    cudaFuncSetAttribute(xqkv_k,     cudaFuncAttributeMaxDynamicSharedMemorySize, SMLN);
    cudaFuncSetAttribute(tgemmT_k,   cudaFuncAttributeMaxDynamicSharedMemorySize, SM2);
    cudaFuncSetAttribute(ffgeglu_k,  cudaFuncAttributeMaxDynamicSharedMemorySize, SMFG);
    cudaFuncSetAttribute(fattn_k,    cudaFuncAttributeMaxDynamicSharedMemorySize, SMFA);

    const dim3 tb(32, 8);

    // merged preamble: weight transposes + GroupNorm stats
    TrJobs J;
    J.src[0]=w_in;  J.dst[0]=wt_in;            J.K[0]=512;  J.N[0]=512;
    J.src[1]=wq1;   J.dst[1]=wqkv;             J.K[1]=512;  J.N[1]=512;
    J.src[2]=wk1;   J.dst[2]=wqkv+512*512;     J.K[2]=512;  J.N[2]=512;
    J.src[3]=wv1;   J.dst[3]=wqkv+1024*512;    J.K[3]=512;  J.N[3]=512;
    J.src[4]=wo1;   J.dst[4]=wto1;             J.K[4]=512;  J.N[4]=512;
    J.src[5]=wq2;   J.dst[5]=wtq2;             J.K[5]=512;  J.N[5]=512;
    J.src[6]=wk2;   J.dst[6]=wtkv2;            J.K[6]=768;  J.N[6]=512;
    J.src[7]=wv2;   J.dst[7]=wtkv2+512*768;    J.K[7]=768;  J.N[7]=512;
    J.src[8]=wo2;   J.dst[8]=wto2;             J.K[8]=512;  J.N[8]=512;
    J.src[9]=wff1;  J.dst[9]=wtff1;            J.K[9]=512;  J.N[9]=4096;
    J.src[10]=wff2; J.dst[10]=wtff2;           J.K[10]=2048;J.N[10]=512;
    J.src[11]=wout; J.dst[11]=wtout;           J.K[11]=512; J.N[11]=512;
    int tot = 0;
    for (int i = 0; i < 12; i++) { J.tiles[i] = (J.K[i]/32)*(J.N[i]/32); tot += J.tiles[i]; }
    J.tot = tot;
    J.x = x;
    J.st = st;
    pre_k<<<tot + BB*32, 256>>>(J);

    // GroupNorm apply + proj_in
    gn_apply_t_k<<<dim3(72, 16, 2), tb>>>(x, st, gng, gnb, hn);
    tgemm_k<<<dim3(4, 36), 256, SM2>>>(hn, wt_in, b_in, nullptr, t_,
        MTOK, 512, 512, 512, 512);

    // self-attention (LN1 fused into qkv GEMM; v transposed into vt)
    tgemmQKV_k<<<dim3(12, 36), 256, SMLN>>>(t_, wqkv, ln1g, ln1b, qkv, vt);
    fattn_k<<<dim3(18, 8, 2), 256, SMFA>>>(qkv, vt, at);
    tgemm_k<<<dim3(4, 36), 256, SM2>>>(at, wto1, bo1, t_, t_,
        MTOK, 512, 512, 512, 512);

    // cross-attention (LN2 fused into q GEMM; kv GEMM merged into same launch)
    xqkv_k<<<dim3(4, 40), 256, SMLN>>>(t_, wtq2, ln2g, ln2b, q, ctx, wtkv2, kvc);
    attn_k<<<dim3(36, 8, 2), 256>>>(q, kvc, kvc + 512, at, NQ, CTX, 512, 1024);
    tgemm_k<<<dim3(4, 36), 256, SM2>>>(at, wto2, bo2, t_, t_,
        MTOK, 512, 512, 512, 512);

    // feed-forward: LN3 + ff1 + GEGLU fused, then ff2
    ffgeglu_k<<<dim3(16, 72), 256, SMFG>>>(t_, wtff1, ln3g, ln3b, bff1, gl);
    tgemm_k<<<dim3(4, 36), 256, SM2>>>(gl, wtff2, bff2, t_, t_,
        MTOK, 2048, 2048, 2048, 512);

    // proj_out + transpose + image residual (fused)
    tgemmT_k<<<dim3(4, 36), 256, SM2>>>(t_, wtout, bout, x, out);
}

// round 14
// speedup vs baseline: 1.1179x; 1.1179x over previous
#include <cuda_runtime.h>
#include <cstdint>
#include <math.h>

// ---------------- problem constants ----------------
#define BB     2
#define CC     512
#define NQ     2304
#define INNER_ 512
#define HEADS_ 8
#define DHEAD_ 64
#define CTX    77
#define CTXD   768
#define FFI    2048
#define MTOK   4608

// ---------------- scratch (device globals) ---------------------------------
__device__ float g_hn  [MTOK*INNER_];
__device__ float g_t   [MTOK*INNER_];
__device__ float g_q   [MTOK*INNER_];
__device__ float g_at  [MTOK*INNER_];
__device__ float g_qkv [MTOK*1536];
__device__ float g_kvc [160*1024];
__device__ float g_gl  [MTOK*FFI];
__device__ float g_stat[BB*32*2];
__device__ float g_vt  [16*DHEAD_*NQ];
// transposed weights [N,K]
__device__ float g_wt_in [512*512];
__device__ float g_wqkv  [1536*512];
__device__ float g_wto1  [512*512];
__device__ float g_wtq2  [512*512];
__device__ float g_wtkv2 [1024*768];
__device__ float g_wto2  [512*512];
__device__ float g_wtff1 [4096*512];
__device__ float g_wtff2 [512*2048];
__device__ float g_wtout [512*512];

// ---------------- PTX helpers ------------------------------------------------
__device__ __forceinline__ uint32_t smem_u32(const void* p) {
    uint32_t a;
    asm("{ .reg .u64 t; cvta.to.shared.u64 t, %1; cvt.u32.u64 %0, t; }"
        : "=r"(a) : "l"(p));
    return a;
}
__device__ __forceinline__ uint32_t f2tf(float x) {
    uint32_t r;
    asm("cvt.rna.tf32.f32 %0, %1;" : "=r"(r) : "f"(x));
    return r;
}
__device__ __forceinline__ void mma_t(float* c, const uint32_t* a, const uint32_t* b) {
    asm volatile("mma.sync.aligned.m16n8k8.row.col.f32.tf32.tf32.f32 "
        "{%0,%1,%2,%3}, {%4,%5,%6,%7}, {%8,%9}, {%0,%1,%2,%3};"
        : "+f"(c[0]), "+f"(c[1]), "+f"(c[2]), "+f"(c[3])
        : "r"(a[0]), "r"(a[1]), "r"(a[2]), "r"(a[3]), "r"(b[0]), "r"(b[1]));
}
__device__ __forceinline__ void cp16(uint32_t dst, const float* src, bool valid) {
    int sz = valid ? 16 : 0;
    asm volatile("cp.async.cg.shared.global [%0], [%1], 16, %2;"
                 :: "r"(dst), "l"(src), "r"(sz) : "memory");
}
#define CP_COMMIT() asm volatile("cp.async.commit_group;" ::: "memory")
#define CP_WAIT(n)  asm volatile("cp.async.wait_group %0;" :: "n"(n) : "memory")
#define U32(x) (*(const uint32_t*)&(x))

// ---------------- tf32 mma.sync GEMM (R4-proven 2-stage, 256 thr) ------------
__global__ void __launch_bounds__(256)
tgemm_k(const float* __restrict__ A, const float* __restrict__ Bt,
        const float* __restrict__ bias, const float* __restrict__ res,
        float* __restrict__ C,
        int M, int K, int lda, int ldb, int ldc)
{
    extern __shared__ float smem[];
    const int t = threadIdx.x, wid = t >> 5, lane = t & 31;
    const int bn = blockIdx.x * 128, bm = blockIdx.y * 128;

    constexpr int AFL = 128 * 36;
    constexpr int STR = 2 * AFL;

    const int mw = wid & 3, nw = wid >> 2;
    const int gp = lane >> 2, qd = lane & 3;

    float acc[2][8][4];
    #pragma unroll
    for (int i = 0; i < 2; i++)
        #pragma unroll
        for (int j = 0; j < 8; j++)
            #pragma unroll
            for (int c = 0; c < 4; c++) acc[i][j][c] = 0.f;

    const uint32_t sbase = smem_u32(smem);

    auto load_tile = [&](int kt, int buf) {
        const int k0 = kt * 32;
        const uint32_t offA = sbase + buf * STR * 4;
        const uint32_t offB = offA + AFL * 4;
        #pragma unroll
        for (int i = 0; i < 4; i++) {
            int idx = t + i * 256, row = idx >> 3, q = idx & 7;
            bool ok = (bm + row) < M;
            cp16(offA + (row * 36 + q * 4) * 4,
                 &A[(size_t)(ok ? bm + row : 0) * lda + k0 + q * 4], ok);
        }
        #pragma unroll
        for (int i = 0; i < 4; i++) {
            int idx = t + i * 256, row = idx >> 3, q = idx & 7;
            cp16(offB + (row * 36 + q * 4) * 4,
                 &Bt[(size_t)(bn + row) * ldb + k0 + q * 4], true);
        }
        CP_COMMIT();
    };

    const int KT = K / 32;
    load_tile(0, 0);

    for (int kt = 0; kt < KT; kt++) {
        const int cur = kt & 1;
        if (kt + 1 < KT) { load_tile(kt + 1, cur ^ 1); CP_WAIT(1); }
        else             { CP_WAIT(0); }
        __syncthreads();
        const float* As = smem + cur * STR;
        const float* Bs = As + AFL;
        #pragma unroll
        for (int ks = 0; ks < 4; ks++) {
            const int kc = ks * 8 + qd;
            uint32_t fA[2][4];
            #pragma unroll
            for (int mt = 0; mt < 2; mt++) {
                const int r = mw * 32 + mt * 16 + gp;
                fA[mt][0] = U32(As[(r    ) * 36 + kc    ]);
                fA[mt][1] = U32(As[(r + 8) * 36 + kc    ]);
                fA[mt][2] = U32(As[(r    ) * 36 + kc + 4]);
                fA[mt][3] = U32(As[(r + 8) * 36 + kc + 4]);
            }
            uint32_t fB[8][2];
            #pragma unroll
            for (int nt = 0; nt < 8; nt++) {
                const int n = nw * 64 + nt * 8 + gp;
                fB[nt][0] = U32(Bs[n * 36 + kc    ]);
                fB[nt][1] = U32(Bs[n * 36 + kc + 4]);
            }
            #pragma unroll
            for (int mt = 0; mt < 2; mt++)
                #pragma unroll
                for (int nt = 0; nt < 8; nt++)
                    mma_t(acc[mt][nt], fA[mt], fB[nt]);
        }
        __syncthreads();
    }

    #pragma unroll
    for (int mt = 0; mt < 2; mt++) {
        const int r0 = bm + mw * 32 + mt * 16 + gp;
        #pragma unroll
        for (int nt = 0; nt < 8; nt++) {
            const int col = bn + nw * 64 + nt * 8 + qd * 2;
            float2 lo = make_float2(acc[mt][nt][0], acc[mt][nt][1]);
            float2 hi = make_float2(acc[mt][nt][2], acc[mt][nt][3]);
            if (bias) {
                const float2 b2 = *(const float2*)&bias[col];
                lo.x += b2.x; lo.y += b2.y; hi.x += b2.x; hi.y += b2.y;
            }
            if (r0 < M) {
                if (res) {
                    const float2 r2 = *(const float2*)&res[(size_t)r0 * ldc + col];
                    lo.x += r2.x; lo.y += r2.y;
                }
                *(float2*)&C[(size_t)r0 * ldc + col] = lo;
            }
            if (r0 + 8 < M) {
                if (res) {
                    const float2 r2 = *(const float2*)&res[(size_t)(r0 + 8) * ldc + col];
                    hi.x += r2.x; hi.y += r2.y;
                }
                *(float2*)&C[(size_t)(r0 + 8) * ldc + col] = hi;
            }
        }
    }
}

// ---------------- qkv GEMM: q/k cols -> C, v cols -> transposed Vt -----------
__global__ void __launch_bounds__(256)
tgemmQKV_k(const float* __restrict__ A, const float* __restrict__ Bt,
           float* __restrict__ C, float* __restrict__ Vt)
{
    extern __shared__ float smem[];
    const int t = threadIdx.x, wid = t >> 5, lane = t & 31;
    const int bn = blockIdx.x * 128, bm = blockIdx.y * 128;

    constexpr int AFL = 128 * 36;
    constexpr int STR = 2 * AFL;

    const int mw = wid & 3, nw = wid >> 2;
    const int gp = lane >> 2, qd = lane & 3;

    float acc[2][8][4];
    #pragma unroll
    for (int i = 0; i < 2; i++)
        #pragma unroll
        for (int j = 0; j < 8; j++)
            #pragma unroll
            for (int c = 0; c < 4; c++) acc[i][j][c] = 0.f;

    const uint32_t sbase = smem_u32(smem);

    auto load_tile = [&](int kt, int buf) {
        const int k0 = kt * 32;
        const uint32_t offA = sbase + buf * STR * 4;
        const uint32_t offB = offA + AFL * 4;
        #pragma unroll
        for (int i = 0; i < 4; i++) {
            int idx = t + i * 256, row = idx >> 3, q = idx & 7;
            cp16(offA + (row * 36 + q * 4) * 4,
                 &A[(size_t)(bm + row) * 512 + k0 + q * 4], true);
        }
        #pragma unroll
        for (int i = 0; i < 4; i++) {
            int idx = t + i * 256, row = idx >> 3, q = idx & 7;
            cp16(offB + (row * 36 + q * 4) * 4,
                 &Bt[(size_t)(bn + row) * 512 + k0 + q * 4], true);
        }
        CP_COMMIT();
    };

    load_tile(0, 0);
    for (int kt = 0; kt < 16; kt++) {
        const int cur = kt & 1;
        if (kt + 1 < 16) { load_tile(kt + 1, cur ^ 1); CP_WAIT(1); }
        else             { CP_WAIT(0); }
        __syncthreads();
        const float* As = smem + cur * STR;
        const float* Bs = As + AFL;
        #pragma unroll
        for (int ks = 0; ks < 4; ks++) {
            const int kc = ks * 8 + qd;
            uint32_t fA[2][4];
            #pragma unroll
            for (int mt = 0; mt < 2; mt++) {
                const int r = mw * 32 + mt * 16 + gp;
                fA[mt][0] = U32(As[(r    ) * 36 + kc    ]);
                fA[mt][1] = U32(As[(r + 8) * 36 + kc    ]);
                fA[mt][2] = U32(As[(r    ) * 36 + kc + 4]);
                fA[mt][3] = U32(As[(r + 8) * 36 + kc + 4]);
            }
            uint32_t fB[8][2];
            #pragma unroll
            for (int nt = 0; nt < 8; nt++) {
                const int n = nw * 64 + nt * 8 + gp;
                fB[nt][0] = U32(Bs[n * 36 + kc    ]);
                fB[nt][1] = U32(Bs[n * 36 + kc + 4]);
            }
            #pragma unroll
            for (int mt = 0; mt < 2; mt++)
                #pragma unroll
                for (int nt = 0; nt < 8; nt++)
                    mma_t(acc[mt][nt], fA[mt], fB[nt]);
        }
        __syncthreads();
    }

    if (bn < 1024) {
        #pragma unroll
        for (int mt = 0; mt < 2; mt++) {
            const int r0 = bm + mw * 32 + mt * 16 + gp;
            #pragma unroll
            for (int nt = 0; nt < 8; nt++) {
                const int col = bn + nw * 64 + nt * 8 + qd * 2;
                *(float2*)&C[(size_t)r0 * 1536 + col] =
                    make_float2(acc[mt][nt][0], acc[mt][nt][1]);
                *(float2*)&C[(size_t)(r0 + 8) * 1536 + col] =
                    make_float2(acc[mt][nt][2], acc[mt][nt][3]);
            }
        }
    } else {
        float* tile = smem;
        __syncthreads();
        #pragma unroll
        for (int mt = 0; mt < 2; mt++) {
            const int nl0 = mw * 32 + mt * 16 + gp;
            #pragma unroll
            for (int nt = 0; nt < 8; nt++) {
                const int cl = nw * 64 + nt * 8 + qd * 2;
                tile[(cl    ) * 132 + nl0    ] = acc[mt][nt][0];
                tile[(cl + 1) * 132 + nl0    ] = acc[mt][nt][1];
                tile[(cl    ) * 132 + nl0 + 8] = acc[mt][nt][2];
                tile[(cl + 1) * 132 + nl0 + 8] = acc[mt][nt][3];
            }
        }
        __syncthreads();

        const int b = bm / NQ;
        const int n0 = bm - b * NQ;
        const int bnl = bn - 1024;
        #pragma unroll
        for (int i = 0; i < 16; i++) {
            int idx4 = t + i * 256;
            int cl = idx4 >> 5, n4 = (idx4 & 31) * 4;
            const int gcol = bnl + cl;
            const int h = gcol >> 6, d = gcol & 63;
            float* dst = &Vt[((size_t)(b * 8 + h) * 64 + d) * NQ + n0 + n4];
            float4 o;
            o.x = tile[cl * 132 + n4 + 0];
            o.y = tile[cl * 132 + n4 + 1];
            o.z = tile[cl * 132 + n4 + 2];
            o.w = tile[cl * 132 + n4 + 3];
            *(float4*)dst = o;
        }
    }
}

// ------ merged cross-attn projections: q GEMM (from hn) + ctx kv GEMM --------
// grid (4, 40): y<36 -> q path (A=hn, Bt=wtq2 -> Q ldc 512).
//               y>=36 -> kv path (ctx@wtkv2 -> KVc ldc 1024), 16 CTAs.
__global__ void __launch_bounds__(256)
xqkv_k(const float* __restrict__ A, const float* __restrict__ Bt,
       float* __restrict__ Q,
       const float* __restrict__ ctx, const float* __restrict__ Btkv,
       float* __restrict__ KVc)
{
    extern __shared__ float smem[];
    const int t = threadIdx.x, wid = t >> 5, lane = t & 31;

    constexpr int AFL = 128 * 36;
    constexpr int STR = 2 * AFL;

    const int mw = wid & 3, nw = wid >> 2;
    const int gp = lane >> 2, qd = lane & 3;

    float acc[2][8][4];
    #pragma unroll
    for (int i = 0; i < 2; i++)
        #pragma unroll
        for (int j = 0; j < 8; j++)
            #pragma unroll
            for (int c = 0; c < 4; c++) acc[i][j][c] = 0.f;

    const uint32_t sbase = smem_u32(smem);

    const bool qpath = blockIdx.y < 36;
    const float* Aa  = qpath ? A   : ctx;
    const float* Bb  = qpath ? Bt  : Btkv;
    int bn, bm, lda, KT, M;
    if (qpath) {
        bn = blockIdx.x * 128; bm = blockIdx.y * 128;
        lda = 512; KT = 16; M = MTOK;
    } else {
        const int idx16 = (blockIdx.y - 36) * 4 + blockIdx.x;   // 0..15
        bn = (idx16 & 7) * 128; bm = (idx16 >> 3) * 128;
        lda = 768; KT = 24; M = BB * CTX;
    }

    auto load_tile = [&](int kt, int buf) {
        const int k0 = kt * 32;
        const uint32_t offA = sbase + buf * STR * 4;
        const uint32_t offB = offA + AFL * 4;
        #pragma unroll
        for (int i = 0; i < 4; i++) {
            int idx = t + i * 256, row = idx >> 3, q = idx & 7;
            bool ok = (bm + row) < M;
            cp16(offA + (row * 36 + q * 4) * 4,
                 &Aa[(size_t)(ok ? bm + row : 0) * lda + k0 + q * 4], ok);
        }
        #pragma unroll
        for (int i = 0; i < 4; i++) {
            int idx = t + i * 256, row = idx >> 3, q = idx & 7;
            cp16(offB + (row * 36 + q * 4) * 4,
                 &Bb[(size_t)(bn + row) * lda + k0 + q * 4], true);
        }
        CP_COMMIT();
    };

    load_tile(0, 0);
    for (int kt = 0; kt < KT; kt++) {
        const int cur = kt & 1;
        if (kt + 1 < KT) { load_tile(kt + 1, cur ^ 1); CP_WAIT(1); }
        else             { CP_WAIT(0); }
        __syncthreads();
        const float* As = smem + cur * STR;
        const float* Bs = As + AFL;
        #pragma unroll
        for (int ks = 0; ks < 4; ks++) {
            const int kc = ks * 8 + qd;
            uint32_t fA[2][4];
            #pragma unroll
            for (int mt = 0; mt < 2; mt++) {
                const int r = mw * 32 + mt * 16 + gp;
                fA[mt][0] = U32(As[(r    ) * 36 + kc    ]);
                fA[mt][1] = U32(As[(r + 8) * 36 + kc    ]);
                fA[mt][2] = U32(As[(r    ) * 36 + kc + 4]);
                fA[mt][3] = U32(As[(r + 8) * 36 + kc + 4]);
            }
            uint32_t fB[8][2];
            #pragma unroll
            for (int nt = 0; nt < 8; nt++) {
                const int n = nw * 64 + nt * 8 + gp;
                fB[nt][0] = U32(Bs[n * 36 + kc    ]);
                fB[nt][1] = U32(Bs[n * 36 + kc + 4]);
            }
            #pragma unroll
            for (int mt = 0; mt < 2; mt++)
                #pragma unroll
                for (int nt = 0; nt < 8; nt++)
                    mma_t(acc[mt][nt], fA[mt], fB[nt]);
        }
        __syncthreads();
    }

    float* Cc = qpath ? Q : KVc;
    const int ldc = qpath ? 512 : 1024;
    #pragma unroll
    for (int mt = 0; mt < 2; mt++) {
        const int r0 = bm + mw * 32 + mt * 16 + gp;
        #pragma unroll
        for (int nt = 0; nt < 8; nt++) {
            const int col = bn + nw * 64 + nt * 8 + qd * 2;
            if (r0 < M)
                *(float2*)&Cc[(size_t)r0 * ldc + col] =
                    make_float2(acc[mt][nt][0], acc[mt][nt][1]);
            if (r0 + 8 < M)
                *(float2*)&Cc[(size_t)(r0 + 8) * ldc + col] =
                    make_float2(acc[mt][nt][2], acc[mt][nt][3]);
        }
    }
}

// ---------------- proj_out GEMM + transpose + image residual -----------------
__global__ void __launch_bounds__(256)
tgemmT_k(const float* __restrict__ A, const float* __restrict__ Bt,
         const float* __restrict__ bias, const float* __restrict__ x,
         float* __restrict__ out)
{
    extern __shared__ float smem[];
    const int t = threadIdx.x, wid = t >> 5, lane = t & 31;
    const int bn = blockIdx.x * 128, bm = blockIdx.y * 128;

    constexpr int AFL = 128 * 36;
    constexpr int STR = 2 * AFL;

    const int mw = wid & 3, nw = wid >> 2;
    const int gp = lane >> 2, qd = lane & 3;

    float acc[2][8][4];
    #pragma unroll
    for (int i = 0; i < 2; i++)
        #pragma unroll
        for (int j = 0; j < 8; j++)
            #pragma unroll
            for (int c = 0; c < 4; c++) acc[i][j][c] = 0.f;

    const uint32_t sbase = smem_u32(smem);

    auto load_tile = [&](int kt, int buf) {
        const int k0 = kt * 32;
        const uint32_t offA = sbase + buf * STR * 4;
        const uint32_t offB = offA + AFL * 4;
        #pragma unroll
        for (int i = 0; i < 4; i++) {
            int idx = t + i * 256, row = idx >> 3, q = idx & 7;
            cp16(offA + (row * 36 + q * 4) * 4,
                 &A[(size_t)(bm + row) * 512 + k0 + q * 4], true);
        }
        #pragma unroll
        for (int i = 0; i < 4; i++) {
            int idx = t + i * 256, row = idx >> 3, q = idx & 7;
            cp16(offB + (row * 36 + q * 4) * 4,
                 &Bt[(size_t)(bn + row) * 512 + k0 + q * 4], true);
        }
        CP_COMMIT();
    };

    load_tile(0, 0);
    for (int kt = 0; kt < 16; kt++) {
        const int cur = kt & 1;
        if (kt + 1 < 16) { load_tile(kt + 1, cur ^ 1); CP_WAIT(1); }
        else             { CP_WAIT(0); }
        __syncthreads();
        const float* As = smem + cur * STR;
        const float* Bs = As + AFL;
        #pragma unroll
        for (int ks = 0; ks < 4; ks++) {
            const int kc = ks * 8 + qd;
            uint32_t fA[2][4];
            #pragma unroll
            for (int mt = 0; mt < 2; mt++) {
                const int r = mw * 32 + mt * 16 + gp;
                fA[mt][0] = U32(As[(r    ) * 36 + kc    ]);
                fA[mt][1] = U32(As[(r + 8) * 36 + kc    ]);
                fA[mt][2] = U32(As[(r    ) * 36 + kc + 4]);
                fA[mt][3] = U32(As[(r + 8) * 36 + kc + 4]);
            }
            uint32_t fB[8][2];
            #pragma unroll
            for (int nt = 0; nt < 8; nt++) {
                const int n = nw * 64 + nt * 8 + gp;
                fB[nt][0] = U32(Bs[n * 36 + kc    ]);
                fB[nt][1] = U32(Bs[n * 36 + kc + 4]);
            }
            #pragma unroll
            for (int mt = 0; mt < 2; mt++)
                #pragma unroll
                for (int nt = 0; nt < 8; nt++)
                    mma_t(acc[mt][nt], fA[mt], fB[nt]);
        }
        __syncthreads();
    }

    float* tile = smem;
    __syncthreads();
    #pragma unroll
    for (int mt = 0; mt < 2; mt++) {
        const int nl0 = mw * 32 + mt * 16 + gp;
        #pragma unroll
        for (int nt = 0; nt < 8; nt++) {
            const int cl = nw * 64 + nt * 8 + qd * 2;
            const float2 b2 = *(const float2*)&bias[bn + cl];
            tile[(cl    ) * 132 + nl0    ] = acc[mt][nt][0] + b2.x;
            tile[(cl + 1) * 132 + nl0    ] = acc[mt][nt][1] + b2.y;
            tile[(cl    ) * 132 + nl0 + 8] = acc[mt][nt][2] + b2.x;
            tile[(cl + 1) * 132 + nl0 + 8] = acc[mt][nt][3] + b2.y;
        }
    }
    __syncthreads();

    const int b = bm / NQ;
    const int n0 = bm - b * NQ;
    #pragma unroll
    for (int i = 0; i < 16; i++) {
        int idx4 = t + i * 256;
        int cl = idx4 >> 5, n4 = (idx4 & 31) * 4;
        const size_t gidx = ((size_t)b * CC + bn + cl) * NQ + n0 + n4;
        const float4 xr = *(const float4*)&x[gidx];
        float4 o;
        o.x = tile[cl * 132 + n4 + 0] + xr.x;
        o.y = tile[cl * 132 + n4 + 1] + xr.y;
        o.z = tile[cl * 132 + n4 + 2] + xr.z;
        o.w = tile[cl * 132 + n4 + 3] + xr.w;
        *(float4*)&out[gidx] = o;
    }
}

// ---------------- fused FF1 + GEGLU (R9-proven) -------------------------------
__global__ void __launch_bounds__(256)
ffgeglu_k(const float* __restrict__ A, const float* __restrict__ Bt,
          const float* __restrict__ bias, float* __restrict__ GL)
{
    extern __shared__ float smem[];
    const int t = threadIdx.x, wid = t >> 5, lane = t & 31;
    const int bn = blockIdx.x * 128;
    const int bm = blockIdx.y * 64;

    constexpr int AFL = 64 * 36;
    constexpr int BFL = 256 * 36;
    constexpr int STR = AFL + BFL;

    const int mw = wid & 1, nw = wid >> 1;
    const int gp = lane >> 2, qd = lane & 3;

    float acc[2][2][4][4];
    #pragma unroll
    for (int h = 0; h < 2; h++)
        #pragma unroll
        for (int i = 0; i < 2; i++)
            #pragma unroll
            for (int j = 0; j < 4; j++)
                #pragma unroll
                for (int c = 0; c < 4; c++) acc[h][i][j][c] = 0.f;

    const uint32_t sbase = smem_u32(smem);

    auto load_tile = [&](int kt, int buf) {
        const int k0 = kt * 32;
        const uint32_t offA = sbase + buf * STR * 4;
        const uint32_t offB = offA + AFL * 4;
        #pragma unroll
        for (int i = 0; i < 2; i++) {
            int idx = t + i * 256, row = idx >> 3, q = idx & 7;
            cp16(offA + (row * 36 + q * 4) * 4,
                 &A[(size_t)(bm + row) * 512 + k0 + q * 4], true);
        }
        #pragma unroll
        for (int i = 0; i < 8; i++) {
            int idx = t + i * 256, row = idx >> 3, q = idx & 7;
            int grow = (row < 128) ? (bn + row) : (2048 + bn + row - 128);
            cp16(offB + (row * 36 + q * 4) * 4,
                 &Bt[(size_t)grow * 512 + k0 + q * 4], true);
        }
        CP_COMMIT();
    };

    load_tile(0, 0);
    for (int kt = 0; kt < 16; kt++) {
        const int cur = kt & 1;
        if (kt + 1 < 16) { load_tile(kt + 1, cur ^ 1); CP_WAIT(1); }
        else             { CP_WAIT(0); }
        __syncthreads();
        const float* As = smem + cur * STR;
        const float* Bs = As + AFL;
        #pragma unroll
        for (int ks = 0; ks < 4; ks++) {
            const int kc = ks * 8 + qd;
            uint32_t fA[2][4];
            #pragma unroll
            for (int mt = 0; mt < 2; mt++) {
                const int r = mw * 32 + mt * 16 + gp;
                fA[mt][0] = U32(As[(r    ) * 36 + kc    ]);
                fA[mt][1] = U32(As[(r + 8) * 36 + kc    ]);
                fA[mt][2] = U32(As[(r    ) * 36 + kc + 4]);
                fA[mt][3] = U32(As[(r + 8) * 36 + kc + 4]);
            }
            #pragma unroll
            for (int h = 0; h < 2; h++) {
                uint32_t fB[4][2];
                #pragma unroll
                for (int nt = 0; nt < 4; nt++) {
                    const int n = h * 128 + nw * 32 + nt * 8 + gp;
                    fB[nt][0] = U32(Bs[n * 36 + kc    ]);
                    fB[nt][1] = U32(Bs[n * 36 + kc + 4]);
                }
                #pragma unroll
                for (int mt = 0; mt < 2; mt++)
                    #pragma unroll
                    for (int nt = 0; nt < 4; nt++)
                        mma_t(acc[h][mt][nt], fA[mt], fB[nt]);
            }
        }
        __syncthreads();
    }

    #pragma unroll
    for (int mt = 0; mt < 2; mt++) {
        const int r0 = bm + mw * 32 + mt * 16 + gp;
        #pragma unroll
        for (int nt = 0; nt < 4; nt++) {
            const int col = bn + nw * 32 + nt * 8 + qd * 2;
            const float2 ba = *(const float2*)&bias[col];
            const float2 bg = *(const float2*)&bias[col + 2048];
            #pragma unroll
            for (int half_row = 0; half_row < 2; half_row++) {
                const int r = r0 + half_row * 8;
                float a0 = acc[0][mt][nt][half_row * 2 + 0] + ba.x;
                float a1 = acc[0][mt][nt][half_row * 2 + 1] + ba.y;
                float g0 = acc[1][mt][nt][half_row * 2 + 0] + bg.x;
                float g1 = acc[1][mt][nt][half_row * 2 + 1] + bg.y;
                float2 o;
                o.x = a0 * (0.5f * g0 * (1.f + erff(g0 * 0.70710678118654752f)));
                o.y = a1 * (0.5f * g1 * (1.f + erff(g1 * 0.70710678118654752f)));
                *(float2*)&GL[(size_t)r * 2048 + col] = o;
            }
        }
    }
}

// ---------------- flash self-attention (R9-proven simple version) ------------
__global__ void __launch_bounds__(256, 2) fattn_k(
    const float* __restrict__ QKV, const float* __restrict__ Vt,
    float* __restrict__ O)
{
    extern __shared__ float sm[];
    float* Qs  = sm;
    float* Ks  = Qs  + 128 * 68;
    float* Vts = Ks  +  64 * 68;
    float* Ps  = Vts +  64 * 68;

    const int t = threadIdx.x, w = t >> 5, lane = t & 31;
    const int gp = lane >> 2, qd = lane & 3;
    const int q0 = blockIdx.x * 128;
    const int h = blockIdx.y, b = blockIdx.z;

    const float* qb  = QKV + ((size_t)b * NQ) * 1536 + h * 64;
    const float* kb  = qb + 512;
    const float* vtb = Vt + ((size_t)(b * 8 + h)) * 64 * NQ;

    const uint32_t aQ = smem_u32(Qs), aK = smem_u32(Ks), aV = smem_u32(Vts);

    #pragma unroll
    for (int i = 0; i < 8; i++) {
        int idx = t + i * 256, r = idx >> 4, c4 = (idx & 15) * 4;
        cp16(aQ + (r * 68 + c4) * 4, &qb[(size_t)(q0 + r) * 1536 + c4], true);
    }
    CP_COMMIT(); CP_WAIT(0);
    __syncthreads();
    #pragma unroll
    for (int i = 0; i < 8; i++) {
        int idx = t + i * 256, r = idx >> 4, c4 = (idx & 15) * 4;
        float4* p = (float4*)&Qs[r * 68 + c4];
        float4 v = *p;
        v.x *= 0.125f; v.y *= 0.125f; v.z *= 0.125f; v.w *= 0.125f;
        *p = v;
    }
    __syncthreads();

    const int r0l = w * 16 + gp, r1l = r0l + 8;

    float o[8][4];
    #pragma unroll
    for (int nt = 0; nt < 8; nt++)
        #pragma unroll
        for (int c = 0; c < 4; c++) o[nt][c] = 0.f;
    float m0 = -1e30f, m1 = -1e30f, l0 = 0.f, l1 = 0.f;

    for (int kt = 0; kt < NQ / 64; kt++) {
        const int k0 = kt * 64;
        #pragma unroll
        for (int i = 0; i < 4; i++) {
            int idx = t + i * 256, r = idx >> 4, c4 = (idx & 15) * 4;
            cp16(aK + (r * 68 + c4) * 4, &kb[(size_t)(k0 + r) * 1536 + c4], true);
        }
        #pragma unroll
        for (int i = 0; i < 4; i++) {
            int idx = t + i * 256, d = idx >> 4, c4 = (idx & 15) * 4;
            cp16(aV + (d * 68 + c4) * 4, &vtb[(size_t)d * NQ + k0 + c4], true);
        }
        CP_COMMIT(); CP_WAIT(0);
        __syncthreads();

        float s[8][4];
        #pragma unroll
        for (int nt = 0; nt < 8; nt++)
            #pragma unroll
            for (int c = 0; c < 4; c++) s[nt][c] = 0.f;
        #pragma unroll
        for (int ks = 0; ks < 8; ks++) {
            const int kc = ks * 8 + qd;
            uint32_t af[4];
            af[0] = U32(Qs[r0l * 68 + kc    ]);
            af[1] = U32(Qs[r1l * 68 + kc    ]);
            af[2] = U32(Qs[r0l * 68 + kc + 4]);
            af[3] = U32(Qs[r1l * 68 + kc + 4]);
            #pragma unroll
            for (int nt = 0; nt < 8; nt++) {
                uint32_t bf[2];
                const int n = nt * 8 + gp;
                bf[0] = U32(Ks[n * 68 + kc    ]);
                bf[1] = U32(Ks[n * 68 + kc + 4]);
                mma_t(s[nt], af, bf);
            }
        }

        float tm0 = -1e30f, tm1 = -1e30f;
        #pragma unroll
        for (int nt = 0; nt < 8; nt++) {
            tm0 = fmaxf(tm0, fmaxf(s[nt][0], s[nt][1]));
            tm1 = fmaxf(tm1, fmaxf(s[nt][2], s[nt][3]));
        }
        tm0 = fmaxf(tm0, __shfl_xor_sync(~0u, tm0, 1));
        tm0 = fmaxf(tm0, __shfl_xor_sync(~0u, tm0, 2));
        tm1 = fmaxf(tm1, __shfl_xor_sync(~0u, tm1, 1));
        tm1 = fmaxf(tm1, __shfl_xor_sync(~0u, tm1, 2));
        const float mn0 = fmaxf(m0, tm0), mn1 = fmaxf(m1, tm1);
        const float al0 = __expf(m0 - mn0), al1 = __expf(m1 - mn1);
        float sum0 = 0.f, sum1 = 0.f;
        #pragma unroll
        for (int nt = 0; nt < 8; nt++) {
            s[nt][0] = __expf(s[nt][0] - mn0);
            s[nt][1] = __expf(s[nt][1] - mn0);
            s[nt][2] = __expf(s[nt][2] - mn1);
            s[nt][3] = __expf(s[nt][3] - mn1);
            sum0 += s[nt][0] + s[nt][1];
            sum1 += s[nt][2] + s[nt][3];
        }
        sum0 += __shfl_xor_sync(~0u, sum0, 1);
        sum0 += __shfl_xor_sync(~0u, sum0, 2);
        sum1 += __shfl_xor_sync(~0u, sum1, 1);
        sum1 += __shfl_xor_sync(~0u, sum1, 2);
        l0 = l0 * al0 + sum0;  m0 = mn0;
        l1 = l1 * al1 + sum1;  m1 = mn1;
        #pragma unroll
        for (int nt = 0; nt < 8; nt++) {
            o[nt][0] *= al0; o[nt][1] *= al0;
            o[nt][2] *= al1; o[nt][3] *= al1;
        }
        #pragma unroll
        for (int nt = 0; nt < 8; nt++) {
            *(float2*)&Ps[r0l * 68 + nt * 8 + 2 * qd] = make_float2(s[nt][0], s[nt][1]);
            *(float2*)&Ps[r1l * 68 + nt * 8 + 2 * qd] = make_float2(s[nt][2], s[nt][3]);
        }
        __syncthreads();

        #pragma unroll
        for (int ks = 0; ks < 8; ks++) {
            const int kc = ks * 8 + qd;
            uint32_t af[4];
            af[0] = U32(Ps[r0l * 68 + kc    ]);
            af[1] = U32(Ps[r1l * 68 + kc    ]);
            af[2] = U32(Ps[r0l * 68 + kc + 4]);
            af[3] = U32(Ps[r1l * 68 + kc + 4]);
            #pragma unroll
            for (int nt = 0; nt < 8; nt++) {
                uint32_t bf[2];
                const int n = nt * 8 + gp;
                bf[0] = U32(Vts[n * 68 + kc    ]);
                bf[1] = U32(Vts[n * 68 + kc + 4]);
                mma_t(o[nt], af, bf);
            }
        }
        __syncthreads();
    }

    const float i0 = 1.f / l0, i1 = 1.f / l1;
    const size_t gr0 = (size_t)(b * NQ + q0 + r0l);
    const size_t gr1 = gr0 + 8;
    #pragma unroll
    for (int nt = 0; nt < 8; nt++) {
        const int col = h * 64 + nt * 8 + 2 * qd;
        *(float2*)&O[gr0 * 512 + col] = make_float2(o[nt][0] * i0, o[nt][1] * i0);
        *(float2*)&O[gr1 * 512 + col] = make_float2(o[nt][2] * i1, o[nt][3] * i1);
    }
}

// ----- merged preamble: weight transposes (+rna) AND GroupNorm stats ---------
struct TrJobs {
    const float* src[12];
    float*       dst[12];
    int K[12], N[12], tiles[12];
    int tot;
    const float* x;
    float* st;
};
__global__ void pre_k(TrJobs J)
{
    const int tid = threadIdx.x;
    if ((int)blockIdx.x >= J.tot) {
        int bg = blockIdx.x - J.tot, b = bg >> 5, g = bg & 31;
        const float* base = J.x + ((size_t)b * CC + (size_t)g * 16) * NQ;
        float s = 0.f, s2 = 0.f;
        for (int i = tid; i < 16 * NQ; i += 256) {
            float v = base[i]; s += v; s2 += v * v;
        }
        for (int o = 16; o > 0; o >>= 1) {
            s  += __shfl_down_sync(~0u, s,  o);
            s2 += __shfl_down_sync(~0u, s2, o);
        }
        __shared__ float sh1[8], sh2[8];
        int w = tid >> 5, lane = tid & 31;
        if (lane == 0) { sh1[w] = s; sh2[w] = s2; }
        __syncthreads();
        if (tid == 0) {
            float S = 0.f, S2 = 0.f;
            for (int i = 0; i < 8; i++) { S += sh1[i]; S2 += sh2[i]; }
            float mean = S / (16.f * NQ);
            float var  = S2 / (16.f * NQ) - mean * mean;
            J.st[bg * 2]     = mean;
            J.st[bg * 2 + 1] = rsqrtf(var + 1e-6f);
        }
        return;
    }
    __shared__ float tl[32][33];
    int bid = blockIdx.x, j = 0;
    #pragma unroll
    for (int i = 0; i < 12; i++) {
        if (bid >= J.tiles[j]) { bid -= J.tiles[j]; j++; }
        else break;
    }
    const int kt = bid % (J.K[j] / 32), nt = bid / (J.K[j] / 32);
    const int k0 = kt * 32, n0 = nt * 32;
    const float* W = J.src[j];
    float* Wt = J.dst[j];
    const int K = J.K[j], N = J.N[j];
    int tx = tid & 31, ty = tid >> 5;
    #pragma unroll
    for (int i = 0; i < 4; i++) {
        float v = W[(size_t)(k0 + ty + i * 8) * N + n0 + tx];
        tl[ty + i * 8][tx] = __uint_as_float(f2tf(v));
    }
    __syncthreads();
    #pragma unroll
    for (int i = 0; i < 4; i++)
        Wt[(size_t)(n0 + ty + i * 8) * K + k0 + tx] = tl[tx][ty + i * 8];
}

// --------- GroupNorm apply + NCHW -> [b,n,c] transpose -----------------------
__global__ void gn_apply_t_k(const float* __restrict__ x, const float* __restrict__ st,
                             const float* __restrict__ gg, const float* __restrict__ gb,
                             float* __restrict__ o)
{
    __shared__ float tile[32][33];
    int n0 = blockIdx.x * 32, c0 = blockIdx.y * 32, b = blockIdx.z;
    int tx = threadIdx.x, ty = threadIdx.y;
    #pragma unroll
    for (int i = 0; i < 4; i++) {
        int c = c0 + ty + i * 8;
        int g = c >> 4;
        float mean = st[(b * 32 + g) * 2], rstd = st[(b * 32 + g) * 2 + 1];
        float v = x[((size_t)b * CC + c) * NQ + n0 + tx];
        tile[ty + i * 8][tx] = (v - mean) * rstd * gg[c] + gb[c];
    }
    __syncthreads();
    #pragma unroll
    for (int i = 0; i < 4; i++) {
        int n = n0 + ty + i * 8;
        o[((size_t)b * NQ + n) * INNER_ + c0 + tx] = tile[tx][ty + i * 8];
    }
}

// ---------------- LayerNorm over 512 -----------------------------------------
__global__ void ln_k(const float* __restrict__ X, const float* __restrict__ g,
                     const float* __restrict__ bb, float* __restrict__ O)
{
    int row = blockIdx.x;
    int t = threadIdx.x;
    const float4 v = ((const float4*)(X + (size_t)row * INNER_))[t];
    float s  = v.x + v.y + v.z + v.w;
    float s2 = v.x*v.x + v.y*v.y + v.z*v.z + v.w*v.w;
    for (int o = 16; o > 0; o >>= 1) {
        s  += __shfl_down_sync(~0u, s,  o);
        s2 += __shfl_down_sync(~0u, s2, o);
    }
    __shared__ float sh1[4], sh2[4];
    int w = t >> 5, lane = t & 31;
    if (lane == 0) { sh1[w] = s; sh2[w] = s2; }
    __syncthreads();
    if (t == 0) {
        float S = sh1[0]+sh1[1]+sh1[2]+sh1[3];
        float S2 = sh2[0]+sh2[1]+sh2[2]+sh2[3];
        float mean = S / 512.f;
        float var  = S2 / 512.f - mean * mean;
        sh1[0] = mean; sh2[0] = rsqrtf(var + 1e-5f);
    }
    __syncthreads();
    float mean = sh1[0], rstd = sh2[0];
    float4 g4 = ((const float4*)g)[t];
    float4 b4 = ((const float4*)bb)[t];
    float4 o;
    o.x = (v.x-mean)*rstd*g4.x + b4.x;
    o.y = (v.y-mean)*rstd*g4.y + b4.y;
    o.z = (v.z-mean)*rstd*g4.z + b4.z;
    o.w = (v.w-mean)*rstd*g4.w + b4.w;
    ((float4*)(O + (size_t)row * INNER_))[t] = o;
}

// ---------------- fp32 flash attention (cross-attn, 77 keys) -----------------
__global__ void __launch_bounds__(256) attn_k(
    const float* __restrict__ Q, const float* __restrict__ Kb,
    const float* __restrict__ Vb, float* __restrict__ O,
    int n_q, int n_kv, int ldq, int ldkv)
{
    __shared__ float Qs[64][68];
    __shared__ float Ks[32][68];
    __shared__ float Vs[32][68];
    __shared__ float Sx[64][33];
    __shared__ float mrow[64], lrow[64], arow[64];

    const int t  = threadIdx.x;
    const int h  = blockIdx.y, b = blockIdx.z;
    const int q0 = blockIdx.x * 64;
    const float* qb = Q  + ((size_t)b * n_q ) * ldq  + h * DHEAD_;
    const float* kb = Kb + ((size_t)b * n_kv) * ldkv + h * DHEAD_;
    const float* vb = Vb + ((size_t)b * n_kv) * ldkv + h * DHEAD_;

    #pragma unroll
    for (int j = 0; j < 4; j++) {
        int idx4 = t + j * 256;
        int r = idx4 >> 4, c4 = (idx4 & 15) * 4;
        float4 v = *(const float4*)&qb[(size_t)(q0 + r) * ldq + c4];
        Qs[r][c4+0]=v.x; Qs[r][c4+1]=v.y; Qs[r][c4+2]=v.z; Qs[r][c4+3]=v.w;
    }
    if (t < 64) { mrow[t] = -1e30f; lrow[t] = 0.f; }

    float acc[16];
    #pragma unroll
    for (int i = 0; i < 16; i++) acc[i] = 0.f;
    const int r  = t >> 2;
    const int jq = t & 3;

    const int ntiles = (n_kv + 31) / 32;
    for (int kt = 0; kt < ntiles; kt++) {
        const int j0 = kt * 32;
        #pragma unroll
        for (int j = 0; j < 2; j++) {
            int idx4 = t + j * 256;
            int jr = idx4 >> 4, c4 = (idx4 & 15) * 4;
            int krow = j0 + jr;
            float4 kv = make_float4(0.f,0.f,0.f,0.f);
            float4 vv = make_float4(0.f,0.f,0.f,0.f);
            if (krow < n_kv) {
                kv = *(const float4*)&kb[(size_t)krow * ldkv + c4];
                vv = *(const float4*)&vb[(size_t)krow * ldkv + c4];
            }
            Ks[jr][c4+0]=kv.x; Ks[jr][c4+1]=kv.y; Ks[jr][c4+2]=kv.z; Ks[jr][c4+3]=kv.w;
            Vs[jr][c4+0]=vv.x; Vs[jr][c4+1]=vv.y; Vs[jr][c4+2]=vv.z; Vs[jr][c4+3]=vv.w;
        }
        __syncthreads();
        #pragma unroll
        for (int jj = 0; jj < 8; jj++) {
            int j = jq + 4*jj;
            float s = 0.f;
            #pragma unroll
            for (int d = 0; d < 64; d++) s += Qs[r][d] * Ks[j][d];
            Sx[r][j] = (j0 + j < n_kv) ? s * 0.125f : -1e30f;
        }
        __syncthreads();
        if (t < 64) {
            float m_old = mrow[t];
            float mnew = m_old;
            #pragma unroll 8
            for (int j = 0; j < 32; j++) mnew = fmaxf(mnew, Sx[t][j]);
            float alpha = __expf(m_old - mnew);
            float psum = 0.f;
            #pragma unroll 8
            for (int j = 0; j < 32; j++) {
                float p = __expf(Sx[t][j] - mnew);
                Sx[t][j] = p; psum += p;
            }
            mrow[t] = mnew;
            lrow[t] = lrow[t]*alpha + psum;
            arow[t] = alpha;
        }
        __syncthreads();
        float alpha = arow[r];
        #pragma unroll
        for (int i = 0; i < 16; i++) acc[i] *= alpha;
        #pragma unroll 4
        for (int j = 0; j < 32; j++) {
            float p = Sx[r][j];
            #pragma unroll
            for (int i = 0; i < 16; i++)
                acc[i] += p * Vs[j][jq + 4*i];
        }
        __syncthreads();
    }
    const float inv = 1.f / lrow[r];
    float* orow = O + ((size_t)(b * n_q + q0 + r)) * INNER_ + h * DHEAD_ + jq;
    #pragma unroll
    for (int i = 0; i < 16; i++) orow[4*i] = acc[i] * inv;
}

// ---------------- launch -------------------------------------------------------
extern "C" void kernel_launch(void* const* d_in, const int* in_sizes, int n_in,
                              void* d_out, int out_size)
{
    const float* x    = (const float*)d_in[0];
    const float* ctx  = (const float*)d_in[1];
    const float* gng  = (const float*)d_in[2];
    const float* gnb  = (const float*)d_in[3];
    const float* w_in = (const float*)d_in[4];
    const float* b_in = (const float*)d_in[5];
    const float* ln1g = (const float*)d_in[6];
    const float* ln1b = (const float*)d_in[7];
    const float* wq1  = (const float*)d_in[8];
    const float* wk1  = (const float*)d_in[9];
    const float* wv1  = (const float*)d_in[10];
    const float* wo1  = (const float*)d_in[11];
    const float* bo1  = (const float*)d_in[12];
    const float* ln2g = (const float*)d_in[13];
    const float* ln2b = (const float*)d_in[14];
    const float* wq2  = (const float*)d_in[15];
    const float* wk2  = (const float*)d_in[16];
    const float* wv2  = (const float*)d_in[17];
    const float* wo2  = (const float*)d_in[18];
    const float* bo2  = (const float*)d_in[19];
    const float* ln3g = (const float*)d_in[20];
    const float* ln3b = (const float*)d_in[21];
    const float* wff1 = (const float*)d_in[22];
    const float* bff1 = (const float*)d_in[23];
    const float* wff2 = (const float*)d_in[24];
    const float* bff2 = (const float*)d_in[25];
    const float* wout = (const float*)d_in[26];
    const float* bout = (const float*)d_in[27];
    float* out = (float*)d_out;

    float *hn,*t_,*q,*at,*qkv,*kvc,*gl,*st,*vt;
    float *wt_in,*wqkv,*wto1,*wtq2,*wtkv2,*wto2,*wtff1,*wtff2,*wtout;
    cudaGetSymbolAddress((void**)&hn,  g_hn);
    cudaGetSymbolAddress((void**)&t_,  g_t);
    cudaGetSymbolAddress((void**)&q,   g_q);
    cudaGetSymbolAddress((void**)&at,  g_at);
    cudaGetSymbolAddress((void**)&qkv, g_qkv);
    cudaGetSymbolAddress((void**)&kvc, g_kvc);
    cudaGetSymbolAddress((void**)&gl,  g_gl);
    cudaGetSymbolAddress((void**)&st,  g_stat);
    cudaGetSymbolAddress((void**)&vt,  g_vt);
    cudaGetSymbolAddress((void**)&wt_in, g_wt_in);
    cudaGetSymbolAddress((void**)&wqkv,  g_wqkv);
    cudaGetSymbolAddress((void**)&wto1,  g_wto1);
    cudaGetSymbolAddress((void**)&wtq2,  g_wtq2);
    cudaGetSymbolAddress((void**)&wtkv2, g_wtkv2);
    cudaGetSymbolAddress((void**)&wto2,  g_wto2);
    cudaGetSymbolAddress((void**)&wtff1, g_wtff1);
    cudaGetSymbolAddress((void**)&wtff2, g_wtff2);
    cudaGetSymbolAddress((void**)&wtout, g_wtout);

    const int SM2  = 2 * (128 * 36 + 128 * 36) * 4;   // 73728
    const int SMFG = 2 * (64 * 36 + 256 * 36) * 4;    // 92160
    const int SMFA = 384 * 68 * 4;                    // 104448
    cudaFuncSetAttribute(tgemm_k,    cudaFuncAttributeMaxDynamicSharedMemorySize, SM2);
    cudaFuncSetAttribute(tgemmQKV_k, cudaFuncAttributeMaxDynamicSharedMemorySize, SM2);
    cudaFuncSetAttribute(xqkv_k,     cudaFuncAttributeMaxDynamicSharedMemorySize, SM2);
    cudaFuncSetAttribute(tgemmT_k,   cudaFuncAttributeMaxDynamicSharedMemorySize, SM2);
    cudaFuncSetAttribute(ffgeglu_k,  cudaFuncAttributeMaxDynamicSharedMemorySize, SMFG);
    cudaFuncSetAttribute(fattn_k,    cudaFuncAttributeMaxDynamicSharedMemorySize, SMFA);

    const dim3 tb(32, 8);

    // merged preamble: weight transposes + GroupNorm stats
    TrJobs J;
    J.src[0]=w_in;  J.dst[0]=wt_in;            J.K[0]=512;  J.N[0]=512;
    J.src[1]=wq1;   J.dst[1]=wqkv;             J.K[1]=512;  J.N[1]=512;
    J.src[2]=wk1;   J.dst[2]=wqkv+512*512;     J.K[2]=512;  J.N[2]=512;
    J.src[3]=wv1;   J.dst[3]=wqkv+1024*512;    J.K[3]=512;  J.N[3]=512;
    J.src[4]=wo1;   J.dst[4]=wto1;             J.K[4]=512;  J.N[4]=512;
    J.src[5]=wq2;   J.dst[5]=wtq2;             J.K[5]=512;  J.N[5]=512;
    J.src[6]=wk2;   J.dst[6]=wtkv2;            J.K[6]=768;  J.N[6]=512;
    J.src[7]=wv2;   J.dst[7]=wtkv2+512*768;    J.K[7]=768;  J.N[7]=512;
    J.src[8]=wo2;   J.dst[8]=wto2;             J.K[8]=512;  J.N[8]=512;
    J.src[9]=wff1;  J.dst[9]=wtff1;            J.K[9]=512;  J.N[9]=4096;
    J.src[10]=wff2; J.dst[10]=wtff2;           J.K[10]=2048;J.N[10]=512;
    J.src[11]=wout; J.dst[11]=wtout;           J.K[11]=512; J.N[11]=512;
    int tot = 0;
    for (int i = 0; i < 12; i++) { J.tiles[i] = (J.K[i]/32)*(J.N[i]/32); tot += J.tiles[i]; }
    J.tot = tot;
    J.x = x;
    J.st = st;
    pre_k<<<tot + BB*32, 256>>>(J);

    // GroupNorm apply + proj_in
    gn_apply_t_k<<<dim3(72, 16, 2), tb>>>(x, st, gng, gnb, hn);
    tgemm_k<<<dim3(4, 36), 256, SM2>>>(hn, wt_in, b_in, nullptr, t_,
        MTOK, 512, 512, 512, 512);

    // self-attention (qkv GEMM writes q/k to qkv, v transposed into vt)
    ln_k<<<MTOK, 128>>>(t_, ln1g, ln1b, hn);
    tgemmQKV_k<<<dim3(12, 36), 256, SM2>>>(hn, wqkv, qkv, vt);
    fattn_k<<<dim3(18, 8, 2), 256, SMFA>>>(qkv, vt, at);
    tgemm_k<<<dim3(4, 36), 256, SM2>>>(at, wto1, bo1, t_, t_,
        MTOK, 512, 512, 512, 512);

    // cross-attention (q GEMM + ctx kv GEMM merged into one launch)
    ln_k<<<MTOK, 128>>>(t_, ln2g, ln2b, hn);
    xqkv_k<<<dim3(4, 40), 256, SM2>>>(hn, wtq2, q, ctx, wtkv2, kvc);
    attn_k<<<dim3(36, 8, 2), 256>>>(q, kvc, kvc + 512, at, NQ, CTX, 512, 1024);
    tgemm_k<<<dim3(4, 36), 256, SM2>>>(at, wto2, bo2, t_, t_,
        MTOK, 512, 512, 512, 512);

    // feed-forward: fused ff1+GEGLU, then ff2
    ln_k<<<MTOK, 128>>>(t_, ln3g, ln3b, hn);
    ffgeglu_k<<<dim3(16, 72), 256, SMFG>>>(hn, wtff1, bff1, gl);
    tgemm_k<<<dim3(4, 36), 256, SM2>>>(gl, wtff2, bff2, t_, t_,
        MTOK, 2048, 2048, 2048, 512);

    // proj_out + transpose + image residual (fused)
    tgemmT_k<<<dim3(4, 36), 256, SM2>>>(t_, wtout, bout, x, out);
}

// round 15
// speedup vs baseline: 1.1211x; 1.0028x over previous
#include <cuda_runtime.h>
#include <cstdint>
#include <math.h>

// ---------------- problem constants ----------------
#define BB     2
#define CC     512
#define NQ     2304
#define INNER_ 512
#define HEADS_ 8
#define DHEAD_ 64
#define CTX    77
#define CTXD   768
#define FFI    2048
#define MTOK   4608

// ---------------- scratch (device globals) ---------------------------------
__device__ float g_hn  [MTOK*INNER_];
__device__ float g_t   [MTOK*INNER_];
__device__ float g_q   [MTOK*INNER_];
__device__ float g_at  [MTOK*INNER_];
__device__ float g_qkv [MTOK*1536];
__device__ float g_kvc [160*1024];
__device__ float g_gl  [MTOK*FFI];
__device__ float g_stat[BB*32*2];
__device__ float g_vt  [16*DHEAD_*NQ];
// transposed weights [N,K]
__device__ float g_wt_in [512*512];
__device__ float g_wqkv  [1536*512];
__device__ float g_wto1  [512*512];
__device__ float g_wtq2  [512*512];
__device__ float g_wtkv2 [1024*768];
__device__ float g_wto2  [512*512];
__device__ float g_wtff1 [4096*512];
__device__ float g_wtff2 [512*2048];
__device__ float g_wtout [512*512];

// ---------------- PTX helpers ------------------------------------------------
__device__ __forceinline__ uint32_t smem_u32(const void* p) {
    uint32_t a;
    asm("{ .reg .u64 t; cvta.to.shared.u64 t, %1; cvt.u32.u64 %0, t; }"
        : "=r"(a) : "l"(p));
    return a;
}
__device__ __forceinline__ uint32_t f2tf(float x) {
    uint32_t r;
    asm("cvt.rna.tf32.f32 %0, %1;" : "=r"(r) : "f"(x));
    return r;
}
__device__ __forceinline__ void mma_t(float* c, const uint32_t* a, const uint32_t* b) {
    asm volatile("mma.sync.aligned.m16n8k8.row.col.f32.tf32.tf32.f32 "
        "{%0,%1,%2,%3}, {%4,%5,%6,%7}, {%8,%9}, {%0,%1,%2,%3};"
        : "+f"(c[0]), "+f"(c[1]), "+f"(c[2]), "+f"(c[3])
        : "r"(a[0]), "r"(a[1]), "r"(a[2]), "r"(a[3]), "r"(b[0]), "r"(b[1]));
}
__device__ __forceinline__ void cp16(uint32_t dst, const float* src, bool valid) {
    int sz = valid ? 16 : 0;
    asm volatile("cp.async.cg.shared.global [%0], [%1], 16, %2;"
                 :: "r"(dst), "l"(src), "r"(sz) : "memory");
}
#define CP_COMMIT() asm volatile("cp.async.commit_group;" ::: "memory")
#define CP_WAIT(n)  asm volatile("cp.async.wait_group %0;" :: "n"(n) : "memory")
#define U32(x) (*(const uint32_t*)&(x))

// ---------------- tf32 mma.sync GEMM (R4-proven 2-stage, 256 thr) ------------
__global__ void __launch_bounds__(256)
tgemm_k(const float* __restrict__ A, const float* __restrict__ Bt,
        const float* __restrict__ bias, const float* __restrict__ res,
        float* __restrict__ C,
        int M, int K, int lda, int ldb, int ldc)
{
    extern __shared__ float smem[];
    const int t = threadIdx.x, wid = t >> 5, lane = t & 31;
    const int bn = blockIdx.x * 128, bm = blockIdx.y * 128;

    constexpr int AFL = 128 * 36;
    constexpr int STR = 2 * AFL;

    const int mw = wid & 3, nw = wid >> 2;
    const int gp = lane >> 2, qd = lane & 3;

    float acc[2][8][4];
    #pragma unroll
    for (int i = 0; i < 2; i++)
        #pragma unroll
        for (int j = 0; j < 8; j++)
            #pragma unroll
            for (int c = 0; c < 4; c++) acc[i][j][c] = 0.f;

    const uint32_t sbase = smem_u32(smem);

    auto load_tile = [&](int kt, int buf) {
        const int k0 = kt * 32;
        const uint32_t offA = sbase + buf * STR * 4;
        const uint32_t offB = offA + AFL * 4;
        #pragma unroll
        for (int i = 0; i < 4; i++) {
            int idx = t + i * 256, row = idx >> 3, q = idx & 7;
            bool ok = (bm + row) < M;
            cp16(offA + (row * 36 + q * 4) * 4,
                 &A[(size_t)(ok ? bm + row : 0) * lda + k0 + q * 4], ok);
        }
        #pragma unroll
        for (int i = 0; i < 4; i++) {
            int idx = t + i * 256, row = idx >> 3, q = idx & 7;
            cp16(offB + (row * 36 + q * 4) * 4,
                 &Bt[(size_t)(bn + row) * ldb + k0 + q * 4], true);
        }
        CP_COMMIT();
    };

    const int KT = K / 32;
    load_tile(0, 0);

    for (int kt = 0; kt < KT; kt++) {
        const int cur = kt & 1;
        if (kt + 1 < KT) { load_tile(kt + 1, cur ^ 1); CP_WAIT(1); }
        else             { CP_WAIT(0); }
        __syncthreads();
        const float* As = smem + cur * STR;
        const float* Bs = As + AFL;
        #pragma unroll
        for (int ks = 0; ks < 4; ks++) {
            const int kc = ks * 8 + qd;
            uint32_t fA[2][4];
            #pragma unroll
            for (int mt = 0; mt < 2; mt++) {
                const int r = mw * 32 + mt * 16 + gp;
                fA[mt][0] = U32(As[(r    ) * 36 + kc    ]);
                fA[mt][1] = U32(As[(r + 8) * 36 + kc    ]);
                fA[mt][2] = U32(As[(r    ) * 36 + kc + 4]);
                fA[mt][3] = U32(As[(r + 8) * 36 + kc + 4]);
            }
            uint32_t fB[8][2];
            #pragma unroll
            for (int nt = 0; nt < 8; nt++) {
                const int n = nw * 64 + nt * 8 + gp;
                fB[nt][0] = U32(Bs[n * 36 + kc    ]);
                fB[nt][1] = U32(Bs[n * 36 + kc + 4]);
            }
            #pragma unroll
            for (int mt = 0; mt < 2; mt++)
                #pragma unroll
                for (int nt = 0; nt < 8; nt++)
                    mma_t(acc[mt][nt], fA[mt], fB[nt]);
        }
        __syncthreads();
    }

    #pragma unroll
    for (int mt = 0; mt < 2; mt++) {
        const int r0 = bm + mw * 32 + mt * 16 + gp;
        #pragma unroll
        for (int nt = 0; nt < 8; nt++) {
            const int col = bn + nw * 64 + nt * 8 + qd * 2;
            float2 lo = make_float2(acc[mt][nt][0], acc[mt][nt][1]);
            float2 hi = make_float2(acc[mt][nt][2], acc[mt][nt][3]);
            if (bias) {
                const float2 b2 = *(const float2*)&bias[col];
                lo.x += b2.x; lo.y += b2.y; hi.x += b2.x; hi.y += b2.y;
            }
            if (r0 < M) {
                if (res) {
                    const float2 r2 = *(const float2*)&res[(size_t)r0 * ldc + col];
                    lo.x += r2.x; lo.y += r2.y;
                }
                *(float2*)&C[(size_t)r0 * ldc + col] = lo;
            }
            if (r0 + 8 < M) {
                if (res) {
                    const float2 r2 = *(const float2*)&res[(size_t)(r0 + 8) * ldc + col];
                    hi.x += r2.x; hi.y += r2.y;
                }
                *(float2*)&C[(size_t)(r0 + 8) * ldc + col] = hi;
            }
        }
    }
}

// ---------------- qkv GEMM: q/k cols -> C, v cols -> transposed Vt -----------
__global__ void __launch_bounds__(256)
tgemmQKV_k(const float* __restrict__ A, const float* __restrict__ Bt,
           float* __restrict__ C, float* __restrict__ Vt)
{
    extern __shared__ float smem[];
    const int t = threadIdx.x, wid = t >> 5, lane = t & 31;
    const int bn = blockIdx.x * 128, bm = blockIdx.y * 128;

    constexpr int AFL = 128 * 36;
    constexpr int STR = 2 * AFL;

    const int mw = wid & 3, nw = wid >> 2;
    const int gp = lane >> 2, qd = lane & 3;

    float acc[2][8][4];
    #pragma unroll
    for (int i = 0; i < 2; i++)
        #pragma unroll
        for (int j = 0; j < 8; j++)
            #pragma unroll
            for (int c = 0; c < 4; c++) acc[i][j][c] = 0.f;

    const uint32_t sbase = smem_u32(smem);

    auto load_tile = [&](int kt, int buf) {
        const int k0 = kt * 32;
        const uint32_t offA = sbase + buf * STR * 4;
        const uint32_t offB = offA + AFL * 4;
        #pragma unroll
        for (int i = 0; i < 4; i++) {
            int idx = t + i * 256, row = idx >> 3, q = idx & 7;
            cp16(offA + (row * 36 + q * 4) * 4,
                 &A[(size_t)(bm + row) * 512 + k0 + q * 4], true);
        }
        #pragma unroll
        for (int i = 0; i < 4; i++) {
            int idx = t + i * 256, row = idx >> 3, q = idx & 7;
            cp16(offB + (row * 36 + q * 4) * 4,
                 &Bt[(size_t)(bn + row) * 512 + k0 + q * 4], true);
        }
        CP_COMMIT();
    };

    load_tile(0, 0);
    for (int kt = 0; kt < 16; kt++) {
        const int cur = kt & 1;
        if (kt + 1 < 16) { load_tile(kt + 1, cur ^ 1); CP_WAIT(1); }
        else             { CP_WAIT(0); }
        __syncthreads();
        const float* As = smem + cur * STR;
        const float* Bs = As + AFL;
        #pragma unroll
        for (int ks = 0; ks < 4; ks++) {
            const int kc = ks * 8 + qd;
            uint32_t fA[2][4];
            #pragma unroll
            for (int mt = 0; mt < 2; mt++) {
                const int r = mw * 32 + mt * 16 + gp;
                fA[mt][0] = U32(As[(r    ) * 36 + kc    ]);
                fA[mt][1] = U32(As[(r + 8) * 36 + kc    ]);
                fA[mt][2] = U32(As[(r    ) * 36 + kc + 4]);
                fA[mt][3] = U32(As[(r + 8) * 36 + kc + 4]);
            }
            uint32_t fB[8][2];
            #pragma unroll
            for (int nt = 0; nt < 8; nt++) {
                const int n = nw * 64 + nt * 8 + gp;
                fB[nt][0] = U32(Bs[n * 36 + kc    ]);
                fB[nt][1] = U32(Bs[n * 36 + kc + 4]);
            }
            #pragma unroll
            for (int mt = 0; mt < 2; mt++)
                #pragma unroll
                for (int nt = 0; nt < 8; nt++)
                    mma_t(acc[mt][nt], fA[mt], fB[nt]);
        }
        __syncthreads();
    }

    if (bn < 1024) {
        #pragma unroll
        for (int mt = 0; mt < 2; mt++) {
            const int r0 = bm + mw * 32 + mt * 16 + gp;
            #pragma unroll
            for (int nt = 0; nt < 8; nt++) {
                const int col = bn + nw * 64 + nt * 8 + qd * 2;
                *(float2*)&C[(size_t)r0 * 1536 + col] =
                    make_float2(acc[mt][nt][0], acc[mt][nt][1]);
                *(float2*)&C[(size_t)(r0 + 8) * 1536 + col] =
                    make_float2(acc[mt][nt][2], acc[mt][nt][3]);
            }
        }
    } else {
        float* tile = smem;
        __syncthreads();
        #pragma unroll
        for (int mt = 0; mt < 2; mt++) {
            const int nl0 = mw * 32 + mt * 16 + gp;
            #pragma unroll
            for (int nt = 0; nt < 8; nt++) {
                const int cl = nw * 64 + nt * 8 + qd * 2;
                tile[(cl    ) * 132 + nl0    ] = acc[mt][nt][0];
                tile[(cl + 1) * 132 + nl0    ] = acc[mt][nt][1];
                tile[(cl    ) * 132 + nl0 + 8] = acc[mt][nt][2];
                tile[(cl + 1) * 132 + nl0 + 8] = acc[mt][nt][3];
            }
        }
        __syncthreads();

        const int b = bm / NQ;
        const int n0 = bm - b * NQ;
        const int bnl = bn - 1024;
        #pragma unroll
        for (int i = 0; i < 16; i++) {
            int idx4 = t + i * 256;
            int cl = idx4 >> 5, n4 = (idx4 & 31) * 4;
            const int gcol = bnl + cl;
            const int h = gcol >> 6, d = gcol & 63;
            float* dst = &Vt[((size_t)(b * 8 + h) * 64 + d) * NQ + n0 + n4];
            float4 o;
            o.x = tile[cl * 132 + n4 + 0];
            o.y = tile[cl * 132 + n4 + 1];
            o.z = tile[cl * 132 + n4 + 2];
            o.w = tile[cl * 132 + n4 + 3];
            *(float4*)dst = o;
        }
    }
}

// ------ merged cross-attn projections: q GEMM (from hn) + ctx kv GEMM --------
__global__ void __launch_bounds__(256)
xqkv_k(const float* __restrict__ A, const float* __restrict__ Bt,
       float* __restrict__ Q,
       const float* __restrict__ ctx, const float* __restrict__ Btkv,
       float* __restrict__ KVc)
{
    extern __shared__ float smem[];
    const int t = threadIdx.x, wid = t >> 5, lane = t & 31;

    constexpr int AFL = 128 * 36;
    constexpr int STR = 2 * AFL;

    const int mw = wid & 3, nw = wid >> 2;
    const int gp = lane >> 2, qd = lane & 3;

    float acc[2][8][4];
    #pragma unroll
    for (int i = 0; i < 2; i++)
        #pragma unroll
        for (int j = 0; j < 8; j++)
            #pragma unroll
            for (int c = 0; c < 4; c++) acc[i][j][c] = 0.f;

    const uint32_t sbase = smem_u32(smem);

    const bool qpath = blockIdx.y < 36;
    const float* Aa  = qpath ? A   : ctx;
    const float* Bb  = qpath ? Bt  : Btkv;
    int bn, bm, lda, KT, M;
    if (qpath) {
        bn = blockIdx.x * 128; bm = blockIdx.y * 128;
        lda = 512; KT = 16; M = MTOK;
    } else {
        const int idx16 = (blockIdx.y - 36) * 4 + blockIdx.x;   // 0..15
        bn = (idx16 & 7) * 128; bm = (idx16 >> 3) * 128;
        lda = 768; KT = 24; M = BB * CTX;
    }

    auto load_tile = [&](int kt, int buf) {
        const int k0 = kt * 32;
        const uint32_t offA = sbase + buf * STR * 4;
        const uint32_t offB = offA + AFL * 4;
        #pragma unroll
        for (int i = 0; i < 4; i++) {
            int idx = t + i * 256, row = idx >> 3, q = idx & 7;
            bool ok = (bm + row) < M;
            cp16(offA + (row * 36 + q * 4) * 4,
                 &Aa[(size_t)(ok ? bm + row : 0) * lda + k0 + q * 4], ok);
        }
        #pragma unroll
        for (int i = 0; i < 4; i++) {
            int idx = t + i * 256, row = idx >> 3, q = idx & 7;
            cp16(offB + (row * 36 + q * 4) * 4,
                 &Bb[(size_t)(bn + row) * lda + k0 + q * 4], true);
        }
        CP_COMMIT();
    };

    load_tile(0, 0);
    for (int kt = 0; kt < KT; kt++) {
        const int cur = kt & 1;
        if (kt + 1 < KT) { load_tile(kt + 1, cur ^ 1); CP_WAIT(1); }
        else             { CP_WAIT(0); }
        __syncthreads();
        const float* As = smem + cur * STR;
        const float* Bs = As + AFL;
        #pragma unroll
        for (int ks = 0; ks < 4; ks++) {
            const int kc = ks * 8 + qd;
            uint32_t fA[2][4];
            #pragma unroll
            for (int mt = 0; mt < 2; mt++) {
                const int r = mw * 32 + mt * 16 + gp;
                fA[mt][0] = U32(As[(r    ) * 36 + kc    ]);
                fA[mt][1] = U32(As[(r + 8) * 36 + kc    ]);
                fA[mt][2] = U32(As[(r    ) * 36 + kc + 4]);
                fA[mt][3] = U32(As[(r + 8) * 36 + kc + 4]);
            }
            uint32_t fB[8][2];
            #pragma unroll
            for (int nt = 0; nt < 8; nt++) {
                const int n = nw * 64 + nt * 8 + gp;
                fB[nt][0] = U32(Bs[n * 36 + kc    ]);
                fB[nt][1] = U32(Bs[n * 36 + kc + 4]);
            }
            #pragma unroll
            for (int mt = 0; mt < 2; mt++)
                #pragma unroll
                for (int nt = 0; nt < 8; nt++)
                    mma_t(acc[mt][nt], fA[mt], fB[nt]);
        }
        __syncthreads();
    }

    float* Cc = qpath ? Q : KVc;
    const int ldc = qpath ? 512 : 1024;
    #pragma unroll
    for (int mt = 0; mt < 2; mt++) {
        const int r0 = bm + mw * 32 + mt * 16 + gp;
        #pragma unroll
        for (int nt = 0; nt < 8; nt++) {
            const int col = bn + nw * 64 + nt * 8 + qd * 2;
            if (r0 < M)
                *(float2*)&Cc[(size_t)r0 * ldc + col] =
                    make_float2(acc[mt][nt][0], acc[mt][nt][1]);
            if (r0 + 8 < M)
                *(float2*)&Cc[(size_t)(r0 + 8) * ldc + col] =
                    make_float2(acc[mt][nt][2], acc[mt][nt][3]);
        }
    }
}

// ---------------- proj_out GEMM + transpose + image residual -----------------
__global__ void __launch_bounds__(256)
tgemmT_k(const float* __restrict__ A, const float* __restrict__ Bt,
         const float* __restrict__ bias, const float* __restrict__ x,
         float* __restrict__ out)
{
    extern __shared__ float smem[];
    const int t = threadIdx.x, wid = t >> 5, lane = t & 31;
    const int bn = blockIdx.x * 128, bm = blockIdx.y * 128;

    constexpr int AFL = 128 * 36;
    constexpr int STR = 2 * AFL;

    const int mw = wid & 3, nw = wid >> 2;
    const int gp = lane >> 2, qd = lane & 3;

    float acc[2][8][4];
    #pragma unroll
    for (int i = 0; i < 2; i++)
        #pragma unroll
        for (int j = 0; j < 8; j++)
            #pragma unroll
            for (int c = 0; c < 4; c++) acc[i][j][c] = 0.f;

    const uint32_t sbase = smem_u32(smem);

    auto load_tile = [&](int kt, int buf) {
        const int k0 = kt * 32;
        const uint32_t offA = sbase + buf * STR * 4;
        const uint32_t offB = offA + AFL * 4;
        #pragma unroll
        for (int i = 0; i < 4; i++) {
            int idx = t + i * 256, row = idx >> 3, q = idx & 7;
            cp16(offA + (row * 36 + q * 4) * 4,
                 &A[(size_t)(bm + row) * 512 + k0 + q * 4], true);
        }
        #pragma unroll
        for (int i = 0; i < 4; i++) {
            int idx = t + i * 256, row = idx >> 3, q = idx & 7;
            cp16(offB + (row * 36 + q * 4) * 4,
                 &Bt[(size_t)(bn + row) * 512 + k0 + q * 4], true);
        }
        CP_COMMIT();
    };

    load_tile(0, 0);
    for (int kt = 0; kt < 16; kt++) {
        const int cur = kt & 1;
        if (kt + 1 < 16) { load_tile(kt + 1, cur ^ 1); CP_WAIT(1); }
        else             { CP_WAIT(0); }
        __syncthreads();
        const float* As = smem + cur * STR;
        const float* Bs = As + AFL;
        #pragma unroll
        for (int ks = 0; ks < 4; ks++) {
            const int kc = ks * 8 + qd;
            uint32_t fA[2][4];
            #pragma unroll
            for (int mt = 0; mt < 2; mt++) {
                const int r = mw * 32 + mt * 16 + gp;
                fA[mt][0] = U32(As[(r    ) * 36 + kc    ]);
                fA[mt][1] = U32(As[(r + 8) * 36 + kc    ]);
                fA[mt][2] = U32(As[(r    ) * 36 + kc + 4]);
                fA[mt][3] = U32(As[(r + 8) * 36 + kc + 4]);
            }
            uint32_t fB[8][2];
            #pragma unroll
            for (int nt = 0; nt < 8; nt++) {
                const int n = nw * 64 + nt * 8 + gp;
                fB[nt][0] = U32(Bs[n * 36 + kc    ]);
                fB[nt][1] = U32(Bs[n * 36 + kc + 4]);
            }
            #pragma unroll
            for (int mt = 0; mt < 2; mt++)
                #pragma unroll
                for (int nt = 0; nt < 8; nt++)
                    mma_t(acc[mt][nt], fA[mt], fB[nt]);
        }
        __syncthreads();
    }

    float* tile = smem;
    __syncthreads();
    #pragma unroll
    for (int mt = 0; mt < 2; mt++) {
        const int nl0 = mw * 32 + mt * 16 + gp;
        #pragma unroll
        for (int nt = 0; nt < 8; nt++) {
            const int cl = nw * 64 + nt * 8 + qd * 2;
            const float2 b2 = *(const float2*)&bias[bn + cl];
            tile[(cl    ) * 132 + nl0    ] = acc[mt][nt][0] + b2.x;
            tile[(cl + 1) * 132 + nl0    ] = acc[mt][nt][1] + b2.y;
            tile[(cl    ) * 132 + nl0 + 8] = acc[mt][nt][2] + b2.x;
            tile[(cl + 1) * 132 + nl0 + 8] = acc[mt][nt][3] + b2.y;
        }
    }
    __syncthreads();

    const int b = bm / NQ;
    const int n0 = bm - b * NQ;
    #pragma unroll
    for (int i = 0; i < 16; i++) {
        int idx4 = t + i * 256;
        int cl = idx4 >> 5, n4 = (idx4 & 31) * 4;
        const size_t gidx = ((size_t)b * CC + bn + cl) * NQ + n0 + n4;
        const float4 xr = *(const float4*)&x[gidx];
        float4 o;
        o.x = tile[cl * 132 + n4 + 0] + xr.x;
        o.y = tile[cl * 132 + n4 + 1] + xr.y;
        o.z = tile[cl * 132 + n4 + 2] + xr.z;
        o.w = tile[cl * 132 + n4 + 3] + xr.w;
        *(float4*)&out[gidx] = o;
    }
}

// ---------------- fused FF1 + GEGLU (R9-proven) -------------------------------
__global__ void __launch_bounds__(256)
ffgeglu_k(const float* __restrict__ A, const float* __restrict__ Bt,
          const float* __restrict__ bias, float* __restrict__ GL)
{
    extern __shared__ float smem[];
    const int t = threadIdx.x, wid = t >> 5, lane = t & 31;
    const int bn = blockIdx.x * 128;
    const int bm = blockIdx.y * 64;

    constexpr int AFL = 64 * 36;
    constexpr int BFL = 256 * 36;
    constexpr int STR = AFL + BFL;

    const int mw = wid & 1, nw = wid >> 1;
    const int gp = lane >> 2, qd = lane & 3;

    float acc[2][2][4][4];
    #pragma unroll
    for (int h = 0; h < 2; h++)
        #pragma unroll
        for (int i = 0; i < 2; i++)
            #pragma unroll
            for (int j = 0; j < 4; j++)
                #pragma unroll
                for (int c = 0; c < 4; c++) acc[h][i][j][c] = 0.f;

    const uint32_t sbase = smem_u32(smem);

    auto load_tile = [&](int kt, int buf) {
        const int k0 = kt * 32;
        const uint32_t offA = sbase + buf * STR * 4;
        const uint32_t offB = offA + AFL * 4;
        #pragma unroll
        for (int i = 0; i < 2; i++) {
            int idx = t + i * 256, row = idx >> 3, q = idx & 7;
            cp16(offA + (row * 36 + q * 4) * 4,
                 &A[(size_t)(bm + row) * 512 + k0 + q * 4], true);
        }
        #pragma unroll
        for (int i = 0; i < 8; i++) {
            int idx = t + i * 256, row = idx >> 3, q = idx & 7;
            int grow = (row < 128) ? (bn + row) : (2048 + bn + row - 128);
            cp16(offB + (row * 36 + q * 4) * 4,
                 &Bt[(size_t)grow * 512 + k0 + q * 4], true);
        }
        CP_COMMIT();
    };

    load_tile(0, 0);
    for (int kt = 0; kt < 16; kt++) {
        const int cur = kt & 1;
        if (kt + 1 < 16) { load_tile(kt + 1, cur ^ 1); CP_WAIT(1); }
        else             { CP_WAIT(0); }
        __syncthreads();
        const float* As = smem + cur * STR;
        const float* Bs = As + AFL;
        #pragma unroll
        for (int ks = 0; ks < 4; ks++) {
            const int kc = ks * 8 + qd;
            uint32_t fA[2][4];
            #pragma unroll
            for (int mt = 0; mt < 2; mt++) {
                const int r = mw * 32 + mt * 16 + gp;
                fA[mt][0] = U32(As[(r    ) * 36 + kc    ]);
                fA[mt][1] = U32(As[(r + 8) * 36 + kc    ]);
                fA[mt][2] = U32(As[(r    ) * 36 + kc + 4]);
                fA[mt][3] = U32(As[(r + 8) * 36 + kc + 4]);
            }
            #pragma unroll
            for (int h = 0; h < 2; h++) {
                uint32_t fB[4][2];
                #pragma unroll
                for (int nt = 0; nt < 4; nt++) {
                    const int n = h * 128 + nw * 32 + nt * 8 + gp;
                    fB[nt][0] = U32(Bs[n * 36 + kc    ]);
                    fB[nt][1] = U32(Bs[n * 36 + kc + 4]);
                }
                #pragma unroll
                for (int mt = 0; mt < 2; mt++)
                    #pragma unroll
                    for (int nt = 0; nt < 4; nt++)
                        mma_t(acc[h][mt][nt], fA[mt], fB[nt]);
            }
        }
        __syncthreads();
    }

    #pragma unroll
    for (int mt = 0; mt < 2; mt++) {
        const int r0 = bm + mw * 32 + mt * 16 + gp;
        #pragma unroll
        for (int nt = 0; nt < 4; nt++) {
            const int col = bn + nw * 32 + nt * 8 + qd * 2;
            const float2 ba = *(const float2*)&bias[col];
            const float2 bg = *(const float2*)&bias[col + 2048];
            #pragma unroll
            for (int half_row = 0; half_row < 2; half_row++) {
                const int r = r0 + half_row * 8;
                float a0 = acc[0][mt][nt][half_row * 2 + 0] + ba.x;
                float a1 = acc[0][mt][nt][half_row * 2 + 1] + ba.y;
                float g0 = acc[1][mt][nt][half_row * 2 + 0] + bg.x;
                float g1 = acc[1][mt][nt][half_row * 2 + 1] + bg.y;
                float2 o;
                o.x = a0 * (0.5f * g0 * (1.f + erff(g0 * 0.70710678118654752f)));
                o.y = a1 * (0.5f * g1 * (1.f + erff(g1 * 0.70710678118654752f)));
                *(float2*)&GL[(size_t)r * 2048 + col] = o;
            }
        }
    }
}

// ---------------- flash self-attention (R9-proven simple version) ------------
__global__ void __launch_bounds__(256, 2) fattn_k(
    const float* __restrict__ QKV, const float* __restrict__ Vt,
    float* __restrict__ O)
{
    extern __shared__ float sm[];
    float* Qs  = sm;
    float* Ks  = Qs  + 128 * 68;
    float* Vts = Ks  +  64 * 68;
    float* Ps  = Vts +  64 * 68;

    const int t = threadIdx.x, w = t >> 5, lane = t & 31;
    const int gp = lane >> 2, qd = lane & 3;
    const int q0 = blockIdx.x * 128;
    const int h = blockIdx.y, b = blockIdx.z;

    const float* qb  = QKV + ((size_t)b * NQ) * 1536 + h * 64;
    const float* kb  = qb + 512;
    const float* vtb = Vt + ((size_t)(b * 8 + h)) * 64 * NQ;

    const uint32_t aQ = smem_u32(Qs), aK = smem_u32(Ks), aV = smem_u32(Vts);

    #pragma unroll
    for (int i = 0; i < 8; i++) {
        int idx = t + i * 256, r = idx >> 4, c4 = (idx & 15) * 4;
        cp16(aQ + (r * 68 + c4) * 4, &qb[(size_t)(q0 + r) * 1536 + c4], true);
    }
    CP_COMMIT(); CP_WAIT(0);
    __syncthreads();
    #pragma unroll
    for (int i = 0; i < 8; i++) {
        int idx = t + i * 256, r = idx >> 4, c4 = (idx & 15) * 4;
        float4* p = (float4*)&Qs[r * 68 + c4];
        float4 v = *p;
        v.x *= 0.125f; v.y *= 0.125f; v.z *= 0.125f; v.w *= 0.125f;
        *p = v;
    }
    __syncthreads();

    const int r0l = w * 16 + gp, r1l = r0l + 8;

    float o[8][4];
    #pragma unroll
    for (int nt = 0; nt < 8; nt++)
        #pragma unroll
        for (int c = 0; c < 4; c++) o[nt][c] = 0.f;
    float m0 = -1e30f, m1 = -1e30f, l0 = 0.f, l1 = 0.f;

    for (int kt = 0; kt < NQ / 64; kt++) {
        const int k0 = kt * 64;
        #pragma unroll
        for (int i = 0; i < 4; i++) {
            int idx = t + i * 256, r = idx >> 4, c4 = (idx & 15) * 4;
            cp16(aK + (r * 68 + c4) * 4, &kb[(size_t)(k0 + r) * 1536 + c4], true);
        }
        #pragma unroll
        for (int i = 0; i < 4; i++) {
            int idx = t + i * 256, d = idx >> 4, c4 = (idx & 15) * 4;
            cp16(aV + (d * 68 + c4) * 4, &vtb[(size_t)d * NQ + k0 + c4], true);
        }
        CP_COMMIT(); CP_WAIT(0);
        __syncthreads();

        float s[8][4];
        #pragma unroll
        for (int nt = 0; nt < 8; nt++)
            #pragma unroll
            for (int c = 0; c < 4; c++) s[nt][c] = 0.f;
        #pragma unroll
        for (int ks = 0; ks < 8; ks++) {
            const int kc = ks * 8 + qd;
            uint32_t af[4];
            af[0] = U32(Qs[r0l * 68 + kc    ]);
            af[1] = U32(Qs[r1l * 68 + kc    ]);
            af[2] = U32(Qs[r0l * 68 + kc + 4]);
            af[3] = U32(Qs[r1l * 68 + kc + 4]);
            #pragma unroll
            for (int nt = 0; nt < 8; nt++) {
                uint32_t bf[2];
                const int n = nt * 8 + gp;
                bf[0] = U32(Ks[n * 68 + kc    ]);
                bf[1] = U32(Ks[n * 68 + kc + 4]);
                mma_t(s[nt], af, bf);
            }
        }

        float tm0 = -1e30f, tm1 = -1e30f;
        #pragma unroll
        for (int nt = 0; nt < 8; nt++) {
            tm0 = fmaxf(tm0, fmaxf(s[nt][0], s[nt][1]));
            tm1 = fmaxf(tm1, fmaxf(s[nt][2], s[nt][3]));
        }
        tm0 = fmaxf(tm0, __shfl_xor_sync(~0u, tm0, 1));
        tm0 = fmaxf(tm0, __shfl_xor_sync(~0u, tm0, 2));
        tm1 = fmaxf(tm1, __shfl_xor_sync(~0u, tm1, 1));
        tm1 = fmaxf(tm1, __shfl_xor_sync(~0u, tm1, 2));
        const float mn0 = fmaxf(m0, tm0), mn1 = fmaxf(m1, tm1);
        const float al0 = __expf(m0 - mn0), al1 = __expf(m1 - mn1);
        float sum0 = 0.f, sum1 = 0.f;
        #pragma unroll
        for (int nt = 0; nt < 8; nt++) {
            s[nt][0] = __expf(s[nt][0] - mn0);
            s[nt][1] = __expf(s[nt][1] - mn0);
            s[nt][2] = __expf(s[nt][2] - mn1);
            s[nt][3] = __expf(s[nt][3] - mn1);
            sum0 += s[nt][0] + s[nt][1];
            sum1 += s[nt][2] + s[nt][3];
        }
        sum0 += __shfl_xor_sync(~0u, sum0, 1);
        sum0 += __shfl_xor_sync(~0u, sum0, 2);
        sum1 += __shfl_xor_sync(~0u, sum1, 1);
        sum1 += __shfl_xor_sync(~0u, sum1, 2);
        l0 = l0 * al0 + sum0;  m0 = mn0;
        l1 = l1 * al1 + sum1;  m1 = mn1;
        #pragma unroll
        for (int nt = 0; nt < 8; nt++) {
            o[nt][0] *= al0; o[nt][1] *= al0;
            o[nt][2] *= al1; o[nt][3] *= al1;
        }
        #pragma unroll
        for (int nt = 0; nt < 8; nt++) {
            *(float2*)&Ps[r0l * 68 + nt * 8 + 2 * qd] = make_float2(s[nt][0], s[nt][1]);
            *(float2*)&Ps[r1l * 68 + nt * 8 + 2 * qd] = make_float2(s[nt][2], s[nt][3]);
        }
        __syncthreads();

        #pragma unroll
        for (int ks = 0; ks < 8; ks++) {
            const int kc = ks * 8 + qd;
            uint32_t af[4];
            af[0] = U32(Ps[r0l * 68 + kc    ]);
            af[1] = U32(Ps[r1l * 68 + kc    ]);
            af[2] = U32(Ps[r0l * 68 + kc + 4]);
            af[3] = U32(Ps[r1l * 68 + kc + 4]);
            #pragma unroll
            for (int nt = 0; nt < 8; nt++) {
                uint32_t bf[2];
                const int n = nt * 8 + gp;
                bf[0] = U32(Vts[n * 68 + kc    ]);
                bf[1] = U32(Vts[n * 68 + kc + 4]);
                mma_t(o[nt], af, bf);
            }
        }
        __syncthreads();
    }

    const float i0 = 1.f / l0, i1 = 1.f / l1;
    const size_t gr0 = (size_t)(b * NQ + q0 + r0l);
    const size_t gr1 = gr0 + 8;
    #pragma unroll
    for (int nt = 0; nt < 8; nt++) {
        const int col = h * 64 + nt * 8 + 2 * qd;
        *(float2*)&O[gr0 * 512 + col] = make_float2(o[nt][0] * i0, o[nt][1] * i0);
        *(float2*)&O[gr1 * 512 + col] = make_float2(o[nt][2] * i1, o[nt][3] * i1);
    }
}

// ----- merged preamble: weight transposes (+rna) AND GroupNorm stats ---------
struct TrJobs {
    const float* src[12];
    float*       dst[12];
    int K[12], N[12], tiles[12];
    int tot;
    const float* x;
    float* st;
};
__global__ void pre_k(TrJobs J)
{
    const int tid = threadIdx.x;
    if ((int)blockIdx.x >= J.tot) {
        int bg = blockIdx.x - J.tot, b = bg >> 5, g = bg & 31;
        const float* base = J.x + ((size_t)b * CC + (size_t)g * 16) * NQ;
        float s = 0.f, s2 = 0.f;
        for (int i = tid; i < 16 * NQ; i += 256) {
            float v = base[i]; s += v; s2 += v * v;
        }
        for (int o = 16; o > 0; o >>= 1) {
            s  += __shfl_down_sync(~0u, s,  o);
            s2 += __shfl_down_sync(~0u, s2, o);
        }
        __shared__ float sh1[8], sh2[8];
        int w = tid >> 5, lane = tid & 31;
        if (lane == 0) { sh1[w] = s; sh2[w] = s2; }
        __syncthreads();
        if (tid == 0) {
            float S = 0.f, S2 = 0.f;
            for (int i = 0; i < 8; i++) { S += sh1[i]; S2 += sh2[i]; }
            float mean = S / (16.f * NQ);
            float var  = S2 / (16.f * NQ) - mean * mean;
            J.st[bg * 2]     = mean;
            J.st[bg * 2 + 1] = rsqrtf(var + 1e-6f);
        }
        return;
    }
    __shared__ float tl[32][33];
    int bid = blockIdx.x, j = 0;
    #pragma unroll
    for (int i = 0; i < 12; i++) {
        if (bid >= J.tiles[j]) { bid -= J.tiles[j]; j++; }
        else break;
    }
    const int kt = bid % (J.K[j] / 32), nt = bid / (J.K[j] / 32);
    const int k0 = kt * 32, n0 = nt * 32;
    const float* W = J.src[j];
    float* Wt = J.dst[j];
    const int K = J.K[j], N = J.N[j];
    int tx = tid & 31, ty = tid >> 5;
    #pragma unroll
    for (int i = 0; i < 4; i++) {
        float v = W[(size_t)(k0 + ty + i * 8) * N + n0 + tx];
        tl[ty + i * 8][tx] = __uint_as_float(f2tf(v));
    }
    __syncthreads();
    #pragma unroll
    for (int i = 0; i < 4; i++)
        Wt[(size_t)(n0 + ty + i * 8) * K + k0 + tx] = tl[tx][ty + i * 8];
}

// --------- GroupNorm apply + NCHW -> [b,n,c] transpose -----------------------
__global__ void gn_apply_t_k(const float* __restrict__ x, const float* __restrict__ st,
                             const float* __restrict__ gg, const float* __restrict__ gb,
                             float* __restrict__ o)
{
    __shared__ float tile[32][33];
    int n0 = blockIdx.x * 32, c0 = blockIdx.y * 32, b = blockIdx.z;
    int tx = threadIdx.x, ty = threadIdx.y;
    #pragma unroll
    for (int i = 0; i < 4; i++) {
        int c = c0 + ty + i * 8;
        int g = c >> 4;
        float mean = st[(b * 32 + g) * 2], rstd = st[(b * 32 + g) * 2 + 1];
        float v = x[((size_t)b * CC + c) * NQ + n0 + tx];
        tile[ty + i * 8][tx] = (v - mean) * rstd * gg[c] + gb[c];
    }
    __syncthreads();
    #pragma unroll
    for (int i = 0; i < 4; i++) {
        int n = n0 + ty + i * 8;
        o[((size_t)b * NQ + n) * INNER_ + c0 + tx] = tile[tx][ty + i * 8];
    }
}

// ---------------- warp-per-row LayerNorm (no block sync) ---------------------
// 256 threads = 8 warps = 8 rows/block; grid MTOK/8 = 576.
__global__ void __launch_bounds__(256)
ln_k(const float* __restrict__ X, const float* __restrict__ g,
     const float* __restrict__ bb, float* __restrict__ O)
{
    const int w = threadIdx.x >> 5, lane = threadIdx.x & 31;
    const int row = blockIdx.x * 8 + w;
    const float4* xr = (const float4*)(X + (size_t)row * INNER_);

    float4 v[4];
    float s = 0.f, s2 = 0.f;
    #pragma unroll
    for (int i = 0; i < 4; i++) {
        v[i] = xr[lane + i * 32];
        s  += v[i].x + v[i].y + v[i].z + v[i].w;
        s2 += v[i].x*v[i].x + v[i].y*v[i].y + v[i].z*v[i].z + v[i].w*v[i].w;
    }
    #pragma unroll
    for (int o = 16; o > 0; o >>= 1) {
        s  += __shfl_xor_sync(~0u, s,  o);
        s2 += __shfl_xor_sync(~0u, s2, o);
    }
    const float mean = s * (1.f / 512.f);
    const float rstd = rsqrtf(s2 * (1.f / 512.f) - mean * mean + 1e-5f);

    float4* orow = (float4*)(O + (size_t)row * INNER_);
    #pragma unroll
    for (int i = 0; i < 4; i++) {
        const int c4 = lane + i * 32;
        const float4 g4 = ((const float4*)g)[c4];
        const float4 b4 = ((const float4*)bb)[c4];
        float4 o;
        o.x = (v[i].x - mean) * rstd * g4.x + b4.x;
        o.y = (v[i].y - mean) * rstd * g4.y + b4.y;
        o.z = (v[i].z - mean) * rstd * g4.z + b4.z;
        o.w = (v[i].w - mean) * rstd * g4.w + b4.w;
        orow[c4] = o;
    }
}

// ---------------- fp32 flash attention (cross-attn, 77 keys) -----------------
__global__ void __launch_bounds__(256) attn_k(
    const float* __restrict__ Q, const float* __restrict__ Kb,
    const float* __restrict__ Vb, float* __restrict__ O,
    int n_q, int n_kv, int ldq, int ldkv)
{
    __shared__ float Qs[64][68];
    __shared__ float Ks[32][68];
    __shared__ float Vs[32][68];
    __shared__ float Sx[64][33];
    __shared__ float mrow[64], lrow[64], arow[64];

    const int t  = threadIdx.x;
    const int h  = blockIdx.y, b = blockIdx.z;
    const int q0 = blockIdx.x * 64;
    const float* qb = Q  + ((size_t)b * n_q ) * ldq  + h * DHEAD_;
    const float* kb = Kb + ((size_t)b * n_kv) * ldkv + h * DHEAD_;
    const float* vb = Vb + ((size_t)b * n_kv) * ldkv + h * DHEAD_;

    #pragma unroll
    for (int j = 0; j < 4; j++) {
        int idx4 = t + j * 256;
        int r = idx4 >> 4, c4 = (idx4 & 15) * 4;
        float4 v = *(const float4*)&qb[(size_t)(q0 + r) * ldq + c4];
        Qs[r][c4+0]=v.x; Qs[r][c4+1]=v.y; Qs[r][c4+2]=v.z; Qs[r][c4+3]=v.w;
    }
    if (t < 64) { mrow[t] = -1e30f; lrow[t] = 0.f; }

    float acc[16];
    #pragma unroll
    for (int i = 0; i < 16; i++) acc[i] = 0.f;
    const int r  = t >> 2;
    const int jq = t & 3;

    const int ntiles = (n_kv + 31) / 32;
    for (int kt = 0; kt < ntiles; kt++) {
        const int j0 = kt * 32;
        #pragma unroll
        for (int j = 0; j < 2; j++) {
            int idx4 = t + j * 256;
            int jr = idx4 >> 4, c4 = (idx4 & 15) * 4;
            int krow = j0 + jr;
            float4 kv = make_float4(0.f,0.f,0.f,0.f);
            float4 vv = make_float4(0.f,0.f,0.f,0.f);
            if (krow < n_kv) {
                kv = *(const float4*)&kb[(size_t)krow * ldkv + c4];
                vv = *(const float4*)&vb[(size_t)krow * ldkv + c4];
            }
            Ks[jr][c4+0]=kv.x; Ks[jr][c4+1]=kv.y; Ks[jr][c4+2]=kv.z; Ks[jr][c4+3]=kv.w;
            Vs[jr][c4+0]=vv.x; Vs[jr][c4+1]=vv.y; Vs[jr][c4+2]=vv.z; Vs[jr][c4+3]=vv.w;
        }
        __syncthreads();
        #pragma unroll
        for (int jj = 0; jj < 8; jj++) {
            int j = jq + 4*jj;
            float s = 0.f;
            #pragma unroll
            for (int d = 0; d < 64; d++) s += Qs[r][d] * Ks[j][d];
            Sx[r][j] = (j0 + j < n_kv) ? s * 0.125f : -1e30f;
        }
        __syncthreads();
        if (t < 64) {
            float m_old = mrow[t];
            float mnew = m_old;
            #pragma unroll 8
            for (int j = 0; j < 32; j++) mnew = fmaxf(mnew, Sx[t][j]);
            float alpha = __expf(m_old - mnew);
            float psum = 0.f;
            #pragma unroll 8
            for (int j = 0; j < 32; j++) {
                float p = __expf(Sx[t][j] - mnew);
                Sx[t][j] = p; psum += p;
            }
            mrow[t] = mnew;
            lrow[t] = lrow[t]*alpha + psum;
            arow[t] = alpha;
        }
        __syncthreads();
        float alpha = arow[r];
        #pragma unroll
        for (int i = 0; i < 16; i++) acc[i] *= alpha;
        #pragma unroll 4
        for (int j = 0; j < 32; j++) {
            float p = Sx[r][j];
            #pragma unroll
            for (int i = 0; i < 16; i++)
                acc[i] += p * Vs[j][jq + 4*i];
        }
        __syncthreads();
    }
    const float inv = 1.f / lrow[r];
    float* orow = O + ((size_t)(b * n_q + q0 + r)) * INNER_ + h * DHEAD_ + jq;
    #pragma unroll
    for (int i = 0; i < 16; i++) orow[4*i] = acc[i] * inv;
}

// ---------------- launch -------------------------------------------------------
extern "C" void kernel_launch(void* const* d_in, const int* in_sizes, int n_in,
                              void* d_out, int out_size)
{
    const float* x    = (const float*)d_in[0];
    const float* ctx  = (const float*)d_in[1];
    const float* gng  = (const float*)d_in[2];
    const float* gnb  = (const float*)d_in[3];
    const float* w_in = (const float*)d_in[4];
    const float* b_in = (const float*)d_in[5];
    const float* ln1g = (const float*)d_in[6];
    const float* ln1b = (const float*)d_in[7];
    const float* wq1  = (const float*)d_in[8];
    const float* wk1  = (const float*)d_in[9];
    const float* wv1  = (const float*)d_in[10];
    const float* wo1  = (const float*)d_in[11];
    const float* bo1  = (const float*)d_in[12];
    const float* ln2g = (const float*)d_in[13];
    const float* ln2b = (const float*)d_in[14];
    const float* wq2  = (const float*)d_in[15];
    const float* wk2  = (const float*)d_in[16];
    const float* wv2  = (const float*)d_in[17];
    const float* wo2  = (const float*)d_in[18];
    const float* bo2  = (const float*)d_in[19];
    const float* ln3g = (const float*)d_in[20];
    const float* ln3b = (const float*)d_in[21];
    const float* wff1 = (const float*)d_in[22];
    const float* bff1 = (const float*)d_in[23];
    const float* wff2 = (const float*)d_in[24];
    const float* bff2 = (const float*)d_in[25];
    const float* wout = (const float*)d_in[26];
    const float* bout = (const float*)d_in[27];
    float* out = (float*)d_out;

    float *hn,*t_,*q,*at,*qkv,*kvc,*gl,*st,*vt;
    float *wt_in,*wqkv,*wto1,*wtq2,*wtkv2,*wto2,*wtff1,*wtff2,*wtout;
    cudaGetSymbolAddress((void**)&hn,  g_hn);
    cudaGetSymbolAddress((void**)&t_,  g_t);
    cudaGetSymbolAddress((void**)&q,   g_q);
    cudaGetSymbolAddress((void**)&at,  g_at);
    cudaGetSymbolAddress((void**)&qkv, g_qkv);
    cudaGetSymbolAddress((void**)&kvc, g_kvc);
    cudaGetSymbolAddress((void**)&gl,  g_gl);
    cudaGetSymbolAddress((void**)&st,  g_stat);
    cudaGetSymbolAddress((void**)&vt,  g_vt);
    cudaGetSymbolAddress((void**)&wt_in, g_wt_in);
    cudaGetSymbolAddress((void**)&wqkv,  g_wqkv);
    cudaGetSymbolAddress((void**)&wto1,  g_wto1);
    cudaGetSymbolAddress((void**)&wtq2,  g_wtq2);
    cudaGetSymbolAddress((void**)&wtkv2, g_wtkv2);
    cudaGetSymbolAddress((void**)&wto2,  g_wto2);
    cudaGetSymbolAddress((void**)&wtff1, g_wtff1);
    cudaGetSymbolAddress((void**)&wtff2, g_wtff2);
    cudaGetSymbolAddress((void**)&wtout, g_wtout);

    const int SM2  = 2 * (128 * 36 + 128 * 36) * 4;   // 73728
    const int SMFG = 2 * (64 * 36 + 256 * 36) * 4;    // 92160
    const int SMFA = 384 * 68 * 4;                    // 104448
    cudaFuncSetAttribute(tgemm_k,    cudaFuncAttributeMaxDynamicSharedMemorySize, SM2);
    cudaFuncSetAttribute(tgemmQKV_k, cudaFuncAttributeMaxDynamicSharedMemorySize, SM2);
    cudaFuncSetAttribute(xqkv_k,     cudaFuncAttributeMaxDynamicSharedMemorySize, SM2);
    cudaFuncSetAttribute(tgemmT_k,   cudaFuncAttributeMaxDynamicSharedMemorySize, SM2);
    cudaFuncSetAttribute(ffgeglu_k,  cudaFuncAttributeMaxDynamicSharedMemorySize, SMFG);
    cudaFuncSetAttribute(fattn_k,    cudaFuncAttributeMaxDynamicSharedMemorySize, SMFA);

    const dim3 tb(32, 8);

    // merged preamble: weight transposes + GroupNorm stats
    TrJobs J;
    J.src[0]=w_in;  J.dst[0]=wt_in;            J.K[0]=512;  J.N[0]=512;
    J.src[1]=wq1;   J.dst[1]=wqkv;             J.K[1]=512;  J.N[1]=512;
    J.src[2]=wk1;   J.dst[2]=wqkv+512*512;     J.K[2]=512;  J.N[2]=512;
    J.src[3]=wv1;   J.dst[3]=wqkv+1024*512;    J.K[3]=512;  J.N[3]=512;
    J.src[4]=wo1;   J.dst[4]=wto1;             J.K[4]=512;  J.N[4]=512;
    J.src[5]=wq2;   J.dst[5]=wtq2;             J.K[5]=512;  J.N[5]=512;
    J.src[6]=wk2;   J.dst[6]=wtkv2;            J.K[6]=768;  J.N[6]=512;
    J.src[7]=wv2;   J.dst[7]=wtkv2+512*768;    J.K[7]=768;  J.N[7]=512;
    J.src[8]=wo2;   J.dst[8]=wto2;             J.K[8]=512;  J.N[8]=512;
    J.src[9]=wff1;  J.dst[9]=wtff1;            J.K[9]=512;  J.N[9]=4096;
    J.src[10]=wff2; J.dst[10]=wtff2;           J.K[10]=2048;J.N[10]=512;
    J.src[11]=wout; J.dst[11]=wtout;           J.K[11]=512; J.N[11]=512;
    int tot = 0;
    for (int i = 0; i < 12; i++) { J.tiles[i] = (J.K[i]/32)*(J.N[i]/32); tot += J.tiles[i]; }
    J.tot = tot;
    J.x = x;
    J.st = st;
    pre_k<<<tot + BB*32, 256>>>(J);

    // GroupNorm apply + proj_in
    gn_apply_t_k<<<dim3(72, 16, 2), tb>>>(x, st, gng, gnb, hn);
    tgemm_k<<<dim3(4, 36), 256, SM2>>>(hn, wt_in, b_in, nullptr, t_,
        MTOK, 512, 512, 512, 512);

    // self-attention (qkv GEMM writes q/k to qkv, v transposed into vt)
    ln_k<<<MTOK/8, 256>>>(t_, ln1g, ln1b, hn);
    tgemmQKV_k<<<dim3(12, 36), 256, SM2>>>(hn, wqkv, qkv, vt);
    fattn_k<<<dim3(18, 8, 2), 256, SMFA>>>(qkv, vt, at);
    tgemm_k<<<dim3(4, 36), 256, SM2>>>(at, wto1, bo1, t_, t_,
        MTOK, 512, 512, 512, 512);

    // cross-attention (q GEMM + ctx kv GEMM merged into one launch)
    ln_k<<<MTOK/8, 256>>>(t_, ln2g, ln2b, hn);
    xqkv_k<<<dim3(4, 40), 256, SM2>>>(hn, wtq2, q, ctx, wtkv2, kvc);
    attn_k<<<dim3(36, 8, 2), 256>>>(q, kvc, kvc + 512, at, NQ, CTX, 512, 1024);
    tgemm_k<<<dim3(4, 36), 256, SM2>>>(at, wto2, bo2, t_, t_,
        MTOK, 512, 512, 512, 512);

    // feed-forward: fused ff1+GEGLU, then ff2
    ln_k<<<MTOK/8, 256>>>(t_, ln3g, ln3b, hn);
    ffgeglu_k<<<dim3(16, 72), 256, SMFG>>>(hn, wtff1, bff1, gl);
    tgemm_k<<<dim3(4, 36), 256, SM2>>>(gl, wtff2, bff2, t_, t_,
        MTOK, 2048, 2048, 2048, 512);

    // proj_out + transpose + image residual (fused)
    tgemmT_k<<<dim3(4, 36), 256, SM2>>>(t_, wtout, bout, x, out);
}

// round 16
// speedup vs baseline: 1.1250x; 1.0036x over previous
#include <cuda_runtime.h>
#include <cstdint>
#include <math.h>

// ---------------- problem constants ----------------
#define BB     2
#define CC     512
#define NQ     2304
#define INNER_ 512
#define HEADS_ 8
#define DHEAD_ 64
#define CTX    77
#define CTXD   768
#define FFI    2048
#define MTOK   4608

// ---------------- scratch (device globals) ---------------------------------
__device__ float g_hn  [MTOK*INNER_];
__device__ float g_t   [MTOK*INNER_];
__device__ float g_q   [MTOK*INNER_];
__device__ float g_at  [MTOK*INNER_];
__device__ float g_qkv [MTOK*1536];
__device__ float g_kvc [160*1024];
__device__ float g_gl  [MTOK*FFI];
__device__ float g_stat[BB*32*2];
__device__ float g_vt  [16*DHEAD_*NQ];
// transposed weights [N,K]
__device__ float g_wt_in [512*512];
__device__ float g_wqkv  [1536*512];
__device__ float g_wto1  [512*512];
__device__ float g_wtq2  [512*512];
__device__ float g_wtkv2 [1024*768];
__device__ float g_wto2  [512*512];
__device__ float g_wtff1 [4096*512];
__device__ float g_wtff2 [512*2048];
__device__ float g_wtout [512*512];

// ---------------- PTX helpers ------------------------------------------------
__device__ __forceinline__ uint32_t smem_u32(const void* p) {
    uint32_t a;
    asm("{ .reg .u64 t; cvta.to.shared.u64 t, %1; cvt.u32.u64 %0, t; }"
        : "=r"(a) : "l"(p));
    return a;
}
__device__ __forceinline__ uint32_t f2tf(float x) {
    uint32_t r;
    asm("cvt.rna.tf32.f32 %0, %1;" : "=r"(r) : "f"(x));
    return r;
}
__device__ __forceinline__ void mma_t(float* c, const uint32_t* a, const uint32_t* b) {
    asm volatile("mma.sync.aligned.m16n8k8.row.col.f32.tf32.tf32.f32 "
        "{%0,%1,%2,%3}, {%4,%5,%6,%7}, {%8,%9}, {%0,%1,%2,%3};"
        : "+f"(c[0]), "+f"(c[1]), "+f"(c[2]), "+f"(c[3])
        : "r"(a[0]), "r"(a[1]), "r"(a[2]), "r"(a[3]), "r"(b[0]), "r"(b[1]));
}
__device__ __forceinline__ void cp16(uint32_t dst, const float* src, bool valid) {
    int sz = valid ? 16 : 0;
    asm volatile("cp.async.cg.shared.global [%0], [%1], 16, %2;"
                 :: "r"(dst), "l"(src), "r"(sz) : "memory");
}
#define CP_COMMIT() asm volatile("cp.async.commit_group;" ::: "memory")
#define CP_WAIT(n)  asm volatile("cp.async.wait_group %0;" :: "n"(n) : "memory")
#define U32(x) (*(const uint32_t*)&(x))

// ---------------- tf32 mma.sync GEMM (R4-proven 2-stage, 256 thr) ------------
__global__ void __launch_bounds__(256)
tgemm_k(const float* __restrict__ A, const float* __restrict__ Bt,
        const float* __restrict__ bias, const float* __restrict__ res,
        float* __restrict__ C,
        int M, int K, int lda, int ldb, int ldc)
{
    extern __shared__ float smem[];
    const int t = threadIdx.x, wid = t >> 5, lane = t & 31;
    const int bn = blockIdx.x * 128, bm = blockIdx.y * 128;

    constexpr int AFL = 128 * 36;
    constexpr int STR = 2 * AFL;

    const int mw = wid & 3, nw = wid >> 2;
    const int gp = lane >> 2, qd = lane & 3;

    float acc[2][8][4];
    #pragma unroll
    for (int i = 0; i < 2; i++)
        #pragma unroll
        for (int j = 0; j < 8; j++)
            #pragma unroll
            for (int c = 0; c < 4; c++) acc[i][j][c] = 0.f;

    const uint32_t sbase = smem_u32(smem);

    auto load_tile = [&](int kt, int buf) {
        const int k0 = kt * 32;
        const uint32_t offA = sbase + buf * STR * 4;
        const uint32_t offB = offA + AFL * 4;
        #pragma unroll
        for (int i = 0; i < 4; i++) {
            int idx = t + i * 256, row = idx >> 3, q = idx & 7;
            bool ok = (bm + row) < M;
            cp16(offA + (row * 36 + q * 4) * 4,
                 &A[(size_t)(ok ? bm + row : 0) * lda + k0 + q * 4], ok);
        }
        #pragma unroll
        for (int i = 0; i < 4; i++) {
            int idx = t + i * 256, row = idx >> 3, q = idx & 7;
            cp16(offB + (row * 36 + q * 4) * 4,
                 &Bt[(size_t)(bn + row) * ldb + k0 + q * 4], true);
        }
        CP_COMMIT();
    };

    const int KT = K / 32;
    load_tile(0, 0);

    for (int kt = 0; kt < KT; kt++) {
        const int cur = kt & 1;
        if (kt + 1 < KT) { load_tile(kt + 1, cur ^ 1); CP_WAIT(1); }
        else             { CP_WAIT(0); }
        __syncthreads();
        const float* As = smem + cur * STR;
        const float* Bs = As + AFL;
        #pragma unroll
        for (int ks = 0; ks < 4; ks++) {
            const int kc = ks * 8 + qd;
            uint32_t fA[2][4];
            #pragma unroll
            for (int mt = 0; mt < 2; mt++) {
                const int r = mw * 32 + mt * 16 + gp;
                fA[mt][0] = U32(As[(r    ) * 36 + kc    ]);
                fA[mt][1] = U32(As[(r + 8) * 36 + kc    ]);
                fA[mt][2] = U32(As[(r    ) * 36 + kc + 4]);
                fA[mt][3] = U32(As[(r + 8) * 36 + kc + 4]);
            }
            uint32_t fB[8][2];
            #pragma unroll
            for (int nt = 0; nt < 8; nt++) {
                const int n = nw * 64 + nt * 8 + gp;
                fB[nt][0] = U32(Bs[n * 36 + kc    ]);
                fB[nt][1] = U32(Bs[n * 36 + kc + 4]);
            }
            #pragma unroll
            for (int mt = 0; mt < 2; mt++)
                #pragma unroll
                for (int nt = 0; nt < 8; nt++)
                    mma_t(acc[mt][nt], fA[mt], fB[nt]);
        }
        __syncthreads();
    }

    #pragma unroll
    for (int mt = 0; mt < 2; mt++) {
        const int r0 = bm + mw * 32 + mt * 16 + gp;
        #pragma unroll
        for (int nt = 0; nt < 8; nt++) {
            const int col = bn + nw * 64 + nt * 8 + qd * 2;
            float2 lo = make_float2(acc[mt][nt][0], acc[mt][nt][1]);
            float2 hi = make_float2(acc[mt][nt][2], acc[mt][nt][3]);
            if (bias) {
                const float2 b2 = *(const float2*)&bias[col];
                lo.x += b2.x; lo.y += b2.y; hi.x += b2.x; hi.y += b2.y;
            }
            if (r0 < M) {
                if (res) {
                    const float2 r2 = *(const float2*)&res[(size_t)r0 * ldc + col];
                    lo.x += r2.x; lo.y += r2.y;
                }
                *(float2*)&C[(size_t)r0 * ldc + col] = lo;
            }
            if (r0 + 8 < M) {
                if (res) {
                    const float2 r2 = *(const float2*)&res[(size_t)(r0 + 8) * ldc + col];
                    hi.x += r2.x; hi.y += r2.y;
                }
                *(float2*)&C[(size_t)(r0 + 8) * ldc + col] = hi;
            }
        }
    }
}

// ---------------- qkv GEMM: q/k cols -> C, v cols -> transposed Vt -----------
__global__ void __launch_bounds__(256)
tgemmQKV_k(const float* __restrict__ A, const float* __restrict__ Bt,
           float* __restrict__ C, float* __restrict__ Vt)
{
    extern __shared__ float smem[];
    const int t = threadIdx.x, wid = t >> 5, lane = t & 31;
    const int bn = blockIdx.x * 128, bm = blockIdx.y * 128;

    constexpr int AFL = 128 * 36;
    constexpr int STR = 2 * AFL;

    const int mw = wid & 3, nw = wid >> 2;
    const int gp = lane >> 2, qd = lane & 3;

    float acc[2][8][4];
    #pragma unroll
    for (int i = 0; i < 2; i++)
        #pragma unroll
        for (int j = 0; j < 8; j++)
            #pragma unroll
            for (int c = 0; c < 4; c++) acc[i][j][c] = 0.f;

    const uint32_t sbase = smem_u32(smem);

    auto load_tile = [&](int kt, int buf) {
        const int k0 = kt * 32;
        const uint32_t offA = sbase + buf * STR * 4;
        const uint32_t offB = offA + AFL * 4;
        #pragma unroll
        for (int i = 0; i < 4; i++) {
            int idx = t + i * 256, row = idx >> 3, q = idx & 7;
            cp16(offA + (row * 36 + q * 4) * 4,
                 &A[(size_t)(bm + row) * 512 + k0 + q * 4], true);
        }
        #pragma unroll
        for (int i = 0; i < 4; i++) {
            int idx = t + i * 256, row = idx >> 3, q = idx & 7;
            cp16(offB + (row * 36 + q * 4) * 4,
                 &Bt[(size_t)(bn + row) * 512 + k0 + q * 4], true);
        }
        CP_COMMIT();
    };

    load_tile(0, 0);
    for (int kt = 0; kt < 16; kt++) {
        const int cur = kt & 1;
        if (kt + 1 < 16) { load_tile(kt + 1, cur ^ 1); CP_WAIT(1); }
        else             { CP_WAIT(0); }
        __syncthreads();
        const float* As = smem + cur * STR;
        const float* Bs = As + AFL;
        #pragma unroll
        for (int ks = 0; ks < 4; ks++) {
            const int kc = ks * 8 + qd;
            uint32_t fA[2][4];
            #pragma unroll
            for (int mt = 0; mt < 2; mt++) {
                const int r = mw * 32 + mt * 16 + gp;
                fA[mt][0] = U32(As[(r    ) * 36 + kc    ]);
                fA[mt][1] = U32(As[(r + 8) * 36 + kc    ]);
                fA[mt][2] = U32(As[(r    ) * 36 + kc + 4]);
                fA[mt][3] = U32(As[(r + 8) * 36 + kc + 4]);
            }
            uint32_t fB[8][2];
            #pragma unroll
            for (int nt = 0; nt < 8; nt++) {
                const int n = nw * 64 + nt * 8 + gp;
                fB[nt][0] = U32(Bs[n * 36 + kc    ]);
                fB[nt][1] = U32(Bs[n * 36 + kc + 4]);
            }
            #pragma unroll
            for (int mt = 0; mt < 2; mt++)
                #pragma unroll
                for (int nt = 0; nt < 8; nt++)
                    mma_t(acc[mt][nt], fA[mt], fB[nt]);
        }
        __syncthreads();
    }

    if (bn < 1024) {
        #pragma unroll
        for (int mt = 0; mt < 2; mt++) {
            const int r0 = bm + mw * 32 + mt * 16 + gp;
            #pragma unroll
            for (int nt = 0; nt < 8; nt++) {
                const int col = bn + nw * 64 + nt * 8 + qd * 2;
                *(float2*)&C[(size_t)r0 * 1536 + col] =
                    make_float2(acc[mt][nt][0], acc[mt][nt][1]);
                *(float2*)&C[(size_t)(r0 + 8) * 1536 + col] =
                    make_float2(acc[mt][nt][2], acc[mt][nt][3]);
            }
        }
    } else {
        float* tile = smem;
        __syncthreads();
        #pragma unroll
        for (int mt = 0; mt < 2; mt++) {
            const int nl0 = mw * 32 + mt * 16 + gp;
            #pragma unroll
            for (int nt = 0; nt < 8; nt++) {
                const int cl = nw * 64 + nt * 8 + qd * 2;
                tile[(cl    ) * 132 + nl0    ] = acc[mt][nt][0];
                tile[(cl + 1) * 132 + nl0    ] = acc[mt][nt][1];
                tile[(cl    ) * 132 + nl0 + 8] = acc[mt][nt][2];
                tile[(cl + 1) * 132 + nl0 + 8] = acc[mt][nt][3];
            }
        }
        __syncthreads();

        const int b = bm / NQ;
        const int n0 = bm - b * NQ;
        const int bnl = bn - 1024;
        #pragma unroll
        for (int i = 0; i < 16; i++) {
            int idx4 = t + i * 256;
            int cl = idx4 >> 5, n4 = (idx4 & 31) * 4;
            const int gcol = bnl + cl;
            const int h = gcol >> 6, d = gcol & 63;
            float* dst = &Vt[((size_t)(b * 8 + h) * 64 + d) * NQ + n0 + n4];
            float4 o;
            o.x = tile[cl * 132 + n4 + 0];
            o.y = tile[cl * 132 + n4 + 1];
            o.z = tile[cl * 132 + n4 + 2];
            o.w = tile[cl * 132 + n4 + 3];
            *(float4*)dst = o;
        }
    }
}

// ------ merged cross-attn projections: q GEMM (from hn) + ctx kv GEMM --------
__global__ void __launch_bounds__(256)
xqkv_k(const float* __restrict__ A, const float* __restrict__ Bt,
       float* __restrict__ Q,
       const float* __restrict__ ctx, const float* __restrict__ Btkv,
       float* __restrict__ KVc)
{
    extern __shared__ float smem[];
    const int t = threadIdx.x, wid = t >> 5, lane = t & 31;

    constexpr int AFL = 128 * 36;
    constexpr int STR = 2 * AFL;

    const int mw = wid & 3, nw = wid >> 2;
    const int gp = lane >> 2, qd = lane & 3;

    float acc[2][8][4];
    #pragma unroll
    for (int i = 0; i < 2; i++)
        #pragma unroll
        for (int j = 0; j < 8; j++)
            #pragma unroll
            for (int c = 0; c < 4; c++) acc[i][j][c] = 0.f;

    const uint32_t sbase = smem_u32(smem);

    const bool qpath = blockIdx.y < 36;
    const float* Aa  = qpath ? A   : ctx;
    const float* Bb  = qpath ? Bt  : Btkv;
    int bn, bm, lda, KT, M;
    if (qpath) {
        bn = blockIdx.x * 128; bm = blockIdx.y * 128;
        lda = 512; KT = 16; M = MTOK;
    } else {
        const int idx16 = (blockIdx.y - 36) * 4 + blockIdx.x;   // 0..15
        bn = (idx16 & 7) * 128; bm = (idx16 >> 3) * 128;
        lda = 768; KT = 24; M = BB * CTX;
    }

    auto load_tile = [&](int kt, int buf) {
        const int k0 = kt * 32;
        const uint32_t offA = sbase + buf * STR * 4;
        const uint32_t offB = offA + AFL * 4;
        #pragma unroll
        for (int i = 0; i < 4; i++) {
            int idx = t + i * 256, row = idx >> 3, q = idx & 7;
            bool ok = (bm + row) < M;
            cp16(offA + (row * 36 + q * 4) * 4,
                 &Aa[(size_t)(ok ? bm + row : 0) * lda + k0 + q * 4], ok);
        }
        #pragma unroll
        for (int i = 0; i < 4; i++) {
            int idx = t + i * 256, row = idx >> 3, q = idx & 7;
            cp16(offB + (row * 36 + q * 4) * 4,
                 &Bb[(size_t)(bn + row) * lda + k0 + q * 4], true);
        }
        CP_COMMIT();
    };

    load_tile(0, 0);
    for (int kt = 0; kt < KT; kt++) {
        const int cur = kt & 1;
        if (kt + 1 < KT) { load_tile(kt + 1, cur ^ 1); CP_WAIT(1); }
        else             { CP_WAIT(0); }
        __syncthreads();
        const float* As = smem + cur * STR;
        const float* Bs = As + AFL;
        #pragma unroll
        for (int ks = 0; ks < 4; ks++) {
            const int kc = ks * 8 + qd;
            uint32_t fA[2][4];
            #pragma unroll
            for (int mt = 0; mt < 2; mt++) {
                const int r = mw * 32 + mt * 16 + gp;
                fA[mt][0] = U32(As[(r    ) * 36 + kc    ]);
                fA[mt][1] = U32(As[(r + 8) * 36 + kc    ]);
                fA[mt][2] = U32(As[(r    ) * 36 + kc + 4]);
                fA[mt][3] = U32(As[(r + 8) * 36 + kc + 4]);
            }
            uint32_t fB[8][2];
            #pragma unroll
            for (int nt = 0; nt < 8; nt++) {
                const int n = nw * 64 + nt * 8 + gp;
                fB[nt][0] = U32(Bs[n * 36 + kc    ]);
                fB[nt][1] = U32(Bs[n * 36 + kc + 4]);
            }
            #pragma unroll
            for (int mt = 0; mt < 2; mt++)
                #pragma unroll
                for (int nt = 0; nt < 8; nt++)
                    mma_t(acc[mt][nt], fA[mt], fB[nt]);
        }
        __syncthreads();
    }

    float* Cc = qpath ? Q : KVc;
    const int ldc = qpath ? 512 : 1024;
    #pragma unroll
    for (int mt = 0; mt < 2; mt++) {
        const int r0 = bm + mw * 32 + mt * 16 + gp;
        #pragma unroll
        for (int nt = 0; nt < 8; nt++) {
            const int col = bn + nw * 64 + nt * 8 + qd * 2;
            if (r0 < M)
                *(float2*)&Cc[(size_t)r0 * ldc + col] =
                    make_float2(acc[mt][nt][0], acc[mt][nt][1]);
            if (r0 + 8 < M)
                *(float2*)&Cc[(size_t)(r0 + 8) * ldc + col] =
                    make_float2(acc[mt][nt][2], acc[mt][nt][3]);
        }
    }
}

// ---------------- proj_out GEMM + transpose + image residual -----------------
__global__ void __launch_bounds__(256)
tgemmT_k(const float* __restrict__ A, const float* __restrict__ Bt,
         const float* __restrict__ bias, const float* __restrict__ x,
         float* __restrict__ out)
{
    extern __shared__ float smem[];
    const int t = threadIdx.x, wid = t >> 5, lane = t & 31;
    const int bn = blockIdx.x * 128, bm = blockIdx.y * 128;

    constexpr int AFL = 128 * 36;
    constexpr int STR = 2 * AFL;

    const int mw = wid & 3, nw = wid >> 2;
    const int gp = lane >> 2, qd = lane & 3;

    float acc[2][8][4];
    #pragma unroll
    for (int i = 0; i < 2; i++)
        #pragma unroll
        for (int j = 0; j < 8; j++)
            #pragma unroll
            for (int c = 0; c < 4; c++) acc[i][j][c] = 0.f;

    const uint32_t sbase = smem_u32(smem);

    auto load_tile = [&](int kt, int buf) {
        const int k0 = kt * 32;
        const uint32_t offA = sbase + buf * STR * 4;
        const uint32_t offB = offA + AFL * 4;
        #pragma unroll
        for (int i = 0; i < 4; i++) {
            int idx = t + i * 256, row = idx >> 3, q = idx & 7;
            cp16(offA + (row * 36 + q * 4) * 4,
                 &A[(size_t)(bm + row) * 512 + k0 + q * 4], true);
        }
        #pragma unroll
        for (int i = 0; i < 4; i++) {
            int idx = t + i * 256, row = idx >> 3, q = idx & 7;
            cp16(offB + (row * 36 + q * 4) * 4,
                 &Bt[(size_t)(bn + row) * 512 + k0 + q * 4], true);
        }
        CP_COMMIT();
    };

    load_tile(0, 0);
    for (int kt = 0; kt < 16; kt++) {
        const int cur = kt & 1;
        if (kt + 1 < 16) { load_tile(kt + 1, cur ^ 1); CP_WAIT(1); }
        else             { CP_WAIT(0); }
        __syncthreads();
        const float* As = smem + cur * STR;
        const float* Bs = As + AFL;
        #pragma unroll
        for (int ks = 0; ks < 4; ks++) {
            const int kc = ks * 8 + qd;
            uint32_t fA[2][4];
            #pragma unroll
            for (int mt = 0; mt < 2; mt++) {
                const int r = mw * 32 + mt * 16 + gp;
                fA[mt][0] = U32(As[(r    ) * 36 + kc    ]);
                fA[mt][1] = U32(As[(r + 8) * 36 + kc    ]);
                fA[mt][2] = U32(As[(r    ) * 36 + kc + 4]);
                fA[mt][3] = U32(As[(r + 8) * 36 + kc + 4]);
            }
            uint32_t fB[8][2];
            #pragma unroll
            for (int nt = 0; nt < 8; nt++) {
                const int n = nw * 64 + nt * 8 + gp;
                fB[nt][0] = U32(Bs[n * 36 + kc    ]);
                fB[nt][1] = U32(Bs[n * 36 + kc + 4]);
            }
            #pragma unroll
            for (int mt = 0; mt < 2; mt++)
                #pragma unroll
                for (int nt = 0; nt < 8; nt++)
                    mma_t(acc[mt][nt], fA[mt], fB[nt]);
        }
        __syncthreads();
    }

    float* tile = smem;
    __syncthreads();
    #pragma unroll
    for (int mt = 0; mt < 2; mt++) {
        const int nl0 = mw * 32 + mt * 16 + gp;
        #pragma unroll
        for (int nt = 0; nt < 8; nt++) {
            const int cl = nw * 64 + nt * 8 + qd * 2;
            const float2 b2 = *(const float2*)&bias[bn + cl];
            tile[(cl    ) * 132 + nl0    ] = acc[mt][nt][0] + b2.x;
            tile[(cl + 1) * 132 + nl0    ] = acc[mt][nt][1] + b2.y;
            tile[(cl    ) * 132 + nl0 + 8] = acc[mt][nt][2] + b2.x;
            tile[(cl + 1) * 132 + nl0 + 8] = acc[mt][nt][3] + b2.y;
        }
    }
    __syncthreads();

    const int b = bm / NQ;
    const int n0 = bm - b * NQ;
    #pragma unroll
    for (int i = 0; i < 16; i++) {
        int idx4 = t + i * 256;
        int cl = idx4 >> 5, n4 = (idx4 & 31) * 4;
        const size_t gidx = ((size_t)b * CC + bn + cl) * NQ + n0 + n4;
        const float4 xr = *(const float4*)&x[gidx];
        float4 o;
        o.x = tile[cl * 132 + n4 + 0] + xr.x;
        o.y = tile[cl * 132 + n4 + 1] + xr.y;
        o.z = tile[cl * 132 + n4 + 2] + xr.z;
        o.w = tile[cl * 132 + n4 + 3] + xr.w;
        *(float4*)&out[gidx] = o;
    }
}

// ---------------- fused FF1 + GEGLU (R9-proven) -------------------------------
__global__ void __launch_bounds__(256)
ffgeglu_k(const float* __restrict__ A, const float* __restrict__ Bt,
          const float* __restrict__ bias, float* __restrict__ GL)
{
    extern __shared__ float smem[];
    const int t = threadIdx.x, wid = t >> 5, lane = t & 31;
    const int bn = blockIdx.x * 128;
    const int bm = blockIdx.y * 64;

    constexpr int AFL = 64 * 36;
    constexpr int BFL = 256 * 36;
    constexpr int STR = AFL + BFL;

    const int mw = wid & 1, nw = wid >> 1;
    const int gp = lane >> 2, qd = lane & 3;

    float acc[2][2][4][4];
    #pragma unroll
    for (int h = 0; h < 2; h++)
        #pragma unroll
        for (int i = 0; i < 2; i++)
            #pragma unroll
            for (int j = 0; j < 4; j++)
                #pragma unroll
                for (int c = 0; c < 4; c++) acc[h][i][j][c] = 0.f;

    const uint32_t sbase = smem_u32(smem);

    auto load_tile = [&](int kt, int buf) {
        const int k0 = kt * 32;
        const uint32_t offA = sbase + buf * STR * 4;
        const uint32_t offB = offA + AFL * 4;
        #pragma unroll
        for (int i = 0; i < 2; i++) {
            int idx = t + i * 256, row = idx >> 3, q = idx & 7;
            cp16(offA + (row * 36 + q * 4) * 4,
                 &A[(size_t)(bm + row) * 512 + k0 + q * 4], true);
        }
        #pragma unroll
        for (int i = 0; i < 8; i++) {
            int idx = t + i * 256, row = idx >> 3, q = idx & 7;
            int grow = (row < 128) ? (bn + row) : (2048 + bn + row - 128);
            cp16(offB + (row * 36 + q * 4) * 4,
                 &Bt[(size_t)grow * 512 + k0 + q * 4], true);
        }
        CP_COMMIT();
    };

    load_tile(0, 0);
    for (int kt = 0; kt < 16; kt++) {
        const int cur = kt & 1;
        if (kt + 1 < 16) { load_tile(kt + 1, cur ^ 1); CP_WAIT(1); }
        else             { CP_WAIT(0); }
        __syncthreads();
        const float* As = smem + cur * STR;
        const float* Bs = As + AFL;
        #pragma unroll
        for (int ks = 0; ks < 4; ks++) {
            const int kc = ks * 8 + qd;
            uint32_t fA[2][4];
            #pragma unroll
            for (int mt = 0; mt < 2; mt++) {
                const int r = mw * 32 + mt * 16 + gp;
                fA[mt][0] = U32(As[(r    ) * 36 + kc    ]);
                fA[mt][1] = U32(As[(r + 8) * 36 + kc    ]);
                fA[mt][2] = U32(As[(r    ) * 36 + kc + 4]);
                fA[mt][3] = U32(As[(r + 8) * 36 + kc + 4]);
            }
            #pragma unroll
            for (int h = 0; h < 2; h++) {
                uint32_t fB[4][2];
                #pragma unroll
                for (int nt = 0; nt < 4; nt++) {
                    const int n = h * 128 + nw * 32 + nt * 8 + gp;
                    fB[nt][0] = U32(Bs[n * 36 + kc    ]);
                    fB[nt][1] = U32(Bs[n * 36 + kc + 4]);
                }
                #pragma unroll
                for (int mt = 0; mt < 2; mt++)
                    #pragma unroll
                    for (int nt = 0; nt < 4; nt++)
                        mma_t(acc[h][mt][nt], fA[mt], fB[nt]);
            }
        }
        __syncthreads();
    }

    #pragma unroll
    for (int mt = 0; mt < 2; mt++) {
        const int r0 = bm + mw * 32 + mt * 16 + gp;
        #pragma unroll
        for (int nt = 0; nt < 4; nt++) {
            const int col = bn + nw * 32 + nt * 8 + qd * 2;
            const float2 ba = *(const float2*)&bias[col];
            const float2 bg = *(const float2*)&bias[col + 2048];
            #pragma unroll
            for (int half_row = 0; half_row < 2; half_row++) {
                const int r = r0 + half_row * 8;
                float a0 = acc[0][mt][nt][half_row * 2 + 0] + ba.x;
                float a1 = acc[0][mt][nt][half_row * 2 + 1] + ba.y;
                float g0 = acc[1][mt][nt][half_row * 2 + 0] + bg.x;
                float g1 = acc[1][mt][nt][half_row * 2 + 1] + bg.y;
                float2 o;
                o.x = a0 * (0.5f * g0 * (1.f + erff(g0 * 0.70710678118654752f)));
                o.y = a1 * (0.5f * g1 * (1.f + erff(g1 * 0.70710678118654752f)));
                *(float2*)&GL[(size_t)r * 2048 + col] = o;
            }
        }
    }
}

// ---------------- flash self-attention (R9-proven simple version) ------------
__global__ void __launch_bounds__(256, 2) fattn_k(
    const float* __restrict__ QKV, const float* __restrict__ Vt,
    float* __restrict__ O)
{
    extern __shared__ float sm[];
    float* Qs  = sm;
    float* Ks  = Qs  + 128 * 68;
    float* Vts = Ks  +  64 * 68;
    float* Ps  = Vts +  64 * 68;

    const int t = threadIdx.x, w = t >> 5, lane = t & 31;
    const int gp = lane >> 2, qd = lane & 3;
    const int q0 = blockIdx.x * 128;
    const int h = blockIdx.y, b = blockIdx.z;

    const float* qb  = QKV + ((size_t)b * NQ) * 1536 + h * 64;
    const float* kb  = qb + 512;
    const float* vtb = Vt + ((size_t)(b * 8 + h)) * 64 * NQ;

    const uint32_t aQ = smem_u32(Qs), aK = smem_u32(Ks), aV = smem_u32(Vts);

    #pragma unroll
    for (int i = 0; i < 8; i++) {
        int idx = t + i * 256, r = idx >> 4, c4 = (idx & 15) * 4;
        cp16(aQ + (r * 68 + c4) * 4, &qb[(size_t)(q0 + r) * 1536 + c4], true);
    }
    CP_COMMIT(); CP_WAIT(0);
    __syncthreads();
    #pragma unroll
    for (int i = 0; i < 8; i++) {
        int idx = t + i * 256, r = idx >> 4, c4 = (idx & 15) * 4;
        float4* p = (float4*)&Qs[r * 68 + c4];
        float4 v = *p;
        v.x *= 0.125f; v.y *= 0.125f; v.z *= 0.125f; v.w *= 0.125f;
        *p = v;
    }
    __syncthreads();

    const int r0l = w * 16 + gp, r1l = r0l + 8;

    float o[8][4];
    #pragma unroll
    for (int nt = 0; nt < 8; nt++)
        #pragma unroll
        for (int c = 0; c < 4; c++) o[nt][c] = 0.f;
    float m0 = -1e30f, m1 = -1e30f, l0 = 0.f, l1 = 0.f;

    for (int kt = 0; kt < NQ / 64; kt++) {
        const int k0 = kt * 64;
        #pragma unroll
        for (int i = 0; i < 4; i++) {
            int idx = t + i * 256, r = idx >> 4, c4 = (idx & 15) * 4;
            cp16(aK + (r * 68 + c4) * 4, &kb[(size_t)(k0 + r) * 1536 + c4], true);
        }
        #pragma unroll
        for (int i = 0; i < 4; i++) {
            int idx = t + i * 256, d = idx >> 4, c4 = (idx & 15) * 4;
            cp16(aV + (d * 68 + c4) * 4, &vtb[(size_t)d * NQ + k0 + c4], true);
        }
        CP_COMMIT(); CP_WAIT(0);
        __syncthreads();

        float s[8][4];
        #pragma unroll
        for (int nt = 0; nt < 8; nt++)
            #pragma unroll
            for (int c = 0; c < 4; c++) s[nt][c] = 0.f;
        #pragma unroll
        for (int ks = 0; ks < 8; ks++) {
            const int kc = ks * 8 + qd;
            uint32_t af[4];
            af[0] = U32(Qs[r0l * 68 + kc    ]);
            af[1] = U32(Qs[r1l * 68 + kc    ]);
            af[2] = U32(Qs[r0l * 68 + kc + 4]);
            af[3] = U32(Qs[r1l * 68 + kc + 4]);
            #pragma unroll
            for (int nt = 0; nt < 8; nt++) {
                uint32_t bf[2];
                const int n = nt * 8 + gp;
                bf[0] = U32(Ks[n * 68 + kc    ]);
                bf[1] = U32(Ks[n * 68 + kc + 4]);
                mma_t(s[nt], af, bf);
            }
        }

        float tm0 = -1e30f, tm1 = -1e30f;
        #pragma unroll
        for (int nt = 0; nt < 8; nt++) {
            tm0 = fmaxf(tm0, fmaxf(s[nt][0], s[nt][1]));
            tm1 = fmaxf(tm1, fmaxf(s[nt][2], s[nt][3]));
        }
        tm0 = fmaxf(tm0, __shfl_xor_sync(~0u, tm0, 1));
        tm0 = fmaxf(tm0, __shfl_xor_sync(~0u, tm0, 2));
        tm1 = fmaxf(tm1, __shfl_xor_sync(~0u, tm1, 1));
        tm1 = fmaxf(tm1, __shfl_xor_sync(~0u, tm1, 2));
        const float mn0 = fmaxf(m0, tm0), mn1 = fmaxf(m1, tm1);
        const float al0 = __expf(m0 - mn0), al1 = __expf(m1 - mn1);
        float sum0 = 0.f, sum1 = 0.f;
        #pragma unroll
        for (int nt = 0; nt < 8; nt++) {
            s[nt][0] = __expf(s[nt][0] - mn0);
            s[nt][1] = __expf(s[nt][1] - mn0);
            s[nt][2] = __expf(s[nt][2] - mn1);
            s[nt][3] = __expf(s[nt][3] - mn1);
            sum0 += s[nt][0] + s[nt][1];
            sum1 += s[nt][2] + s[nt][3];
        }
        sum0 += __shfl_xor_sync(~0u, sum0, 1);
        sum0 += __shfl_xor_sync(~0u, sum0, 2);
        sum1 += __shfl_xor_sync(~0u, sum1, 1);
        sum1 += __shfl_xor_sync(~0u, sum1, 2);
        l0 = l0 * al0 + sum0;  m0 = mn0;
        l1 = l1 * al1 + sum1;  m1 = mn1;
        #pragma unroll
        for (int nt = 0; nt < 8; nt++) {
            o[nt][0] *= al0; o[nt][1] *= al0;
            o[nt][2] *= al1; o[nt][3] *= al1;
        }
        #pragma unroll
        for (int nt = 0; nt < 8; nt++) {
            *(float2*)&Ps[r0l * 68 + nt * 8 + 2 * qd] = make_float2(s[nt][0], s[nt][1]);
            *(float2*)&Ps[r1l * 68 + nt * 8 + 2 * qd] = make_float2(s[nt][2], s[nt][3]);
        }
        __syncthreads();

        #pragma unroll
        for (int ks = 0; ks < 8; ks++) {
            const int kc = ks * 8 + qd;
            uint32_t af[4];
            af[0] = U32(Ps[r0l * 68 + kc    ]);
            af[1] = U32(Ps[r1l * 68 + kc    ]);
            af[2] = U32(Ps[r0l * 68 + kc + 4]);
            af[3] = U32(Ps[r1l * 68 + kc + 4]);
            #pragma unroll
            for (int nt = 0; nt < 8; nt++) {
                uint32_t bf[2];
                const int n = nt * 8 + gp;
                bf[0] = U32(Vts[n * 68 + kc    ]);
                bf[1] = U32(Vts[n * 68 + kc + 4]);
                mma_t(o[nt], af, bf);
            }
        }
        __syncthreads();
    }

    const float i0 = 1.f / l0, i1 = 1.f / l1;
    const size_t gr0 = (size_t)(b * NQ + q0 + r0l);
    const size_t gr1 = gr0 + 8;
    #pragma unroll
    for (int nt = 0; nt < 8; nt++) {
        const int col = h * 64 + nt * 8 + 2 * qd;
        *(float2*)&O[gr0 * 512 + col] = make_float2(o[nt][0] * i0, o[nt][1] * i0);
        *(float2*)&O[gr1 * 512 + col] = make_float2(o[nt][2] * i1, o[nt][3] * i1);
    }
}

// ----- merged preamble: weight transposes (+rna) AND GroupNorm stats ---------
struct TrJobs {
    const float* src[12];
    float*       dst[12];
    int K[12], N[12], tiles[12];
    int tot;
    const float* x;
    float* st;
};
__global__ void pre_k(TrJobs J)
{
    const int tid = threadIdx.x;
    if ((int)blockIdx.x >= J.tot) {
        int bg = blockIdx.x - J.tot, b = bg >> 5, g = bg & 31;
        const float* base = J.x + ((size_t)b * CC + (size_t)g * 16) * NQ;
        float s = 0.f, s2 = 0.f;
        for (int i = tid; i < 16 * NQ; i += 256) {
            float v = base[i]; s += v; s2 += v * v;
        }
        for (int o = 16; o > 0; o >>= 1) {
            s  += __shfl_down_sync(~0u, s,  o);
            s2 += __shfl_down_sync(~0u, s2, o);
        }
        __shared__ float sh1[8], sh2[8];
        int w = tid >> 5, lane = tid & 31;
        if (lane == 0) { sh1[w] = s; sh2[w] = s2; }
        __syncthreads();
        if (tid == 0) {
            float S = 0.f, S2 = 0.f;
            for (int i = 0; i < 8; i++) { S += sh1[i]; S2 += sh2[i]; }
            float mean = S / (16.f * NQ);
            float var  = S2 / (16.f * NQ) - mean * mean;
            J.st[bg * 2]     = mean;
            J.st[bg * 2 + 1] = rsqrtf(var + 1e-6f);
        }
        return;
    }
    __shared__ float tl[32][33];
    int bid = blockIdx.x, j = 0;
    #pragma unroll
    for (int i = 0; i < 12; i++) {
        if (bid >= J.tiles[j]) { bid -= J.tiles[j]; j++; }
        else break;
    }
    const int kt = bid % (J.K[j] / 32), nt = bid / (J.K[j] / 32);
    const int k0 = kt * 32, n0 = nt * 32;
    const float* W = J.src[j];
    float* Wt = J.dst[j];
    const int K = J.K[j], N = J.N[j];
    int tx = tid & 31, ty = tid >> 5;
    #pragma unroll
    for (int i = 0; i < 4; i++) {
        float v = W[(size_t)(k0 + ty + i * 8) * N + n0 + tx];
        tl[ty + i * 8][tx] = __uint_as_float(f2tf(v));
    }
    __syncthreads();
    #pragma unroll
    for (int i = 0; i < 4; i++)
        Wt[(size_t)(n0 + ty + i * 8) * K + k0 + tx] = tl[tx][ty + i * 8];
}

// --------- GroupNorm apply + NCHW -> [b,n,c] transpose -----------------------
__global__ void gn_apply_t_k(const float* __restrict__ x, const float* __restrict__ st,
                             const float* __restrict__ gg, const float* __restrict__ gb,
                             float* __restrict__ o)
{
    __shared__ float tile[32][33];
    int n0 = blockIdx.x * 32, c0 = blockIdx.y * 32, b = blockIdx.z;
    int tx = threadIdx.x, ty = threadIdx.y;
    #pragma unroll
    for (int i = 0; i < 4; i++) {
        int c = c0 + ty + i * 8;
        int g = c >> 4;
        float mean = st[(b * 32 + g) * 2], rstd = st[(b * 32 + g) * 2 + 1];
        float v = x[((size_t)b * CC + c) * NQ + n0 + tx];
        tile[ty + i * 8][tx] = (v - mean) * rstd * gg[c] + gb[c];
    }
    __syncthreads();
    #pragma unroll
    for (int i = 0; i < 4; i++) {
        int n = n0 + ty + i * 8;
        o[((size_t)b * NQ + n) * INNER_ + c0 + tx] = tile[tx][ty + i * 8];
    }
}

// ---------------- warp-per-2-rows LayerNorm (MLP=8, no block sync) -----------
// 256 threads = 8 warps; each warp handles 2 rows; grid MTOK/16 = 288.
__global__ void __launch_bounds__(256)
ln_k(const float* __restrict__ X, const float* __restrict__ g,
     const float* __restrict__ bb, float* __restrict__ O)
{
    const int w = threadIdx.x >> 5, lane = threadIdx.x & 31;
    const int row0 = blockIdx.x * 16 + w * 2;
    const float4* xr0 = (const float4*)(X + (size_t)row0 * INNER_);
    const float4* xr1 = (const float4*)(X + (size_t)(row0 + 1) * INNER_);

    float4 va[4], vb[4];
    #pragma unroll
    for (int i = 0; i < 4; i++) va[i] = xr0[lane + i * 32];
    #pragma unroll
    for (int i = 0; i < 4; i++) vb[i] = xr1[lane + i * 32];

    float sa = 0.f, sa2 = 0.f, sb = 0.f, sb2 = 0.f;
    #pragma unroll
    for (int i = 0; i < 4; i++) {
        sa  += va[i].x + va[i].y + va[i].z + va[i].w;
        sa2 += va[i].x*va[i].x + va[i].y*va[i].y + va[i].z*va[i].z + va[i].w*va[i].w;
        sb  += vb[i].x + vb[i].y + vb[i].z + vb[i].w;
        sb2 += vb[i].x*vb[i].x + vb[i].y*vb[i].y + vb[i].z*vb[i].z + vb[i].w*vb[i].w;
    }
    #pragma unroll
    for (int o = 16; o > 0; o >>= 1) {
        sa  += __shfl_xor_sync(~0u, sa,  o);
        sa2 += __shfl_xor_sync(~0u, sa2, o);
        sb  += __shfl_xor_sync(~0u, sb,  o);
        sb2 += __shfl_xor_sync(~0u, sb2, o);
    }
    const float ma = sa * (1.f / 512.f);
    const float ra = rsqrtf(sa2 * (1.f / 512.f) - ma * ma + 1e-5f);
    const float mb = sb * (1.f / 512.f);
    const float rb = rsqrtf(sb2 * (1.f / 512.f) - mb * mb + 1e-5f);

    float4* o0 = (float4*)(O + (size_t)row0 * INNER_);
    float4* o1 = (float4*)(O + (size_t)(row0 + 1) * INNER_);
    #pragma unroll
    for (int i = 0; i < 4; i++) {
        const int c4 = lane + i * 32;
        const float4 g4 = ((const float4*)g)[c4];
        const float4 b4 = ((const float4*)bb)[c4];
        float4 oa, ob;
        oa.x = (va[i].x - ma) * ra * g4.x + b4.x;
        oa.y = (va[i].y - ma) * ra * g4.y + b4.y;
        oa.z = (va[i].z - ma) * ra * g4.z + b4.z;
        oa.w = (va[i].w - ma) * ra * g4.w + b4.w;
        ob.x = (vb[i].x - mb) * rb * g4.x + b4.x;
        ob.y = (vb[i].y - mb) * rb * g4.y + b4.y;
        ob.z = (vb[i].z - mb) * rb * g4.z + b4.z;
        ob.w = (vb[i].w - mb) * rb * g4.w + b4.w;
        o0[c4] = oa;
        o1[c4] = ob;
    }
}

// ---------------- fp32 flash attention (cross-attn, 77 keys) -----------------
__global__ void __launch_bounds__(256) attn_k(
    const float* __restrict__ Q, const float* __restrict__ Kb,
    const float* __restrict__ Vb, float* __restrict__ O,
    int n_q, int n_kv, int ldq, int ldkv)
{
    __shared__ float Qs[64][68];
    __shared__ float Ks[32][68];
    __shared__ float Vs[32][68];
    __shared__ float Sx[64][33];
    __shared__ float mrow[64], lrow[64], arow[64];

    const int t  = threadIdx.x;
    const int h  = blockIdx.y, b = blockIdx.z;
    const int q0 = blockIdx.x * 64;
    const float* qb = Q  + ((size_t)b * n_q ) * ldq  + h * DHEAD_;
    const float* kb = Kb + ((size_t)b * n_kv) * ldkv + h * DHEAD_;
    const float* vb = Vb + ((size_t)b * n_kv) * ldkv + h * DHEAD_;

    #pragma unroll
    for (int j = 0; j < 4; j++) {
        int idx4 = t + j * 256;
        int r = idx4 >> 4, c4 = (idx4 & 15) * 4;
        float4 v = *(const float4*)&qb[(size_t)(q0 + r) * ldq + c4];
        Qs[r][c4+0]=v.x; Qs[r][c4+1]=v.y; Qs[r][c4+2]=v.z; Qs[r][c4+3]=v.w;
    }
    if (t < 64) { mrow[t] = -1e30f; lrow[t] = 0.f; }

    float acc[16];
    #pragma unroll
    for (int i = 0; i < 16; i++) acc[i] = 0.f;
    const int r  = t >> 2;
    const int jq = t & 3;

    const int ntiles = (n_kv + 31) / 32;
    for (int kt = 0; kt < ntiles; kt++) {
        const int j0 = kt * 32;
        #pragma unroll
        for (int j = 0; j < 2; j++) {
            int idx4 = t + j * 256;
            int jr = idx4 >> 4, c4 = (idx4 & 15) * 4;
            int krow = j0 + jr;
            float4 kv = make_float4(0.f,0.f,0.f,0.f);
            float4 vv = make_float4(0.f,0.f,0.f,0.f);
            if (krow < n_kv) {
                kv = *(const float4*)&kb[(size_t)krow * ldkv + c4];
                vv = *(const float4*)&vb[(size_t)krow * ldkv + c4];
            }
            Ks[jr][c4+0]=kv.x; Ks[jr][c4+1]=kv.y; Ks[jr][c4+2]=kv.z; Ks[jr][c4+3]=kv.w;
            Vs[jr][c4+0]=vv.x; Vs[jr][c4+1]=vv.y; Vs[jr][c4+2]=vv.z; Vs[jr][c4+3]=vv.w;
        }
        __syncthreads();
        #pragma unroll
        for (int jj = 0; jj < 8; jj++) {
            int j = jq + 4*jj;
            float s = 0.f;
            #pragma unroll
            for (int d = 0; d < 64; d++) s += Qs[r][d] * Ks[j][d];
            Sx[r][j] = (j0 + j < n_kv) ? s * 0.125f : -1e30f;
        }
        __syncthreads();
        if (t < 64) {
            float m_old = mrow[t];
            float mnew = m_old;
            #pragma unroll 8
            for (int j = 0; j < 32; j++) mnew = fmaxf(mnew, Sx[t][j]);
            float alpha = __expf(m_old - mnew);
            float psum = 0.f;
            #pragma unroll 8
            for (int j = 0; j < 32; j++) {
                float p = __expf(Sx[t][j] - mnew);
                Sx[t][j] = p; psum += p;
            }
            mrow[t] = mnew;
            lrow[t] = lrow[t]*alpha + psum;
            arow[t] = alpha;
        }
        __syncthreads();
        float alpha = arow[r];
        #pragma unroll
        for (int i = 0; i < 16; i++) acc[i] *= alpha;
        #pragma unroll 4
        for (int j = 0; j < 32; j++) {
            float p = Sx[r][j];
            #pragma unroll
            for (int i = 0; i < 16; i++)
                acc[i] += p * Vs[j][jq + 4*i];
        }
        __syncthreads();
    }
    const float inv = 1.f / lrow[r];
    float* orow = O + ((size_t)(b * n_q + q0 + r)) * INNER_ + h * DHEAD_ + jq;
    #pragma unroll
    for (int i = 0; i < 16; i++) orow[4*i] = acc[i] * inv;
}

// ---------------- launch -------------------------------------------------------
extern "C" void kernel_launch(void* const* d_in, const int* in_sizes, int n_in,
                              void* d_out, int out_size)
{
    const float* x    = (const float*)d_in[0];
    const float* ctx  = (const float*)d_in[1];
    const float* gng  = (const float*)d_in[2];
    const float* gnb  = (const float*)d_in[3];
    const float* w_in = (const float*)d_in[4];
    const float* b_in = (const float*)d_in[5];
    const float* ln1g = (const float*)d_in[6];
    const float* ln1b = (const float*)d_in[7];
    const float* wq1  = (const float*)d_in[8];
    const float* wk1  = (const float*)d_in[9];
    const float* wv1  = (const float*)d_in[10];
    const float* wo1  = (const float*)d_in[11];
    const float* bo1  = (const float*)d_in[12];
    const float* ln2g = (const float*)d_in[13];
    const float* ln2b = (const float*)d_in[14];
    const float* wq2  = (const float*)d_in[15];
    const float* wk2  = (const float*)d_in[16];
    const float* wv2  = (const float*)d_in[17];
    const float* wo2  = (const float*)d_in[18];
    const float* bo2  = (const float*)d_in[19];
    const float* ln3g = (const float*)d_in[20];
    const float* ln3b = (const float*)d_in[21];
    const float* wff1 = (const float*)d_in[22];
    const float* bff1 = (const float*)d_in[23];
    const float* wff2 = (const float*)d_in[24];
    const float* bff2 = (const float*)d_in[25];
    const float* wout = (const float*)d_in[26];
    const float* bout = (const float*)d_in[27];
    float* out = (float*)d_out;

    float *hn,*t_,*q,*at,*qkv,*kvc,*gl,*st,*vt;
    float *wt_in,*wqkv,*wto1,*wtq2,*wtkv2,*wto2,*wtff1,*wtff2,*wtout;
    cudaGetSymbolAddress((void**)&hn,  g_hn);
    cudaGetSymbolAddress((void**)&t_,  g_t);
    cudaGetSymbolAddress((void**)&q,   g_q);
    cudaGetSymbolAddress((void**)&at,  g_at);
    cudaGetSymbolAddress((void**)&qkv, g_qkv);
    cudaGetSymbolAddress((void**)&kvc, g_kvc);
    cudaGetSymbolAddress((void**)&gl,  g_gl);
    cudaGetSymbolAddress((void**)&st,  g_stat);
    cudaGetSymbolAddress((void**)&vt,  g_vt);
    cudaGetSymbolAddress((void**)&wt_in, g_wt_in);
    cudaGetSymbolAddress((void**)&wqkv,  g_wqkv);
    cudaGetSymbolAddress((void**)&wto1,  g_wto1);
    cudaGetSymbolAddress((void**)&wtq2,  g_wtq2);
    cudaGetSymbolAddress((void**)&wtkv2, g_wtkv2);
    cudaGetSymbolAddress((void**)&wto2,  g_wto2);
    cudaGetSymbolAddress((void**)&wtff1, g_wtff1);
    cudaGetSymbolAddress((void**)&wtff2, g_wtff2);
    cudaGetSymbolAddress((void**)&wtout, g_wtout);

    const int SM2  = 2 * (128 * 36 + 128 * 36) * 4;   // 73728
    const int SMFG = 2 * (64 * 36 + 256 * 36) * 4;    // 92160
    const int SMFA = 384 * 68 * 4;                    // 104448
    cudaFuncSetAttribute(tgemm_k,    cudaFuncAttributeMaxDynamicSharedMemorySize, SM2);
    cudaFuncSetAttribute(tgemmQKV_k, cudaFuncAttributeMaxDynamicSharedMemorySize, SM2);
    cudaFuncSetAttribute(xqkv_k,     cudaFuncAttributeMaxDynamicSharedMemorySize, SM2);
    cudaFuncSetAttribute(tgemmT_k,   cudaFuncAttributeMaxDynamicSharedMemorySize, SM2);
    cudaFuncSetAttribute(ffgeglu_k,  cudaFuncAttributeMaxDynamicSharedMemorySize, SMFG);
    cudaFuncSetAttribute(fattn_k,    cudaFuncAttributeMaxDynamicSharedMemorySize, SMFA);

    const dim3 tb(32, 8);

    // merged preamble: weight transposes + GroupNorm stats
    TrJobs J;
    J.src[0]=w_in;  J.dst[0]=wt_in;            J.K[0]=512;  J.N[0]=512;
    J.src[1]=wq1;   J.dst[1]=wqkv;             J.K[1]=512;  J.N[1]=512;
    J.src[2]=wk1;   J.dst[2]=wqkv+512*512;     J.K[2]=512;  J.N[2]=512;
    J.src[3]=wv1;   J.dst[3]=wqkv+1024*512;    J.K[3]=512;  J.N[3]=512;
    J.src[4]=wo1;   J.dst[4]=wto1;             J.K[4]=512;  J.N[4]=512;
    J.src[5]=wq2;   J.dst[5]=wtq2;             J.K[5]=512;  J.N[5]=512;
    J.src[6]=wk2;   J.dst[6]=wtkv2;            J.K[6]=768;  J.N[6]=512;
    J.src[7]=wv2;   J.dst[7]=wtkv2+512*768;    J.K[7]=768;  J.N[7]=512;
    J.src[8]=wo2;   J.dst[8]=wto2;             J.K[8]=512;  J.N[8]=512;
    J.src[9]=wff1;  J.dst[9]=wtff1;            J.K[9]=512;  J.N[9]=4096;
    J.src[10]=wff2; J.dst[10]=wtff2;           J.K[10]=2048;J.N[10]=512;
    J.src[11]=wout; J.dst[11]=wtout;           J.K[11]=512; J.N[11]=512;
    int tot = 0;
    for (int i = 0; i < 12; i++) { J.tiles[i] = (J.K[i]/32)*(J.N[i]/32); tot += J.tiles[i]; }
    J.tot = tot;
    J.x = x;
    J.st = st;
    pre_k<<<tot + BB*32, 256>>>(J);

    // GroupNorm apply + proj_in
    gn_apply_t_k<<<dim3(72, 16, 2), tb>>>(x, st, gng, gnb, hn);
    tgemm_k<<<dim3(4, 36), 256, SM2>>>(hn, wt_in, b_in, nullptr, t_,
        MTOK, 512, 512, 512, 512);

    // self-attention (qkv GEMM writes q/k to qkv, v transposed into vt)
    ln_k<<<MTOK/16, 256>>>(t_, ln1g, ln1b, hn);
    tgemmQKV_k<<<dim3(12, 36), 256, SM2>>>(hn, wqkv, qkv, vt);
    fattn_k<<<dim3(18, 8, 2), 256, SMFA>>>(qkv, vt, at);
    tgemm_k<<<dim3(4, 36), 256, SM2>>>(at, wto1, bo1, t_, t_,
        MTOK, 512, 512, 512, 512);

    // cross-attention (q GEMM + ctx kv GEMM merged into one launch)
    ln_k<<<MTOK/16, 256>>>(t_, ln2g, ln2b, hn);
    xqkv_k<<<dim3(4, 40), 256, SM2>>>(hn, wtq2, q, ctx, wtkv2, kvc);
    attn_k<<<dim3(36, 8, 2), 256>>>(q, kvc, kvc + 512, at, NQ, CTX, 512, 1024);
    tgemm_k<<<dim3(4, 36), 256, SM2>>>(at, wto2, bo2, t_, t_,
        MTOK, 512, 512, 512, 512);

    // feed-forward: fused ff1+GEGLU, then ff2
    ln_k<<<MTOK/16, 256>>>(t_, ln3g, ln3b, hn);
    ffgeglu_k<<<dim3(16, 72), 256, SMFG>>>(hn, wtff1, bff1, gl);
    tgemm_k<<<dim3(4, 36), 256, SM2>>>(gl, wtff2, bff2, t_, t_,
        MTOK, 2048, 2048, 2048, 512);

    // proj_out + transpose + image residual (fused)
    tgemmT_k<<<dim3(4, 36), 256, SM2>>>(t_, wtout, bout, x, out);
}